// round 2
// baseline (speedup 1.0000x reference)
#include <cuda_runtime.h>

// Problem constants
#define BB 2
#define TT 1024
#define DD 1024
#define VV 32000
#define LL 8

// Scratch (device globals; no allocation allowed)
__device__ float g_x[BB * TT * DD];   // residual stream
__device__ float g_q[BB * TT * DD];   // Q / final-LN output (reused)
__device__ float g_k[BB * TT * DD];   // K
__device__ float g_v[BB * TT * DD];   // V
__device__ float g_a[BB * TT * TT];   // scores -> softmax weights
__device__ float g_o[BB * TT * DD];   // attention output

// ---------------------------------------------------------------------------
// Embedding + (faithfully buggy) positional encoding: x[b,t,:] = embed[src[b,t]] + pe[b,0,:]
// ---------------------------------------------------------------------------
__global__ void embed_pe_kernel(const int* __restrict__ src,
                                const float* __restrict__ pe,
                                const float* __restrict__ embed,
                                float* __restrict__ x)
{
    int row = blockIdx.x;            // 0 .. B*T-1
    int b   = row >> 10;             // T = 1024
    long tok = src[row];
    const float4* e = reinterpret_cast<const float4*>(embed + tok * (long)DD);
    const float4* p = reinterpret_cast<const float4*>(pe + (long)b * DD);
    float4* xo = reinterpret_cast<float4*>(x + (long)row * DD);
    int i = threadIdx.x;             // 256 threads * float4 = 1024 floats
    float4 ev = e[i], pv = p[i];
    xo[i] = make_float4(ev.x + pv.x, ev.y + pv.y, ev.z + pv.z, ev.w + pv.w);
}

// ---------------------------------------------------------------------------
// 128x128x16 SGEMM, 256 threads, 8x8 per-thread microtile.
// BKMAJ=true : C[M,N] = A[M,K] * B[N,K]^T  (NT; both operands K-contiguous)
// BKMAJ=false: C[M,N] = A[M,K] * B[K,N]    (NN; B is N-contiguous)
// CAUSAL=true: skip blocks strictly above the diagonal (scores GEMM).
// All dims are multiples of the tile sizes -> no bounds checks.
// ---------------------------------------------------------------------------
template <bool BKMAJ, bool CAUSAL>
__global__ __launch_bounds__(256, 2)
void sgemm128(const float* __restrict__ A, const float* __restrict__ B,
              const float* __restrict__ bias, float* __restrict__ C,
              int K, int lda, int ldb, int ldc,
              long aBatch, long bBatch, long cBatch)
{
    if (CAUSAL && blockIdx.x > blockIdx.y) return;
    A += blockIdx.z * aBatch;
    B += blockIdx.z * bBatch;
    C += blockIdx.z * cBatch;

    __shared__ float As[16][128];
    __shared__ float Bs[16][128];

    const int tid = threadIdx.x;
    const int m0 = blockIdx.y * 128;
    const int n0 = blockIdx.x * 128;
    const int tr = (tid >> 4) << 3;   // row offset in tile (0..120)
    const int tc = (tid & 15) << 3;   // col offset in tile (0..120)

    float acc[8][8];
#pragma unroll
    for (int i = 0; i < 8; i++)
#pragma unroll
        for (int j = 0; j < 8; j++) acc[i][j] = 0.f;

    for (int k0 = 0; k0 < K; k0 += 16) {
        // A tile: 128 rows x 16 k, K-contiguous, transposed into As[k][m]
#pragma unroll
        for (int f = tid; f < 512; f += 256) {
            int row = f >> 2, kk = (f & 3) << 2;
            float4 val = *reinterpret_cast<const float4*>(A + (long)(m0 + row) * lda + k0 + kk);
            As[kk + 0][row] = val.x;
            As[kk + 1][row] = val.y;
            As[kk + 2][row] = val.z;
            As[kk + 3][row] = val.w;
        }
        if (BKMAJ) {
#pragma unroll
            for (int f = tid; f < 512; f += 256) {
                int row = f >> 2, kk = (f & 3) << 2;
                float4 val = *reinterpret_cast<const float4*>(B + (long)(n0 + row) * ldb + k0 + kk);
                Bs[kk + 0][row] = val.x;
                Bs[kk + 1][row] = val.y;
                Bs[kk + 2][row] = val.z;
                Bs[kk + 3][row] = val.w;
            }
        } else {
#pragma unroll
            for (int f = tid; f < 512; f += 256) {
                int kr = f >> 5, nn = (f & 31) << 2;
                *reinterpret_cast<float4*>(&Bs[kr][nn]) =
                    *reinterpret_cast<const float4*>(B + (long)(k0 + kr) * ldb + n0 + nn);
            }
        }
        __syncthreads();

#pragma unroll
        for (int k = 0; k < 16; k++) {
            float a[8], b[8];
            *reinterpret_cast<float4*>(a)     = *reinterpret_cast<const float4*>(&As[k][tr]);
            *reinterpret_cast<float4*>(a + 4) = *reinterpret_cast<const float4*>(&As[k][tr + 4]);
            *reinterpret_cast<float4*>(b)     = *reinterpret_cast<const float4*>(&Bs[k][tc]);
            *reinterpret_cast<float4*>(b + 4) = *reinterpret_cast<const float4*>(&Bs[k][tc + 4]);
#pragma unroll
            for (int i = 0; i < 8; i++)
#pragma unroll
                for (int j = 0; j < 8; j++)
                    acc[i][j] = fmaf(a[i], b[j], acc[i][j]);
        }
        __syncthreads();
    }

    float bv[8];
#pragma unroll
    for (int j = 0; j < 8; j++) bv[j] = bias ? bias[n0 + tc + j] : 0.f;
#pragma unroll
    for (int i = 0; i < 8; i++) {
        float* cp = C + (long)(m0 + tr + i) * ldc + n0 + tc;
        float4 v0 = make_float4(acc[i][0] + bv[0], acc[i][1] + bv[1],
                                acc[i][2] + bv[2], acc[i][3] + bv[3]);
        float4 v1 = make_float4(acc[i][4] + bv[4], acc[i][5] + bv[5],
                                acc[i][6] + bv[6], acc[i][7] + bv[7]);
        *reinterpret_cast<float4*>(cp)     = v0;
        *reinterpret_cast<float4*>(cp + 4) = v1;
    }
}

// ---------------------------------------------------------------------------
// Causal masked softmax over a row of A[b,t,:]; writes exact zeros for s > t
// so the downstream w@V GEMM can be dense.
// ---------------------------------------------------------------------------
__global__ void softmax_kernel(float* __restrict__ A)
{
    int t = blockIdx.x;
    int b = blockIdx.y;
    float* row = A + ((long)b * TT + t) * TT;
    int n = t + 1;                         // valid entries: s in [0, t]
    int i = threadIdx.x;
    __shared__ float red[256];

    float m = -1e30f;
    for (int s = i; s < n; s += 256) m = fmaxf(m, row[s]);
    red[i] = m;
    __syncthreads();
    for (int st = 128; st > 0; st >>= 1) {
        if (i < st) red[i] = fmaxf(red[i], red[i + st]);
        __syncthreads();
    }
    m = red[0];
    __syncthreads();

    float sum = 0.f;
    for (int s = i; s < n; s += 256) {
        float e = expf(row[s] - m);
        row[s] = e;
        sum += e;
    }
    red[i] = sum;
    __syncthreads();
    for (int st = 128; st > 0; st >>= 1) {
        if (i < st) red[i] += red[i + st];
        __syncthreads();
    }
    float inv = 1.0f / red[0];

    for (int s = i; s < TT; s += 256)
        row[s] = (s < n) ? row[s] * inv : 0.0f;
}

// ---------------------------------------------------------------------------
// Custom LN (eps inside sqrt, 1e-6, biased var) + residual add into x.
// Two-pass mean/var for accuracy. One block (256 thr) per row, float4 lanes.
// ---------------------------------------------------------------------------
__global__ void ln_res_kernel(const float* __restrict__ O,
                              const float* __restrict__ w,
                              const float* __restrict__ bb,
                              float* __restrict__ X)
{
    int row = blockIdx.x;
    int i = threadIdx.x;
    const float4 o = reinterpret_cast<const float4*>(O + (long)row * DD)[i];
    float4* x4 = reinterpret_cast<float4*>(X + (long)row * DD);
    __shared__ float red[256];

    red[i] = o.x + o.y + o.z + o.w;
    __syncthreads();
    for (int st = 128; st > 0; st >>= 1) {
        if (i < st) red[i] += red[i + st];
        __syncthreads();
    }
    float mu = red[0] * (1.0f / DD);
    __syncthreads();

    float dx = o.x - mu, dy = o.y - mu, dz = o.z - mu, dw_ = o.w - mu;
    red[i] = dx * dx + dy * dy + dz * dz + dw_ * dw_;
    __syncthreads();
    for (int st = 128; st > 0; st >>= 1) {
        if (i < st) red[i] += red[i + st];
        __syncthreads();
    }
    float rstd = rsqrtf(red[0] * (1.0f / DD) + 1e-6f);

    float4 wv = reinterpret_cast<const float4*>(w)[i];
    float4 bv = reinterpret_cast<const float4*>(bb)[i];
    float4 xv = x4[i];
    xv.x += dx * rstd * wv.x + bv.x;
    xv.y += dy * rstd * wv.y + bv.y;
    xv.z += dz * rstd * wv.z + bv.z;
    xv.w += dw_ * rstd * wv.w + bv.w;
    x4[i] = xv;
}

// ---------------------------------------------------------------------------
// Final nn.LayerNorm (eps=1e-5) -> out buffer
// ---------------------------------------------------------------------------
__global__ void final_ln_kernel(const float* __restrict__ X,
                                const float* __restrict__ fw,
                                const float* __restrict__ fb,
                                float* __restrict__ Y)
{
    int row = blockIdx.x;
    int i = threadIdx.x;
    const float4 x = reinterpret_cast<const float4*>(X + (long)row * DD)[i];
    float4* y4 = reinterpret_cast<float4*>(Y + (long)row * DD);
    __shared__ float red[256];

    red[i] = x.x + x.y + x.z + x.w;
    __syncthreads();
    for (int st = 128; st > 0; st >>= 1) {
        if (i < st) red[i] += red[i + st];
        __syncthreads();
    }
    float mu = red[0] * (1.0f / DD);
    __syncthreads();

    float dx = x.x - mu, dy = x.y - mu, dz = x.z - mu, dw_ = x.w - mu;
    red[i] = dx * dx + dy * dy + dz * dz + dw_ * dw_;
    __syncthreads();
    for (int st = 128; st > 0; st >>= 1) {
        if (i < st) red[i] += red[i + st];
        __syncthreads();
    }
    float rstd = rsqrtf(red[0] * (1.0f / DD) + 1e-5f);

    float4 wv = reinterpret_cast<const float4*>(fw)[i];
    float4 bv = reinterpret_cast<const float4*>(fb)[i];
    y4[i] = make_float4(dx * rstd * wv.x + bv.x,
                        dy * rstd * wv.y + bv.y,
                        dz * rstd * wv.z + bv.z,
                        dw_ * rstd * wv.w + bv.w);
}

// ---------------------------------------------------------------------------
// Launch
// ---------------------------------------------------------------------------
extern "C" void kernel_launch(void* const* d_in, const int* in_sizes, int n_in,
                              void* d_out, int out_size)
{
    const int*   src = (const int*)d_in[0];
    const float* pe  = (const float*)d_in[1];
    const float* emb = (const float*)d_in[2];
    const float* qw  = (const float*)d_in[3];
    const float* qb  = (const float*)d_in[4];
    const float* kw  = (const float*)d_in[5];
    const float* kb  = (const float*)d_in[6];
    const float* vw  = (const float*)d_in[7];
    const float* vb  = (const float*)d_in[8];
    const float* lnw = (const float*)d_in[9];
    const float* lnb = (const float*)d_in[10];
    const float* fw  = (const float*)d_in[11];
    const float* fb  = (const float*)d_in[12];
    const float* dw  = (const float*)d_in[13];
    const float* db  = (const float*)d_in[14];
    float* out = (float*)d_out;

    void *px, *pq, *pk, *pv, *pa, *po;
    cudaGetSymbolAddress(&px, g_x);
    cudaGetSymbolAddress(&pq, g_q);
    cudaGetSymbolAddress(&pk, g_k);
    cudaGetSymbolAddress(&pv, g_v);
    cudaGetSymbolAddress(&pa, g_a);
    cudaGetSymbolAddress(&po, g_o);
    float* x = (float*)px;
    float* q = (float*)pq;
    float* k = (float*)pk;
    float* v = (float*)pv;
    float* a = (float*)pa;
    float* o = (float*)po;

    const long MD = (long)TT * DD;   // per-batch elements of Q/K/V/x
    const long AA = (long)TT * TT;   // per-batch elements of scores

    embed_pe_kernel<<<BB * TT, 256>>>(src, pe, emb, x);

    dim3 gp(DD / 128, (BB * TT) / 128);       // projections: M=2048, N=1024
    dim3 gs(TT / 128, TT / 128, BB);          // attention GEMMs: per batch
    for (int l = 0; l < LL; l++) {
        const long wo = (long)l * DD * DD;
        sgemm128<true, false><<<gp, 256>>>(x, qw + wo, qb + l * DD, q, DD, DD, DD, DD, 0, 0, 0);
        sgemm128<true, false><<<gp, 256>>>(x, kw + wo, kb + l * DD, k, DD, DD, DD, DD, 0, 0, 0);
        sgemm128<true, false><<<gp, 256>>>(x, vw + wo, vb + l * DD, v, DD, DD, DD, DD, 0, 0, 0);
        // scores = Q K^T (unscaled), causal blocks only
        sgemm128<true, true><<<gs, 256>>>(q, k, nullptr, a, DD, DD, DD, TT, MD, MD, AA);
        softmax_kernel<<<dim3(TT, BB), 256>>>(a);
        // o = w @ V (dense: w has exact zeros above diagonal)
        sgemm128<false, false><<<gs, 256>>>(a, v, nullptr, o, TT, TT, DD, DD, AA, MD, MD);
        ln_res_kernel<<<BB * TT, 256>>>(o, lnw + l * DD, lnb + l * DD, x);
    }

    final_ln_kernel<<<BB * TT, 256>>>(x, fw, fb, q);
    dim3 gf(VV / 128, (BB * TT) / 128);       // vocab projection: M=2048, N=32000
    sgemm128<true, false><<<gf, 256>>>(q, dw, db, out, DD, DD, DD, VV, 0, 0, 0);
}

// round 6
// speedup vs baseline: 1.7745x; 1.7745x over previous
#include <cuda_runtime.h>
#include <cuda_bf16.h>
#include <cstdint>

#define BB 2
#define TT 1024
#define DD 1024
#define VV 32000
#define LL 8

__device__ float g_x[BB * TT * DD];
__device__ float g_q[BB * TT * DD];
__device__ float g_k[BB * TT * DD];
__device__ float g_v[BB * TT * DD];   // V^T per batch: [D][T]
__device__ float g_a[BB * TT * TT];
__device__ float g_o[BB * TT * DD];

// smem row: 32 bf16 data + 8 pad = 40 elems = 80 bytes (conflict-free ldmatrix)
#define RB 40
#define BUFB (128 * RB)               // elems per buffer

__device__ __forceinline__ uint32_t smem_u32(const void* p) {
    uint32_t a;
    asm("{ .reg .u64 t; cvta.to.shared.u64 t, %1; cvt.u32.u64 %0, t; }" : "=r"(a) : "l"(p));
    return a;
}

#define LDM4(r0, r1, r2, r3, ad) \
    asm volatile("ldmatrix.sync.aligned.m8n8.x4.shared.b16 {%0,%1,%2,%3},[%4];" \
                 : "=r"(r0), "=r"(r1), "=r"(r2), "=r"(r3) : "r"(ad))

#define MMA16(c, a, b0_, b1_) \
    asm volatile("mma.sync.aligned.m16n8k16.row.col.f32.bf16.bf16.f32 " \
                 "{%0,%1,%2,%3},{%4,%5,%6,%7},{%8,%9},{%0,%1,%2,%3};" \
                 : "+f"((c)[0]), "+f"((c)[1]), "+f"((c)[2]), "+f"((c)[3]) \
                 : "r"((a)[0]), "r"((a)[1]), "r"((a)[2]), "r"((a)[3]), "r"(b0_), "r"(b1_))

union BF2U { __nv_bfloat162 b; uint32_t u; };

__device__ __forceinline__ uint2 pack_hi(float4 v, float4& rest) {
    __nv_bfloat16 h0 = __float2bfloat16_rn(v.x), h1 = __float2bfloat16_rn(v.y);
    __nv_bfloat16 h2 = __float2bfloat16_rn(v.z), h3 = __float2bfloat16_rn(v.w);
    rest.x = v.x - __bfloat162float(h0);
    rest.y = v.y - __bfloat162float(h1);
    rest.z = v.z - __bfloat162float(h2);
    rest.w = v.w - __bfloat162float(h3);
    BF2U u0, u1;
    u0.b = __halves2bfloat162(h0, h1);
    u1.b = __halves2bfloat162(h2, h3);
    return make_uint2(u0.u, u1.u);
}
__device__ __forceinline__ uint2 pack_rn(float4 v) {
    BF2U u0, u1;
    u0.b = __halves2bfloat162(__float2bfloat16_rn(v.x), __float2bfloat16_rn(v.y));
    u1.b = __halves2bfloat162(__float2bfloat16_rn(v.z), __float2bfloat16_rn(v.w));
    return make_uint2(u0.u, u1.u);
}

// C[M,N] = A[M,K] * B[N,K]^T (both K-contiguous). Tile 128x128, BK=32, 256 thr.
// SPLIT: 3-term bf16 compensation. CAUSAL: skip bx>by. KLIM: Keff=m0+128.
// BIAS: 0 none, 1 per-N, 2 per-M. FUSEQK: blockIdx.z selects (B0,bias0,C0)/(B1,..).
template <bool SPLIT, bool CAUSAL, bool KLIM, int BIAS, bool FUSEQK>
__global__ void __launch_bounds__(256)
bgemm(const float* __restrict__ A, const float* __restrict__ B0,
      const float* __restrict__ bias0, float* __restrict__ C0,
      const float* __restrict__ B1, const float* __restrict__ bias1,
      float* __restrict__ C1,
      int K, int lda, int ldb, int ldc, long aB, long bB, long cB)
{
    const int bx = blockIdx.x, by = blockIdx.y, bz = blockIdx.z;
    if (CAUSAL && bx > by) return;
    constexpr int NBUF = SPLIT ? 4 : 2;   // Ahi, Bhi, (Alo, Blo)

    const float* Bp = B0;
    const float* bias = bias0;
    float* C = C0;
    if (FUSEQK) {
        if (bz) { Bp = B1; bias = bias1; C = C1; }
    } else {
        A += bz * aB; Bp += bz * bB; C += bz * cB;
    }

    const int m0 = by * 128, n0 = bx * 128;
    const int Keff = KLIM ? min(K, m0 + 128) : K;
    const int S = Keff >> 5;

    extern __shared__ __nv_bfloat16 sm[];
    const uint32_t sb = smem_u32(sm);

    const int tid = threadIdx.x, lane = tid & 31, wrp = tid >> 5;
    const int wm = wrp >> 2, wn = wrp & 3;

    // ldmatrix per-lane offsets
    const int a_ml = (lane & 7) + ((lane >> 3) & 1) * 8;
    const int a_kc = (lane >> 4) * 16;
    const int b_nl = (lane & 7) + ((lane >> 4) << 3);
    const int b_kc = ((lane >> 3) & 1) * 16;

    float acc[4][4][4];
#pragma unroll
    for (int i = 0; i < 4; i++)
#pragma unroll
        for (int j = 0; j < 4; j++)
#pragma unroll
            for (int r = 0; r < 4; r++) acc[i][j][r] = 0.f;

    float4 av[4], bv[4];
    const int lrow = tid >> 3, lq = (tid & 7) << 2;

    auto ldg = [&](int s) {
        const int k0 = s << 5;
        const float* Ap = A + (long)(m0 + lrow) * lda + k0 + lq;
        const float* Bq = Bp + (long)(n0 + lrow) * ldb + k0 + lq;
#pragma unroll
        for (int i = 0; i < 4; i++) {
            av[i] = *reinterpret_cast<const float4*>(Ap + (long)(i * 32) * lda);
            bv[i] = *reinterpret_cast<const float4*>(Bq + (long)(i * 32) * ldb);
        }
    };
    auto sts = [&](int st) {
        __nv_bfloat16* ah = sm + (st * NBUF + 0) * BUFB;
        __nv_bfloat16* bh = sm + (st * NBUF + 1) * BUFB;
#pragma unroll
        for (int i = 0; i < 4; i++) {
            const int off = (lrow + i * 32) * RB + lq;
            if (SPLIT) {
                __nv_bfloat16* al = sm + (st * NBUF + 2) * BUFB;
                __nv_bfloat16* bl = sm + (st * NBUF + 3) * BUFB;
                float4 ra, rb;
                *reinterpret_cast<uint2*>(ah + off) = pack_hi(av[i], ra);
                *reinterpret_cast<uint2*>(al + off) = pack_rn(ra);
                *reinterpret_cast<uint2*>(bh + off) = pack_hi(bv[i], rb);
                *reinterpret_cast<uint2*>(bl + off) = pack_rn(rb);
            } else {
                *reinterpret_cast<uint2*>(ah + off) = pack_rn(av[i]);
                *reinterpret_cast<uint2*>(bh + off) = pack_rn(bv[i]);
            }
        }
    };

    ldg(0);
    for (int s = 0; s < S; s++) {
        const int st = s & 1;
        sts(st);
        __syncthreads();
        if (s + 1 < S) ldg(s + 1);

        const uint32_t ahb = sb + (st * NBUF + 0) * BUFB * 2;
        const uint32_t bhb = sb + (st * NBUF + 1) * BUFB * 2;
        const uint32_t alb = sb + (st * NBUF + 2) * BUFB * 2;
        const uint32_t blb = sb + (st * NBUF + 3) * BUFB * 2;
#pragma unroll
        for (int ks = 0; ks < 2; ks++) {
            uint32_t bhf[8], blf[8];
#pragma unroll
            for (int p = 0; p < 2; p++) {
                const uint32_t boff = (uint32_t)((wn * 32 + p * 16 + b_nl) * 80 + ks * 32 + b_kc);
                LDM4(bhf[p * 4 + 0], bhf[p * 4 + 1], bhf[p * 4 + 2], bhf[p * 4 + 3], bhb + boff);
                if (SPLIT)
                    LDM4(blf[p * 4 + 0], blf[p * 4 + 1], blf[p * 4 + 2], blf[p * 4 + 3], blb + boff);
            }
#pragma unroll
            for (int mt = 0; mt < 4; mt++) {
                uint32_t ahf[4], alf[4];
                const uint32_t aoff = (uint32_t)((wm * 64 + mt * 16 + a_ml) * 80 + ks * 32 + a_kc);
                LDM4(ahf[0], ahf[1], ahf[2], ahf[3], ahb + aoff);
                if (SPLIT) LDM4(alf[0], alf[1], alf[2], alf[3], alb + aoff);
#pragma unroll
                for (int nt = 0; nt < 4; nt++) {
                    const int bi = (nt >> 1) * 4 + (nt & 1) * 2;
                    float* c = acc[mt][nt];
                    MMA16(c, ahf, bhf[bi], bhf[bi + 1]);
                    if (SPLIT) {
                        MMA16(c, ahf, blf[bi], blf[bi + 1]);
                        MMA16(c, alf, bhf[bi], bhf[bi + 1]);
                    }
                }
            }
        }
        __syncthreads();
    }

    const int er = lane >> 2, ec = (lane & 3) * 2;
#pragma unroll
    for (int mt = 0; mt < 4; mt++) {
        const int m = m0 + wm * 64 + mt * 16 + er;
        float bm0 = 0.f, bm8 = 0.f;
        if (BIAS == 2) { bm0 = bias[m]; bm8 = bias[m + 8]; }
#pragma unroll
        for (int nt = 0; nt < 4; nt++) {
            const int n = n0 + wn * 32 + nt * 8 + ec;
            float bn0 = 0.f, bn1 = 0.f;
            if (BIAS == 1) { bn0 = bias[n]; bn1 = bias[n + 1]; }
            const float* c = acc[mt][nt];
            *reinterpret_cast<float2*>(C + (long)m * ldc + n) =
                make_float2(c[0] + bn0 + bm0, c[1] + bn1 + bm0);
            *reinterpret_cast<float2*>(C + (long)(m + 8) * ldc + n) =
                make_float2(c[2] + bn0 + bm8, c[3] + bn1 + bm8);
        }
    }
}

__global__ void embed_pe_kernel(const int* __restrict__ src, const float* __restrict__ pe,
                                const float* __restrict__ embed, float* __restrict__ x)
{
    int row = blockIdx.x, b = row >> 10;
    long tok = src[row];
    const float4* e = reinterpret_cast<const float4*>(embed + tok * (long)DD);
    const float4* p = reinterpret_cast<const float4*>(pe + (long)b * DD);
    float4* xo = reinterpret_cast<float4*>(x + (long)row * DD);
    int i = threadIdx.x;
    float4 ev = e[i], pv = p[i];
    xo[i] = make_float4(ev.x + pv.x, ev.y + pv.y, ev.z + pv.z, ev.w + pv.w);
}

__global__ void softmax_kernel(float* __restrict__ A)
{
    int t = blockIdx.x, b = blockIdx.y;
    float* row = A + ((long)b * TT + t) * TT;
    int n = t + 1, i = threadIdx.x;
    __shared__ float red[256];
    float m = -1e30f;
    for (int s = i; s < n; s += 256) m = fmaxf(m, row[s]);
    red[i] = m; __syncthreads();
    for (int st = 128; st > 0; st >>= 1) { if (i < st) red[i] = fmaxf(red[i], red[i + st]); __syncthreads(); }
    m = red[0]; __syncthreads();
    float sum = 0.f;
    for (int s = i; s < n; s += 256) { float e = expf(row[s] - m); row[s] = e; sum += e; }
    red[i] = sum; __syncthreads();
    for (int st = 128; st > 0; st >>= 1) { if (i < st) red[i] += red[i + st]; __syncthreads(); }
    float inv = 1.0f / red[0];
    for (int s = i; s < TT; s += 256) row[s] = (s < n) ? row[s] * inv : 0.0f;
}

__global__ void ln_res_kernel(const float* __restrict__ O, const float* __restrict__ w,
                              const float* __restrict__ bb, float* __restrict__ X)
{
    int row = blockIdx.x, i = threadIdx.x;
    const float4 o = reinterpret_cast<const float4*>(O + (long)row * DD)[i];
    float4* x4 = reinterpret_cast<float4*>(X + (long)row * DD);
    __shared__ float red[256];
    red[i] = o.x + o.y + o.z + o.w; __syncthreads();
    for (int st = 128; st > 0; st >>= 1) { if (i < st) red[i] += red[i + st]; __syncthreads(); }
    float mu = red[0] * (1.0f / DD); __syncthreads();
    float dx = o.x - mu, dy = o.y - mu, dz = o.z - mu, dw_ = o.w - mu;
    red[i] = dx * dx + dy * dy + dz * dz + dw_ * dw_; __syncthreads();
    for (int st = 128; st > 0; st >>= 1) { if (i < st) red[i] += red[i + st]; __syncthreads(); }
    float rstd = rsqrtf(red[0] * (1.0f / DD) + 1e-6f);
    float4 wv = reinterpret_cast<const float4*>(w)[i];
    float4 bv = reinterpret_cast<const float4*>(bb)[i];
    float4 xv = x4[i];
    xv.x += dx * rstd * wv.x + bv.x;
    xv.y += dy * rstd * wv.y + bv.y;
    xv.z += dz * rstd * wv.z + bv.z;
    xv.w += dw_ * rstd * wv.w + bv.w;
    x4[i] = xv;
}

__global__ void final_ln_kernel(const float* __restrict__ X, const float* __restrict__ fw,
                                const float* __restrict__ fb, float* __restrict__ Y)
{
    int row = blockIdx.x, i = threadIdx.x;
    const float4 x = reinterpret_cast<const float4*>(X + (long)row * DD)[i];
    float4* y4 = reinterpret_cast<float4*>(Y + (long)row * DD);
    __shared__ float red[256];
    red[i] = x.x + x.y + x.z + x.w; __syncthreads();
    for (int st = 128; st > 0; st >>= 1) { if (i < st) red[i] += red[i + st]; __syncthreads(); }
    float mu = red[0] * (1.0f / DD); __syncthreads();
    float dx = x.x - mu, dy = x.y - mu, dz = x.z - mu, dw_ = x.w - mu;
    red[i] = dx * dx + dy * dy + dz * dz + dw_ * dw_; __syncthreads();
    for (int st = 128; st > 0; st >>= 1) { if (i < st) red[i] += red[i + st]; __syncthreads(); }
    float rstd = rsqrtf(red[0] * (1.0f / DD) + 1e-5f);
    float4 wv = reinterpret_cast<const float4*>(fw)[i];
    float4 bv = reinterpret_cast<const float4*>(fb)[i];
    y4[i] = make_float4(dx * rstd * wv.x + bv.x, dy * rstd * wv.y + bv.y,
                        dz * rstd * wv.z + bv.z, dw_ * rstd * wv.w + bv.w);
}

extern "C" void kernel_launch(void* const* d_in, const int* in_sizes, int n_in,
                              void* d_out, int out_size)
{
    const int*   src = (const int*)d_in[0];
    const float* pe  = (const float*)d_in[1];
    const float* emb = (const float*)d_in[2];
    const float* qw  = (const float*)d_in[3];
    const float* qb  = (const float*)d_in[4];
    const float* kw  = (const float*)d_in[5];
    const float* kb  = (const float*)d_in[6];
    const float* vw  = (const float*)d_in[7];
    const float* vb  = (const float*)d_in[8];
    const float* lnw = (const float*)d_in[9];
    const float* lnb = (const float*)d_in[10];
    const float* fw  = (const float*)d_in[11];
    const float* fb  = (const float*)d_in[12];
    const float* dw  = (const float*)d_in[13];
    const float* db  = (const float*)d_in[14];
    float* out = (float*)d_out;

    void *px, *pq, *pk, *pv, *pa, *po;
    cudaGetSymbolAddress(&px, g_x);
    cudaGetSymbolAddress(&pq, g_q);
    cudaGetSymbolAddress(&pk, g_k);
    cudaGetSymbolAddress(&pv, g_v);
    cudaGetSymbolAddress(&pa, g_a);
    cudaGetSymbolAddress(&po, g_o);
    float* x = (float*)px;  float* q = (float*)pq;  float* k = (float*)pk;
    float* v = (float*)pv;  float* a = (float*)pa;  float* o = (float*)po;

    const long MD = (long)TT * DD;
    const long AA = (long)TT * TT;

    auto GQK = bgemm<true, false, false, 1, true >;   // Q + K proj (z-fused)
    auto GVT = bgemm<true, false, false, 2, false>;   // V^T = vw @ x^T
    auto GSC = bgemm<true, true,  false, 0, false>;   // scores (causal skip)
    auto GAV = bgemm<true, false, true,  0, false>;   // o = w @ V (K-limited)
    auto GVO = bgemm<true, false, false, 1, false>;   // vocab (split bf16 too)

    const int SMS = 2 * 4 * BUFB * 2;   // 81920 B (split)
    cudaFuncSetAttribute(GQK, cudaFuncAttributeMaxDynamicSharedMemorySize, SMS);
    cudaFuncSetAttribute(GVT, cudaFuncAttributeMaxDynamicSharedMemorySize, SMS);
    cudaFuncSetAttribute(GSC, cudaFuncAttributeMaxDynamicSharedMemorySize, SMS);
    cudaFuncSetAttribute(GAV, cudaFuncAttributeMaxDynamicSharedMemorySize, SMS);
    cudaFuncSetAttribute(GVO, cudaFuncAttributeMaxDynamicSharedMemorySize, SMS);

    embed_pe_kernel<<<BB * TT, 256>>>(src, pe, emb, x);

    dim3 gqk(DD / 128, (BB * TT) / 128, 2);   // 8 x 16 x 2
    dim3 gvt(TT / 128, DD / 128, BB);         // 8 x 8 x 2
    dim3 gs(TT / 128, TT / 128, BB);          // 8 x 8 x 2
    for (int l = 0; l < LL; l++) {
        const long wo = (long)l * DD * DD;
        GQK<<<gqk, 256, SMS>>>(x, qw + wo, qb + l * DD, q, kw + wo, kb + l * DD, k,
                               DD, DD, DD, DD, 0, 0, 0);
        GVT<<<gvt, 256, SMS>>>(vw + wo, x, vb + l * DD, v, nullptr, nullptr, nullptr,
                               DD, DD, DD, TT, 0, MD, MD);
        GSC<<<gs, 256, SMS>>>(q, k, nullptr, a, nullptr, nullptr, nullptr,
                              DD, DD, DD, TT, MD, MD, AA);
        softmax_kernel<<<dim3(TT, BB), 256>>>(a);
        GAV<<<gs, 256, SMS>>>(a, v, nullptr, o, nullptr, nullptr, nullptr,
                              TT, TT, TT, DD, AA, MD, MD);
        ln_res_kernel<<<BB * TT, 256>>>(o, lnw + l * DD, lnb + l * DD, x);
    }

    final_ln_kernel<<<BB * TT, 256>>>(x, fw, fb, q);
    dim3 gf(VV / 128, (BB * TT) / 128, 1);    // 250 x 16
    GVO<<<gf, 256, SMS>>>(q, dw, db, out, nullptr, nullptr, nullptr,
                          DD, DD, DD, VV, 0, 0, 0);
}

// round 7
// speedup vs baseline: 2.8072x; 1.5820x over previous
#include <cuda_runtime.h>
#include <cuda_bf16.h>
#include <cuda_fp16.h>
#include <cstdint>

#define BB 2
#define TT 1024
#define DD 1024
#define VV 32000
#define LL 8

__device__ float g_x[BB * TT * DD];
__device__ float g_q[BB * TT * DD];
__device__ float g_k[BB * TT * DD];
__device__ float g_v[BB * TT * DD];   // V^T per batch: [D][T]
__device__ float g_a[BB * TT * TT];
__device__ float g_o[BB * TT * DD];

// smem row: 32 elems data + 8 pad = 40 elems = 80 bytes (conflict-free ldmatrix)
#define RB 40
#define BUFB (128 * RB)               // elems per buffer

__device__ __forceinline__ uint32_t smem_u32(const void* p) {
    uint32_t a;
    asm("{ .reg .u64 t; cvta.to.shared.u64 t, %1; cvt.u32.u64 %0, t; }" : "=r"(a) : "l"(p));
    return a;
}

#define LDM4(r0, r1, r2, r3, ad) \
    asm volatile("ldmatrix.sync.aligned.m8n8.x4.shared.b16 {%0,%1,%2,%3},[%4];" \
                 : "=r"(r0), "=r"(r1), "=r"(r2), "=r"(r3) : "r"(ad))

#define MMA16B(c, a, b0_, b1_) \
    asm volatile("mma.sync.aligned.m16n8k16.row.col.f32.bf16.bf16.f32 " \
                 "{%0,%1,%2,%3},{%4,%5,%6,%7},{%8,%9},{%0,%1,%2,%3};" \
                 : "+f"((c)[0]), "+f"((c)[1]), "+f"((c)[2]), "+f"((c)[3]) \
                 : "r"((a)[0]), "r"((a)[1]), "r"((a)[2]), "r"((a)[3]), "r"(b0_), "r"(b1_))

#define MMA16H(c, a, b0_, b1_) \
    asm volatile("mma.sync.aligned.m16n8k16.row.col.f32.f16.f16.f32 " \
                 "{%0,%1,%2,%3},{%4,%5,%6,%7},{%8,%9},{%0,%1,%2,%3};" \
                 : "+f"((c)[0]), "+f"((c)[1]), "+f"((c)[2]), "+f"((c)[3]) \
                 : "r"((a)[0]), "r"((a)[1]), "r"((a)[2]), "r"((a)[3]), "r"(b0_), "r"(b1_))

union BF2U { __nv_bfloat162 b; uint32_t u; };
union HF2U { __half2 h; uint32_t u; };

__device__ __forceinline__ uint2 pack_hi(float4 v, float4& rest) {
    __nv_bfloat16 h0 = __float2bfloat16_rn(v.x), h1 = __float2bfloat16_rn(v.y);
    __nv_bfloat16 h2 = __float2bfloat16_rn(v.z), h3 = __float2bfloat16_rn(v.w);
    rest.x = v.x - __bfloat162float(h0);
    rest.y = v.y - __bfloat162float(h1);
    rest.z = v.z - __bfloat162float(h2);
    rest.w = v.w - __bfloat162float(h3);
    BF2U u0, u1;
    u0.b = __halves2bfloat162(h0, h1);
    u1.b = __halves2bfloat162(h2, h3);
    return make_uint2(u0.u, u1.u);
}
__device__ __forceinline__ uint2 pack_rn(float4 v) {
    BF2U u0, u1;
    u0.b = __halves2bfloat162(__float2bfloat16_rn(v.x), __float2bfloat16_rn(v.y));
    u1.b = __halves2bfloat162(__float2bfloat16_rn(v.z), __float2bfloat16_rn(v.w));
    return make_uint2(u0.u, u1.u);
}
__device__ __forceinline__ uint2 pack_rn_h(float4 v) {
    HF2U u0, u1;
    u0.h = __floats2half2_rn(v.x, v.y);
    u1.h = __floats2half2_rn(v.z, v.w);
    return make_uint2(u0.u, u1.u);
}

// C[M,N] = A[M,K] * B[N,K]^T (both K-contiguous). Tile 128x128, BK=32, 512 thr,
// 16 warps of 32x32. FP16: single-pass f16 mma. SPLIT: 3-term bf16 compensation.
// CAUSAL: skip bx>by. KLIM: Keff=m0+128. BIAS: 0 none, 1 per-N, 2 per-M.
// FUSEQK: blockIdx.z selects (B0,bias0,C0)/(B1,bias1,C1).
template <bool FP16, bool SPLIT, bool CAUSAL, bool KLIM, int BIAS, bool FUSEQK>
__global__ void __launch_bounds__(512)
bgemm(const float* __restrict__ A, const float* __restrict__ B0,
      const float* __restrict__ bias0, float* __restrict__ C0,
      const float* __restrict__ B1, const float* __restrict__ bias1,
      float* __restrict__ C1,
      int K, int lda, int ldb, int ldc, long aB, long bB, long cB)
{
    const int bx = blockIdx.x, by = blockIdx.y, bz = blockIdx.z;
    if (CAUSAL && bx > by) return;
    constexpr int NBUF = SPLIT ? 4 : 2;   // Ahi, Bhi, (Alo, Blo)

    const float* Bp = B0;
    const float* bias = bias0;
    float* C = C0;
    if (FUSEQK) {
        if (bz) { Bp = B1; bias = bias1; C = C1; }
    } else {
        A += bz * aB; Bp += bz * bB; C += bz * cB;
    }

    const int m0 = by * 128, n0 = bx * 128;
    const int Keff = KLIM ? min(K, m0 + 128) : K;
    const int S = Keff >> 5;

    extern __shared__ uint16_t sm[];
    const uint32_t sb = smem_u32(sm);

    const int tid = threadIdx.x, lane = tid & 31, wrp = tid >> 5;
    const int wm = wrp >> 2, wn = wrp & 3;   // 4x4 warp grid, 32x32 tiles

    // ldmatrix per-lane offsets
    const int a_ml = (lane & 7) + ((lane >> 3) & 1) * 8;
    const int a_kc = (lane >> 4) * 16;
    const int b_nl = (lane & 7) + ((lane >> 4) << 3);
    const int b_kc = ((lane >> 3) & 1) * 16;

    float acc[2][4][4];
#pragma unroll
    for (int i = 0; i < 2; i++)
#pragma unroll
        for (int j = 0; j < 4; j++)
#pragma unroll
            for (int r = 0; r < 4; r++) acc[i][j][r] = 0.f;

    float4 av[2], bv[2];
    const int lrow = tid >> 3, lq = (tid & 7) << 2;   // 64 rows x 8 threads

    auto ldg = [&](int s) {
        const int k0 = s << 5;
        const float* Ap = A + (long)(m0 + lrow) * lda + k0 + lq;
        const float* Bq = Bp + (long)(n0 + lrow) * ldb + k0 + lq;
#pragma unroll
        for (int i = 0; i < 2; i++) {
            av[i] = *reinterpret_cast<const float4*>(Ap + (long)(i * 64) * lda);
            bv[i] = *reinterpret_cast<const float4*>(Bq + (long)(i * 64) * ldb);
        }
    };
    auto sts = [&](int st) {
        uint16_t* ah = sm + (st * NBUF + 0) * BUFB;
        uint16_t* bh = sm + (st * NBUF + 1) * BUFB;
#pragma unroll
        for (int i = 0; i < 2; i++) {
            const int off = (lrow + i * 64) * RB + lq;
            if (SPLIT) {
                uint16_t* al = sm + (st * NBUF + 2) * BUFB;
                uint16_t* bl = sm + (st * NBUF + 3) * BUFB;
                float4 ra, rb;
                *reinterpret_cast<uint2*>(ah + off) = pack_hi(av[i], ra);
                *reinterpret_cast<uint2*>(al + off) = pack_rn(ra);
                *reinterpret_cast<uint2*>(bh + off) = pack_hi(bv[i], rb);
                *reinterpret_cast<uint2*>(bl + off) = pack_rn(rb);
            } else if (FP16) {
                *reinterpret_cast<uint2*>(ah + off) = pack_rn_h(av[i]);
                *reinterpret_cast<uint2*>(bh + off) = pack_rn_h(bv[i]);
            } else {
                *reinterpret_cast<uint2*>(ah + off) = pack_rn(av[i]);
                *reinterpret_cast<uint2*>(bh + off) = pack_rn(bv[i]);
            }
        }
    };

    ldg(0);
    for (int s = 0; s < S; s++) {
        const int st = s & 1;
        sts(st);
        __syncthreads();
        if (s + 1 < S) ldg(s + 1);

        const uint32_t ahb = sb + (st * NBUF + 0) * BUFB * 2;
        const uint32_t bhb = sb + (st * NBUF + 1) * BUFB * 2;
        const uint32_t alb = sb + (st * NBUF + 2) * BUFB * 2;
        const uint32_t blb = sb + (st * NBUF + 3) * BUFB * 2;
#pragma unroll
        for (int ks = 0; ks < 2; ks++) {
            uint32_t bhf[8], blf[8];
#pragma unroll
            for (int p = 0; p < 2; p++) {
                const uint32_t boff = (uint32_t)((wn * 32 + p * 16 + b_nl) * 80 + ks * 32 + b_kc);
                LDM4(bhf[p * 4 + 0], bhf[p * 4 + 1], bhf[p * 4 + 2], bhf[p * 4 + 3], bhb + boff);
                if (SPLIT)
                    LDM4(blf[p * 4 + 0], blf[p * 4 + 1], blf[p * 4 + 2], blf[p * 4 + 3], blb + boff);
            }
#pragma unroll
            for (int mt = 0; mt < 2; mt++) {
                uint32_t ahf[4], alf[4];
                const uint32_t aoff = (uint32_t)((wm * 32 + mt * 16 + a_ml) * 80 + ks * 32 + a_kc);
                LDM4(ahf[0], ahf[1], ahf[2], ahf[3], ahb + aoff);
                if (SPLIT) LDM4(alf[0], alf[1], alf[2], alf[3], alb + aoff);
#pragma unroll
                for (int nt = 0; nt < 4; nt++) {
                    const int bi = (nt >> 1) * 4 + (nt & 1) * 2;
                    float* c = acc[mt][nt];
                    if (FP16) {
                        MMA16H(c, ahf, bhf[bi], bhf[bi + 1]);
                    } else {
                        MMA16B(c, ahf, bhf[bi], bhf[bi + 1]);
                        if (SPLIT) {
                            MMA16B(c, ahf, blf[bi], blf[bi + 1]);
                            MMA16B(c, alf, bhf[bi], bhf[bi + 1]);
                        }
                    }
                }
            }
        }
        __syncthreads();
    }

    const int er = lane >> 2, ec = (lane & 3) * 2;
#pragma unroll
    for (int mt = 0; mt < 2; mt++) {
        const int m = m0 + wm * 32 + mt * 16 + er;
        float bm0 = 0.f, bm8 = 0.f;
        if (BIAS == 2) { bm0 = bias[m]; bm8 = bias[m + 8]; }
#pragma unroll
        for (int nt = 0; nt < 4; nt++) {
            const int n = n0 + wn * 32 + nt * 8 + ec;
            float bn0 = 0.f, bn1 = 0.f;
            if (BIAS == 1) { bn0 = bias[n]; bn1 = bias[n + 1]; }
            const float* c = acc[mt][nt];
            *reinterpret_cast<float2*>(C + (long)m * ldc + n) =
                make_float2(c[0] + bn0 + bm0, c[1] + bn1 + bm0);
            *reinterpret_cast<float2*>(C + (long)(m + 8) * ldc + n) =
                make_float2(c[2] + bn0 + bm8, c[3] + bn1 + bm8);
        }
    }
}

__global__ void embed_pe_kernel(const int* __restrict__ src, const float* __restrict__ pe,
                                const float* __restrict__ embed, float* __restrict__ x)
{
    int row = blockIdx.x, b = row >> 10;
    long tok = src[row];
    const float4* e = reinterpret_cast<const float4*>(embed + tok * (long)DD);
    const float4* p = reinterpret_cast<const float4*>(pe + (long)b * DD);
    float4* xo = reinterpret_cast<float4*>(x + (long)row * DD);
    int i = threadIdx.x;
    float4 ev = e[i], pv = p[i];
    xo[i] = make_float4(ev.x + pv.x, ev.y + pv.y, ev.z + pv.z, ev.w + pv.w);
}

__global__ void softmax_kernel(float* __restrict__ A)
{
    int t = blockIdx.x, b = blockIdx.y;
    float* row = A + ((long)b * TT + t) * TT;
    int n = t + 1, i = threadIdx.x;
    __shared__ float red[256];
    float m = -1e30f;
    for (int s = i; s < n; s += 256) m = fmaxf(m, row[s]);
    red[i] = m; __syncthreads();
    for (int st = 128; st > 0; st >>= 1) { if (i < st) red[i] = fmaxf(red[i], red[i + st]); __syncthreads(); }
    m = red[0]; __syncthreads();
    float sum = 0.f;
    for (int s = i; s < n; s += 256) { float e = expf(row[s] - m); row[s] = e; sum += e; }
    red[i] = sum; __syncthreads();
    for (int st = 128; st > 0; st >>= 1) { if (i < st) red[i] += red[i + st]; __syncthreads(); }
    float inv = 1.0f / red[0];
    for (int s = i; s < TT; s += 256) row[s] = (s < n) ? row[s] * inv : 0.0f;
}

__global__ void ln_res_kernel(const float* __restrict__ O, const float* __restrict__ w,
                              const float* __restrict__ bb, float* __restrict__ X)
{
    int row = blockIdx.x, i = threadIdx.x;
    const float4 o = reinterpret_cast<const float4*>(O + (long)row * DD)[i];
    float4* x4 = reinterpret_cast<float4*>(X + (long)row * DD);
    __shared__ float red[256];
    red[i] = o.x + o.y + o.z + o.w; __syncthreads();
    for (int st = 128; st > 0; st >>= 1) { if (i < st) red[i] += red[i + st]; __syncthreads(); }
    float mu = red[0] * (1.0f / DD); __syncthreads();
    float dx = o.x - mu, dy = o.y - mu, dz = o.z - mu, dw_ = o.w - mu;
    red[i] = dx * dx + dy * dy + dz * dz + dw_ * dw_; __syncthreads();
    for (int st = 128; st > 0; st >>= 1) { if (i < st) red[i] += red[i + st]; __syncthreads(); }
    float rstd = rsqrtf(red[0] * (1.0f / DD) + 1e-6f);
    float4 wv = reinterpret_cast<const float4*>(w)[i];
    float4 bv = reinterpret_cast<const float4*>(bb)[i];
    float4 xv = x4[i];
    xv.x += dx * rstd * wv.x + bv.x;
    xv.y += dy * rstd * wv.y + bv.y;
    xv.z += dz * rstd * wv.z + bv.z;
    xv.w += dw_ * rstd * wv.w + bv.w;
    x4[i] = xv;
}

__global__ void final_ln_kernel(const float* __restrict__ X, const float* __restrict__ fw,
                                const float* __restrict__ fb, float* __restrict__ Y)
{
    int row = blockIdx.x, i = threadIdx.x;
    const float4 x = reinterpret_cast<const float4*>(X + (long)row * DD)[i];
    float4* y4 = reinterpret_cast<float4*>(Y + (long)row * DD);
    __shared__ float red[256];
    red[i] = x.x + x.y + x.z + x.w; __syncthreads();
    for (int st = 128; st > 0; st >>= 1) { if (i < st) red[i] += red[i + st]; __syncthreads(); }
    float mu = red[0] * (1.0f / DD); __syncthreads();
    float dx = x.x - mu, dy = x.y - mu, dz = x.z - mu, dw_ = x.w - mu;
    red[i] = dx * dx + dy * dy + dz * dz + dw_ * dw_; __syncthreads();
    for (int st = 128; st > 0; st >>= 1) { if (i < st) red[i] += red[i + st]; __syncthreads(); }
    float rstd = rsqrtf(red[0] * (1.0f / DD) + 1e-5f);
    float4 wv = reinterpret_cast<const float4*>(fw)[i];
    float4 bv = reinterpret_cast<const float4*>(fb)[i];
    y4[i] = make_float4(dx * rstd * wv.x + bv.x, dy * rstd * wv.y + bv.y,
                        dz * rstd * wv.z + bv.z, dw_ * rstd * wv.w + bv.w);
}

extern "C" void kernel_launch(void* const* d_in, const int* in_sizes, int n_in,
                              void* d_out, int out_size)
{
    const int*   src = (const int*)d_in[0];
    const float* pe  = (const float*)d_in[1];
    const float* emb = (const float*)d_in[2];
    const float* qw  = (const float*)d_in[3];
    const float* qb  = (const float*)d_in[4];
    const float* kw  = (const float*)d_in[5];
    const float* kb  = (const float*)d_in[6];
    const float* vw  = (const float*)d_in[7];
    const float* vb  = (const float*)d_in[8];
    const float* lnw = (const float*)d_in[9];
    const float* lnb = (const float*)d_in[10];
    const float* fw  = (const float*)d_in[11];
    const float* fb  = (const float*)d_in[12];
    const float* dw  = (const float*)d_in[13];
    const float* db  = (const float*)d_in[14];
    float* out = (float*)d_out;

    void *px, *pq, *pk, *pv, *pa, *po;
    cudaGetSymbolAddress(&px, g_x);
    cudaGetSymbolAddress(&pq, g_q);
    cudaGetSymbolAddress(&pk, g_k);
    cudaGetSymbolAddress(&pv, g_v);
    cudaGetSymbolAddress(&pa, g_a);
    cudaGetSymbolAddress(&po, g_o);
    float* x = (float*)px;  float* q = (float*)pq;  float* k = (float*)pk;
    float* v = (float*)pv;  float* a = (float*)pa;  float* o = (float*)po;

    const long MD = (long)TT * DD;
    const long AA = (long)TT * TT;

    auto GQK = bgemm<false, true, false, false, 1, true >;   // Q + K proj (z-fused)
    auto GVT = bgemm<false, true, false, false, 2, false>;   // V^T = vw @ x^T
    auto GSC = bgemm<false, true, true,  false, 0, false>;   // scores (causal skip)
    auto GAV = bgemm<false, true, false, true,  0, false>;   // o = w @ V (K-limited)
    auto GVO = bgemm<true,  false, false, false, 1, false>;  // vocab (single fp16)

    const int SMS = 2 * 4 * BUFB * 2;   // 81920 B (split)
    const int SM1 = 2 * 2 * BUFB * 2;   // 40960 B (fp16 plain)
    cudaFuncSetAttribute(GQK, cudaFuncAttributeMaxDynamicSharedMemorySize, SMS);
    cudaFuncSetAttribute(GVT, cudaFuncAttributeMaxDynamicSharedMemorySize, SMS);
    cudaFuncSetAttribute(GSC, cudaFuncAttributeMaxDynamicSharedMemorySize, SMS);
    cudaFuncSetAttribute(GAV, cudaFuncAttributeMaxDynamicSharedMemorySize, SMS);
    cudaFuncSetAttribute(GVO, cudaFuncAttributeMaxDynamicSharedMemorySize, SM1);

    embed_pe_kernel<<<BB * TT, 256>>>(src, pe, emb, x);

    dim3 gqk(DD / 128, (BB * TT) / 128, 2);   // 8 x 16 x 2
    dim3 gvt(TT / 128, DD / 128, BB);         // 8 x 8 x 2
    dim3 gs(TT / 128, TT / 128, BB);          // 8 x 8 x 2
    for (int l = 0; l < LL; l++) {
        const long wo = (long)l * DD * DD;
        GQK<<<gqk, 512, SMS>>>(x, qw + wo, qb + l * DD, q, kw + wo, kb + l * DD, k,
                               DD, DD, DD, DD, 0, 0, 0);
        GVT<<<gvt, 512, SMS>>>(vw + wo, x, vb + l * DD, v, nullptr, nullptr, nullptr,
                               DD, DD, DD, TT, 0, MD, MD);
        GSC<<<gs, 512, SMS>>>(q, k, nullptr, a, nullptr, nullptr, nullptr,
                              DD, DD, DD, TT, MD, MD, AA);
        softmax_kernel<<<dim3(TT, BB), 256>>>(a);
        GAV<<<gs, 512, SMS>>>(a, v, nullptr, o, nullptr, nullptr, nullptr,
                              TT, TT, TT, DD, AA, MD, MD);
        ln_res_kernel<<<BB * TT, 256>>>(o, lnw + l * DD, lnb + l * DD, x);
    }

    final_ln_kernel<<<BB * TT, 256>>>(x, fw, fb, q);
    dim3 gf(VV / 128, (BB * TT) / 128, 1);    // 250 x 16
    GVO<<<gf, 512, SM1>>>(q, dw, db, out, nullptr, nullptr, nullptr,
                          DD, DD, DD, VV, 0, 0, 0);
}

// round 8
// speedup vs baseline: 3.7298x; 1.3287x over previous
#include <cuda_runtime.h>
#include <cuda_bf16.h>
#include <cuda_fp16.h>
#include <cstdint>

#define BB 2
#define TT 1024
#define DD 1024
#define VV 32000
#define LL 8
#define MD (TT * DD)
#define AA (TT * TT)

typedef __nv_bfloat16 bf16;

// fp32 masters
__device__ float g_x[BB * MD];
__device__ float g_a[BB * AA];
__device__ float g_o[BB * MD];
// pre-split bf16 operands
__device__ bf16 g_xh[BB * MD], g_xl[BB * MD];
__device__ bf16 g_qh[BB * MD], g_ql[BB * MD];
__device__ bf16 g_kh[BB * MD], g_kl[BB * MD];
__device__ bf16 g_vh[BB * MD], g_vl[BB * MD];      // V^T [b][d][t]
__device__ bf16 g_wh[BB * AA], g_wl[BB * AA];
__device__ bf16 g_qwh[LL * DD * DD], g_qwl[LL * DD * DD];
__device__ bf16 g_kwh[LL * DD * DD], g_kwl[LL * DD * DD];
__device__ bf16 g_vwh[LL * DD * DD], g_vwl[LL * DD * DD];
__device__ __half g_dwh[VV * DD];
__device__ __half g_xnh[BB * TT * DD];

#define NSTAGE 3
#define BUFBY 10240     // 128 rows * 80B
#define PITCH 80

__device__ __forceinline__ uint32_t smem_u32(const void* p) {
    uint32_t a;
    asm("{ .reg .u64 t; cvta.to.shared.u64 t, %1; cvt.u32.u64 %0, t; }" : "=r"(a) : "l"(p));
    return a;
}
#define LDM4(r0, r1, r2, r3, ad) \
    asm volatile("ldmatrix.sync.aligned.m8n8.x4.shared.b16 {%0,%1,%2,%3},[%4];" \
                 : "=r"(r0), "=r"(r1), "=r"(r2), "=r"(r3) : "r"(ad))
#define MMA16B(c, a, b0_, b1_) \
    asm volatile("mma.sync.aligned.m16n8k16.row.col.f32.bf16.bf16.f32 " \
                 "{%0,%1,%2,%3},{%4,%5,%6,%7},{%8,%9},{%0,%1,%2,%3};" \
                 : "+f"((c)[0]), "+f"((c)[1]), "+f"((c)[2]), "+f"((c)[3]) \
                 : "r"((a)[0]), "r"((a)[1]), "r"((a)[2]), "r"((a)[3]), "r"(b0_), "r"(b1_))
#define MMA16H(c, a, b0_, b1_) \
    asm volatile("mma.sync.aligned.m16n8k16.row.col.f32.f16.f16.f32 " \
                 "{%0,%1,%2,%3},{%4,%5,%6,%7},{%8,%9},{%0,%1,%2,%3};" \
                 : "+f"((c)[0]), "+f"((c)[1]), "+f"((c)[2]), "+f"((c)[3]) \
                 : "r"((a)[0]), "r"((a)[1]), "r"((a)[2]), "r"((a)[3]), "r"(b0_), "r"(b1_))
#define CPA16(d, s) asm volatile("cp.async.cg.shared.global [%0], [%1], 16;" :: "r"(d), "l"(s))
#define CPCOMMIT()  asm volatile("cp.async.commit_group;" ::: "memory")
#define CPWAIT1()   asm volatile("cp.async.wait_group 1;" ::: "memory")

__device__ __forceinline__ void bsplit(float v, bf16& h, bf16& l) {
    h = __float2bfloat16_rn(v);
    l = __float2bfloat16_rn(v - __bfloat162float(h));
}

// ---------------------------------------------------------------------------
// bf16 3-term split GEMM core: C[M,N] = A*B^T, pre-split hi/lo operands,
// 3-stage cp.async pipeline, 128x128 tile, 512 thr (16 warps of 32x32).
// BIAS: 0 none, 1 per-N, 2 per-M.  OUT: 0 fp32 Cf, 1 bf16 hi/lo Ch/Cl.
// ---------------------------------------------------------------------------
template <int BIAS, int OUT>
__device__ __forceinline__ void gemm_core(
    const bf16* __restrict__ Ah, const bf16* __restrict__ Al, int lda,
    const bf16* __restrict__ Bh, const bf16* __restrict__ Bl, int ldb,
    const float* __restrict__ bias,
    float* __restrict__ Cf, bf16* __restrict__ Ch, bf16* __restrict__ Cl, int ldc,
    int m0, int n0, int Keff)
{
    extern __shared__ uint16_t sm[];
    const uint32_t sb = smem_u32(sm);
    const int tid = threadIdx.x, lane = tid & 31, wrp = tid >> 5;
    const int wm = wrp >> 2, wn = wrp & 3;
    const int S = Keff >> 5;

    const int a_ml = (lane & 7) + ((lane >> 3) & 1) * 8;
    const int a_kc = (lane >> 4) * 16;
    const int b_nl = (lane & 7) + ((lane >> 4) << 3);
    const int b_kc = ((lane >> 3) & 1) * 16;

    const int row = tid >> 2, ch = tid & 3;
    const bf16* Aph = Ah + (long)(m0 + row) * lda + ch * 8;
    const bf16* Apl = Al + (long)(m0 + row) * lda + ch * 8;
    const bf16* Bph = Bh + (long)(n0 + row) * ldb + ch * 8;
    const bf16* Bpl = Bl + (long)(n0 + row) * ldb + ch * 8;
    const uint32_t dsm = sb + row * PITCH + ch * 16;

    auto issue = [&](int s) {
        const int k0 = s << 5;
        const uint32_t db = dsm + (uint32_t)(s % NSTAGE) * (4 * BUFBY);
        CPA16(db,             Aph + k0);
        CPA16(db + BUFBY,     Apl + k0);
        CPA16(db + 2 * BUFBY, Bph + k0);
        CPA16(db + 3 * BUFBY, Bpl + k0);
        CPCOMMIT();
    };

    float acc[2][4][4] = {};

    issue(0); issue(1);
    for (int s = 0; s < S; s++) {
        CPWAIT1();
        __syncthreads();
        const uint32_t stb = sb + (uint32_t)(s % NSTAGE) * (4 * BUFBY);
        const uint32_t ahb = stb, alb = stb + BUFBY, bhb = stb + 2 * BUFBY, blb = stb + 3 * BUFBY;
#pragma unroll
        for (int ks = 0; ks < 2; ks++) {
            uint32_t bhf[8], blf[8];
#pragma unroll
            for (int p = 0; p < 2; p++) {
                const uint32_t boff = (uint32_t)((wn * 32 + p * 16 + b_nl) * PITCH + ks * 32 + b_kc);
                LDM4(bhf[p * 4 + 0], bhf[p * 4 + 1], bhf[p * 4 + 2], bhf[p * 4 + 3], bhb + boff);
                LDM4(blf[p * 4 + 0], blf[p * 4 + 1], blf[p * 4 + 2], blf[p * 4 + 3], blb + boff);
            }
#pragma unroll
            for (int mt = 0; mt < 2; mt++) {
                uint32_t ahf[4], alf[4];
                const uint32_t aoff = (uint32_t)((wm * 32 + mt * 16 + a_ml) * PITCH + ks * 32 + a_kc);
                LDM4(ahf[0], ahf[1], ahf[2], ahf[3], ahb + aoff);
                LDM4(alf[0], alf[1], alf[2], alf[3], alb + aoff);
#pragma unroll
                for (int nt = 0; nt < 4; nt++) {
                    const int bi = (nt >> 1) * 4 + (nt & 1) * 2;
                    float* c = acc[mt][nt];
                    MMA16B(c, ahf, bhf[bi], bhf[bi + 1]);
                    MMA16B(c, ahf, blf[bi], blf[bi + 1]);
                    MMA16B(c, alf, bhf[bi], bhf[bi + 1]);
                }
            }
        }
        if (s + 2 < S) issue(s + 2); else CPCOMMIT();
    }

    const int er = lane >> 2, ec = (lane & 3) * 2;
#pragma unroll
    for (int mt = 0; mt < 2; mt++) {
        const int m = m0 + wm * 32 + mt * 16 + er;
        float bm0 = 0.f, bm8 = 0.f;
        if (BIAS == 2) { bm0 = bias[m]; bm8 = bias[m + 8]; }
#pragma unroll
        for (int nt = 0; nt < 4; nt++) {
            const int n = n0 + wn * 32 + nt * 8 + ec;
            float bn0 = 0.f, bn1 = 0.f;
            if (BIAS == 1) { bn0 = bias[n]; bn1 = bias[n + 1]; }
            const float* c = acc[mt][nt];
            float v00 = c[0] + bn0 + bm0, v01 = c[1] + bn1 + bm0;
            float v10 = c[2] + bn0 + bm8, v11 = c[3] + bn1 + bm8;
            if (OUT == 0) {
                *reinterpret_cast<float2*>(Cf + (long)m * ldc + n) = make_float2(v00, v01);
                *reinterpret_cast<float2*>(Cf + (long)(m + 8) * ldc + n) = make_float2(v10, v11);
            } else {
                bf16 h0, l0, h1, l1;
                bsplit(v00, h0, l0); bsplit(v01, h1, l1);
                *reinterpret_cast<__nv_bfloat162*>(Ch + (long)m * ldc + n) = __halves2bfloat162(h0, h1);
                *reinterpret_cast<__nv_bfloat162*>(Cl + (long)m * ldc + n) = __halves2bfloat162(l0, l1);
                bsplit(v10, h0, l0); bsplit(v11, h1, l1);
                *reinterpret_cast<__nv_bfloat162*>(Ch + (long)(m + 8) * ldc + n) = __halves2bfloat162(h0, h1);
                *reinterpret_cast<__nv_bfloat162*>(Cl + (long)(m + 8) * ldc + n) = __halves2bfloat162(l0, l1);
            }
        }
    }
}

// fp16 single-pass core (vocab GEMM): 2 buffers, per-N bias, fp32 out.
__device__ __forceinline__ void gemm_core_h(
    const __half* __restrict__ A, int lda, const __half* __restrict__ B, int ldb,
    const float* __restrict__ bias, float* __restrict__ C, int ldc,
    int m0, int n0, int Keff)
{
    extern __shared__ uint16_t sm[];
    const uint32_t sb = smem_u32(sm);
    const int tid = threadIdx.x, lane = tid & 31, wrp = tid >> 5;
    const int wm = wrp >> 2, wn = wrp & 3;
    const int S = Keff >> 5;

    const int a_ml = (lane & 7) + ((lane >> 3) & 1) * 8;
    const int a_kc = (lane >> 4) * 16;
    const int b_nl = (lane & 7) + ((lane >> 4) << 3);
    const int b_kc = ((lane >> 3) & 1) * 16;

    const int row = tid >> 2, ch = tid & 3;
    const __half* Ap = A + (long)(m0 + row) * lda + ch * 8;
    const __half* Bp = B + (long)(n0 + row) * ldb + ch * 8;
    const uint32_t dsm = sb + row * PITCH + ch * 16;

    auto issue = [&](int s) {
        const int k0 = s << 5;
        const uint32_t db = dsm + (uint32_t)(s % NSTAGE) * (2 * BUFBY);
        CPA16(db,         Ap + k0);
        CPA16(db + BUFBY, Bp + k0);
        CPCOMMIT();
    };

    float acc[2][4][4] = {};
    issue(0); issue(1);
    for (int s = 0; s < S; s++) {
        CPWAIT1();
        __syncthreads();
        const uint32_t stb = sb + (uint32_t)(s % NSTAGE) * (2 * BUFBY);
        const uint32_t ahb = stb, bhb = stb + BUFBY;
#pragma unroll
        for (int ks = 0; ks < 2; ks++) {
            uint32_t bhf[8];
#pragma unroll
            for (int p = 0; p < 2; p++) {
                const uint32_t boff = (uint32_t)((wn * 32 + p * 16 + b_nl) * PITCH + ks * 32 + b_kc);
                LDM4(bhf[p * 4 + 0], bhf[p * 4 + 1], bhf[p * 4 + 2], bhf[p * 4 + 3], bhb + boff);
            }
#pragma unroll
            for (int mt = 0; mt < 2; mt++) {
                uint32_t ahf[4];
                const uint32_t aoff = (uint32_t)((wm * 32 + mt * 16 + a_ml) * PITCH + ks * 32 + a_kc);
                LDM4(ahf[0], ahf[1], ahf[2], ahf[3], ahb + aoff);
#pragma unroll
                for (int nt = 0; nt < 4; nt++) {
                    const int bi = (nt >> 1) * 4 + (nt & 1) * 2;
                    MMA16H(acc[mt][nt], ahf, bhf[bi], bhf[bi + 1]);
                }
            }
        }
        if (s + 2 < S) issue(s + 2); else CPCOMMIT();
    }

    const int er = lane >> 2, ec = (lane & 3) * 2;
#pragma unroll
    for (int mt = 0; mt < 2; mt++) {
        const int m = m0 + wm * 32 + mt * 16 + er;
#pragma unroll
        for (int nt = 0; nt < 4; nt++) {
            const int n = n0 + wn * 32 + nt * 8 + ec;
            const float bn0 = bias[n], bn1 = bias[n + 1];
            const float* c = acc[mt][nt];
            *reinterpret_cast<float2*>(C + (long)m * ldc + n) = make_float2(c[0] + bn0, c[1] + bn1);
            *reinterpret_cast<float2*>(C + (long)(m + 8) * ldc + n) = make_float2(c[2] + bn0, c[3] + bn1);
        }
    }
}

// ---------------------------------------------------------------------------
// GEMM kernel wrappers
// ---------------------------------------------------------------------------
struct QKVP {
    const bf16 *xh, *xl;
    const bf16 *qwh, *qwl, *kwh, *kwl, *vwh, *vwl;
    const float *qb, *kb, *vb;
    bf16 *qh, *ql, *kh, *kl, *vh, *vl;
};

__global__ void __launch_bounds__(512) qkv_kernel(QKVP p)
{
    const int bx = blockIdx.x, by = blockIdx.y, bz = blockIdx.z;
    if (bz == 0) {
        gemm_core<1, 1>(p.xh, p.xl, DD, p.qwh, p.qwl, DD, p.qb,
                        nullptr, p.qh, p.ql, DD, by * 128, bx * 128, DD);
    } else if (bz == 1) {
        gemm_core<1, 1>(p.xh, p.xl, DD, p.kwh, p.kwl, DD, p.kb,
                        nullptr, p.kh, p.kl, DD, by * 128, bx * 128, DD);
    } else {
        const int b = by >> 3, dt = by & 7;
        gemm_core<2, 1>(p.vwh, p.vwl, DD, p.xh + (long)b * MD, p.xl + (long)b * MD, DD, p.vb,
                        nullptr, p.vh + (long)b * MD, p.vl + (long)b * MD, TT,
                        dt * 128, bx * 128, DD);
    }
}

__global__ void __launch_bounds__(512) sc_kernel(const bf16* __restrict__ qh, const bf16* __restrict__ ql,
                                                 const bf16* __restrict__ kh, const bf16* __restrict__ kl,
                                                 float* __restrict__ a)
{
    const int bx = blockIdx.x, by = blockIdx.y, b = blockIdx.z;
    if (bx > by) return;
    gemm_core<0, 0>(qh + (long)b * MD, ql + (long)b * MD, DD,
                    kh + (long)b * MD, kl + (long)b * MD, DD, nullptr,
                    a + (long)b * AA, nullptr, nullptr, TT, by * 128, bx * 128, DD);
}

__global__ void __launch_bounds__(512) av_kernel(const bf16* __restrict__ wh, const bf16* __restrict__ wl,
                                                 const bf16* __restrict__ vh, const bf16* __restrict__ vl,
                                                 float* __restrict__ o)
{
    const int bx = blockIdx.x, by = blockIdx.y, b = blockIdx.z;
    gemm_core<0, 0>(wh + (long)b * AA, wl + (long)b * AA, TT,
                    vh + (long)b * MD, vl + (long)b * MD, TT, nullptr,
                    o + (long)b * MD, nullptr, nullptr, DD,
                    by * 128, bx * 128, min(TT, by * 128 + 128));
}

__global__ void __launch_bounds__(512) vocab_kernel(const __half* __restrict__ xn, const __half* __restrict__ dwh,
                                                    const float* __restrict__ db, float* __restrict__ out)
{
    gemm_core_h(xn, DD, dwh, DD, db, out, VV, blockIdx.y * 128, blockIdx.x * 128, DD);
}

// ---------------------------------------------------------------------------
// Converters + elementwise
// ---------------------------------------------------------------------------
__global__ void splitw_kernel(const float4* __restrict__ src, bf16* __restrict__ h,
                              bf16* __restrict__ l, int n4)
{
    int i = blockIdx.x * blockDim.x + threadIdx.x;
    if (i >= n4) return;
    float4 v = src[i];
    bf16 h0, l0, h1, l1, h2, l2, h3, l3;
    bsplit(v.x, h0, l0); bsplit(v.y, h1, l1); bsplit(v.z, h2, l2); bsplit(v.w, h3, l3);
    *reinterpret_cast<__nv_bfloat162*>(h + (long)i * 4)     = __halves2bfloat162(h0, h1);
    *reinterpret_cast<__nv_bfloat162*>(h + (long)i * 4 + 2) = __halves2bfloat162(h2, h3);
    *reinterpret_cast<__nv_bfloat162*>(l + (long)i * 4)     = __halves2bfloat162(l0, l1);
    *reinterpret_cast<__nv_bfloat162*>(l + (long)i * 4 + 2) = __halves2bfloat162(l2, l3);
}

__global__ void tohalf_kernel(const float4* __restrict__ src, __half* __restrict__ dst, int n4)
{
    int i = blockIdx.x * blockDim.x + threadIdx.x;
    if (i >= n4) return;
    float4 v = src[i];
    *reinterpret_cast<__half2*>(dst + (long)i * 4)     = __floats2half2_rn(v.x, v.y);
    *reinterpret_cast<__half2*>(dst + (long)i * 4 + 2) = __floats2half2_rn(v.z, v.w);
}

__global__ void embed_pe_kernel(const int* __restrict__ src, const float* __restrict__ pe,
                                const float* __restrict__ embed, float* __restrict__ x,
                                bf16* __restrict__ xh, bf16* __restrict__ xl)
{
    int row = blockIdx.x, b = row >> 10;
    long tok = src[row];
    const float4* e = reinterpret_cast<const float4*>(embed + tok * (long)DD);
    const float4* p = reinterpret_cast<const float4*>(pe + (long)b * DD);
    int i = threadIdx.x;
    float4 ev = e[i], pv = p[i];
    float4 v = make_float4(ev.x + pv.x, ev.y + pv.y, ev.z + pv.z, ev.w + pv.w);
    reinterpret_cast<float4*>(x + (long)row * DD)[i] = v;
    bf16 h0, l0, h1, l1, h2, l2, h3, l3;
    bsplit(v.x, h0, l0); bsplit(v.y, h1, l1); bsplit(v.z, h2, l2); bsplit(v.w, h3, l3);
    long o = (long)row * DD + i * 4;
    *reinterpret_cast<__nv_bfloat162*>(xh + o)     = __halves2bfloat162(h0, h1);
    *reinterpret_cast<__nv_bfloat162*>(xh + o + 2) = __halves2bfloat162(h2, h3);
    *reinterpret_cast<__nv_bfloat162*>(xl + o)     = __halves2bfloat162(l0, l1);
    *reinterpret_cast<__nv_bfloat162*>(xl + o + 2) = __halves2bfloat162(l2, l3);
}

__global__ void softmax_kernel(const float* __restrict__ A, bf16* __restrict__ Wh, bf16* __restrict__ Wl)
{
    int t = blockIdx.x, b = blockIdx.y;
    const float* row = A + ((long)b * TT + t) * TT;
    bf16* wh = Wh + ((long)b * TT + t) * TT;
    bf16* wl = Wl + ((long)b * TT + t) * TT;
    int n = t + 1, i = threadIdx.x;
    __shared__ float red[256];
    __shared__ float rowe[TT];
    float m = -1e30f;
    for (int s = i; s < n; s += 256) m = fmaxf(m, row[s]);
    red[i] = m; __syncthreads();
    for (int st = 128; st > 0; st >>= 1) { if (i < st) red[i] = fmaxf(red[i], red[i + st]); __syncthreads(); }
    m = red[0]; __syncthreads();
    float sum = 0.f;
    for (int s = i; s < n; s += 256) { float e = expf(row[s] - m); rowe[s] = e; sum += e; }
    red[i] = sum; __syncthreads();
    for (int st = 128; st > 0; st >>= 1) { if (i < st) red[i] += red[i + st]; __syncthreads(); }
    float inv = 1.0f / red[0];
    for (int s = i; s < TT; s += 256) {
        if (s < n) {
            float w = rowe[s] * inv;
            bf16 h, l; bsplit(w, h, l);
            wh[s] = h; wl[s] = l;
        } else {
            wh[s] = __float2bfloat16(0.f); wl[s] = __float2bfloat16(0.f);
        }
    }
}

__global__ void ln_res_kernel(const float* __restrict__ O, const float* __restrict__ w,
                              const float* __restrict__ bb, float* __restrict__ X,
                              bf16* __restrict__ xh, bf16* __restrict__ xl)
{
    int row = blockIdx.x, i = threadIdx.x;
    const float4 o = reinterpret_cast<const float4*>(O + (long)row * DD)[i];
    float4* x4 = reinterpret_cast<float4*>(X + (long)row * DD);
    __shared__ float red[256];
    red[i] = o.x + o.y + o.z + o.w; __syncthreads();
    for (int st = 128; st > 0; st >>= 1) { if (i < st) red[i] += red[i + st]; __syncthreads(); }
    float mu = red[0] * (1.0f / DD); __syncthreads();
    float dx = o.x - mu, dy = o.y - mu, dz = o.z - mu, dw_ = o.w - mu;
    red[i] = dx * dx + dy * dy + dz * dz + dw_ * dw_; __syncthreads();
    for (int st = 128; st > 0; st >>= 1) { if (i < st) red[i] += red[i + st]; __syncthreads(); }
    float rstd = rsqrtf(red[0] * (1.0f / DD) + 1e-6f);
    float4 wv = reinterpret_cast<const float4*>(w)[i];
    float4 bv = reinterpret_cast<const float4*>(bb)[i];
    float4 xv = x4[i];
    xv.x += dx * rstd * wv.x + bv.x;
    xv.y += dy * rstd * wv.y + bv.y;
    xv.z += dz * rstd * wv.z + bv.z;
    xv.w += dw_ * rstd * wv.w + bv.w;
    x4[i] = xv;
    bf16 h0, l0, h1, l1, h2, l2, h3, l3;
    bsplit(xv.x, h0, l0); bsplit(xv.y, h1, l1); bsplit(xv.z, h2, l2); bsplit(xv.w, h3, l3);
    long off = (long)row * DD + i * 4;
    *reinterpret_cast<__nv_bfloat162*>(xh + off)     = __halves2bfloat162(h0, h1);
    *reinterpret_cast<__nv_bfloat162*>(xh + off + 2) = __halves2bfloat162(h2, h3);
    *reinterpret_cast<__nv_bfloat162*>(xl + off)     = __halves2bfloat162(l0, l1);
    *reinterpret_cast<__nv_bfloat162*>(xl + off + 2) = __halves2bfloat162(l2, l3);
}

__global__ void final_ln_kernel(const float* __restrict__ X, const float* __restrict__ fw,
                                const float* __restrict__ fb, __half* __restrict__ Y)
{
    int row = blockIdx.x, i = threadIdx.x;
    const float4 x = reinterpret_cast<const float4*>(X + (long)row * DD)[i];
    __shared__ float red[256];
    red[i] = x.x + x.y + x.z + x.w; __syncthreads();
    for (int st = 128; st > 0; st >>= 1) { if (i < st) red[i] += red[i + st]; __syncthreads(); }
    float mu = red[0] * (1.0f / DD); __syncthreads();
    float dx = x.x - mu, dy = x.y - mu, dz = x.z - mu, dw_ = x.w - mu;
    red[i] = dx * dx + dy * dy + dz * dz + dw_ * dw_; __syncthreads();
    for (int st = 128; st > 0; st >>= 1) { if (i < st) red[i] += red[i + st]; __syncthreads(); }
    float rstd = rsqrtf(red[0] * (1.0f / DD) + 1e-5f);
    float4 wv = reinterpret_cast<const float4*>(fw)[i];
    float4 bv = reinterpret_cast<const float4*>(fb)[i];
    long off = (long)row * DD + i * 4;
    *reinterpret_cast<__half2*>(Y + off)     = __floats2half2_rn(dx * rstd * wv.x + bv.x, dy * rstd * wv.y + bv.y);
    *reinterpret_cast<__half2*>(Y + off + 2) = __floats2half2_rn(dz * rstd * wv.z + bv.z, dw_ * rstd * wv.w + bv.w);
}

// ---------------------------------------------------------------------------
extern "C" void kernel_launch(void* const* d_in, const int* in_sizes, int n_in,
                              void* d_out, int out_size)
{
    const int*   src = (const int*)d_in[0];
    const float* pe  = (const float*)d_in[1];
    const float* emb = (const float*)d_in[2];
    const float* qw  = (const float*)d_in[3];
    const float* qb  = (const float*)d_in[4];
    const float* kw  = (const float*)d_in[5];
    const float* kb  = (const float*)d_in[6];
    const float* vw  = (const float*)d_in[7];
    const float* vb  = (const float*)d_in[8];
    const float* lnw = (const float*)d_in[9];
    const float* lnb = (const float*)d_in[10];
    const float* fw  = (const float*)d_in[11];
    const float* fb  = (const float*)d_in[12];
    const float* dw  = (const float*)d_in[13];
    const float* db  = (const float*)d_in[14];
    float* out = (float*)d_out;

#define GA(sym, var) void* var##_; cudaGetSymbolAddress(&var##_, sym)
    GA(g_x, x);  GA(g_a, a);  GA(g_o, o);
    GA(g_xh, xh); GA(g_xl, xl);
    GA(g_qh, qh); GA(g_ql, ql); GA(g_kh, kh); GA(g_kl, kl);
    GA(g_vh, vh); GA(g_vl, vl); GA(g_wh, wh); GA(g_wl, wl);
    GA(g_qwh, qwh); GA(g_qwl, qwl); GA(g_kwh, kwh); GA(g_kwl, kwl);
    GA(g_vwh, vwh); GA(g_vwl, vwl);
    GA(g_dwh, dwh); GA(g_xnh, xnh);
#undef GA

    const int SMB = NSTAGE * 4 * BUFBY;   // 122880
    const int SMH = NSTAGE * 2 * BUFBY;   // 61440
    cudaFuncSetAttribute(qkv_kernel,   cudaFuncAttributeMaxDynamicSharedMemorySize, SMB);
    cudaFuncSetAttribute(sc_kernel,    cudaFuncAttributeMaxDynamicSharedMemorySize, SMB);
    cudaFuncSetAttribute(av_kernel,    cudaFuncAttributeMaxDynamicSharedMemorySize, SMB);
    cudaFuncSetAttribute(vocab_kernel, cudaFuncAttributeMaxDynamicSharedMemorySize, SMH);

    // one-time (per launch) weight conversions
    {
        const int n4w = LL * DD * DD / 4;
        splitw_kernel<<<(n4w + 511) / 512, 512>>>((const float4*)qw, (bf16*)qwh_, (bf16*)qwl_, n4w);
        splitw_kernel<<<(n4w + 511) / 512, 512>>>((const float4*)kw, (bf16*)kwh_, (bf16*)kwl_, n4w);
        splitw_kernel<<<(n4w + 511) / 512, 512>>>((const float4*)vw, (bf16*)vwh_, (bf16*)vwl_, n4w);
        const int n4d = VV * DD / 4;
        tohalf_kernel<<<(n4d + 511) / 512, 512>>>((const float4*)dw, (__half*)dwh_, n4d);
    }

    embed_pe_kernel<<<BB * TT, 256>>>(src, pe, emb, (float*)x_, (bf16*)xh_, (bf16*)xl_);

    dim3 gqkv(DD / 128, (BB * TT) / 128, 3);
    dim3 gs(TT / 128, TT / 128, BB);
    for (int l = 0; l < LL; l++) {
        const long wo = (long)l * DD * DD;
        QKVP p;
        p.xh = (const bf16*)xh_; p.xl = (const bf16*)xl_;
        p.qwh = (const bf16*)qwh_ + wo; p.qwl = (const bf16*)qwl_ + wo;
        p.kwh = (const bf16*)kwh_ + wo; p.kwl = (const bf16*)kwl_ + wo;
        p.vwh = (const bf16*)vwh_ + wo; p.vwl = (const bf16*)vwl_ + wo;
        p.qb = qb + l * DD; p.kb = kb + l * DD; p.vb = vb + l * DD;
        p.qh = (bf16*)qh_; p.ql = (bf16*)ql_;
        p.kh = (bf16*)kh_; p.kl = (bf16*)kl_;
        p.vh = (bf16*)vh_; p.vl = (bf16*)vl_;
        qkv_kernel<<<gqkv, 512, SMB>>>(p);
        sc_kernel<<<gs, 512, SMB>>>((const bf16*)qh_, (const bf16*)ql_,
                                    (const bf16*)kh_, (const bf16*)kl_, (float*)a_);
        softmax_kernel<<<dim3(TT, BB), 256>>>((const float*)a_, (bf16*)wh_, (bf16*)wl_);
        av_kernel<<<gs, 512, SMB>>>((const bf16*)wh_, (const bf16*)wl_,
                                    (const bf16*)vh_, (const bf16*)vl_, (float*)o_);
        ln_res_kernel<<<BB * TT, 256>>>((const float*)o_, lnw + l * DD, lnb + l * DD,
                                        (float*)x_, (bf16*)xh_, (bf16*)xl_);
    }

    final_ln_kernel<<<BB * TT, 256>>>((const float*)x_, fw, fb, (__half*)xnh_);
    dim3 gf(VV / 128, (BB * TT) / 128);
    vocab_kernel<<<gf, 512, SMH>>>((const __half*)xnh_, (const __half*)dwh_, db, out);
}

// round 9
// speedup vs baseline: 3.8830x; 1.0411x over previous
#include <cuda_runtime.h>
#include <cuda_bf16.h>
#include <cuda_fp16.h>
#include <cstdint>

#define BB 2
#define TT 1024
#define DD 1024
#define VV 32000
#define LL 8
#define MD (TT * DD)
#define AA (TT * TT)

typedef __nv_bfloat16 bf16;

// fp32 masters
__device__ float g_x[BB * MD];
__device__ float g_a[BB * AA];
__device__ float g_o[BB * MD];
// pre-split bf16 operands
__device__ bf16 g_xh[BB * MD], g_xl[BB * MD];
__device__ bf16 g_qh[BB * MD], g_ql[BB * MD];
__device__ bf16 g_kh[BB * MD], g_kl[BB * MD];
__device__ bf16 g_vh[BB * MD], g_vl[BB * MD];      // V^T [b][d][t]
__device__ bf16 g_wh[BB * AA], g_wl[BB * AA];
__device__ bf16 g_qwh[LL * DD * DD], g_qwl[LL * DD * DD];
__device__ bf16 g_kwh[LL * DD * DD], g_kwl[LL * DD * DD];
__device__ bf16 g_vwh[LL * DD * DD], g_vwl[LL * DD * DD];
__device__ __half g_dwh[VV * DD];
__device__ __half g_xnh[BB * TT * DD];

#define NSTAGE 3
// 64B rows + XOR swizzle: chunk c (16B) of row r lives at r*64 + (c ^ ((r>>1)&3))*16.
// Bank-start per row-phase = 16r+4c' mod 32: even rows get {0,4,8,12}<<?, odd rows
// the 16-offset half, each distinct -> conflict-free ldmatrix, no padding.
#define SWZ(r, c) ((((uint32_t)(r)) << 6) + ((((c) ^ (((r) >> 1) & 3))) << 4))

__device__ __forceinline__ uint32_t smem_u32(const void* p) {
    uint32_t a;
    asm("{ .reg .u64 t; cvta.to.shared.u64 t, %1; cvt.u32.u64 %0, t; }" : "=r"(a) : "l"(p));
    return a;
}
#define LDM4(r0, r1, r2, r3, ad) \
    asm volatile("ldmatrix.sync.aligned.m8n8.x4.shared.b16 {%0,%1,%2,%3},[%4];" \
                 : "=r"(r0), "=r"(r1), "=r"(r2), "=r"(r3) : "r"(ad))
#define MMA16B(c, a, b0_, b1_) \
    asm volatile("mma.sync.aligned.m16n8k16.row.col.f32.bf16.bf16.f32 " \
                 "{%0,%1,%2,%3},{%4,%5,%6,%7},{%8,%9},{%0,%1,%2,%3};" \
                 : "+f"((c)[0]), "+f"((c)[1]), "+f"((c)[2]), "+f"((c)[3]) \
                 : "r"((a)[0]), "r"((a)[1]), "r"((a)[2]), "r"((a)[3]), "r"(b0_), "r"(b1_))
#define MMA16H(c, a, b0_, b1_) \
    asm volatile("mma.sync.aligned.m16n8k16.row.col.f32.f16.f16.f32 " \
                 "{%0,%1,%2,%3},{%4,%5,%6,%7},{%8,%9},{%0,%1,%2,%3};" \
                 : "+f"((c)[0]), "+f"((c)[1]), "+f"((c)[2]), "+f"((c)[3]) \
                 : "r"((a)[0]), "r"((a)[1]), "r"((a)[2]), "r"((a)[3]), "r"(b0_), "r"(b1_))
#define CPA16(d, s) asm volatile("cp.async.cg.shared.global [%0], [%1], 16;" :: "r"(d), "l"(s))
#define CPCOMMIT()  asm volatile("cp.async.commit_group;" ::: "memory")
#define CPWAIT1()   asm volatile("cp.async.wait_group 1;" ::: "memory")

__device__ __forceinline__ void bsplit(float v, bf16& h, bf16& l) {
    h = __float2bfloat16_rn(v);
    l = __float2bfloat16_rn(v - __bfloat162float(h));
}

// ---------------------------------------------------------------------------
// bf16 3-term split GEMM core. MT=128: 512 thr, 16 warps (4x4 of 32x32).
// MT=64: 256 thr, 8 warps (2x4 of 32x32). N tile always 128, BK=32.
// BIAS: 0 none, 1 per-N, 2 per-M.  OUT: 0 fp32 Cf, 1 bf16 hi/lo Ch/Cl.
// ---------------------------------------------------------------------------
template <int MT, int BIAS, int OUT>
__device__ __forceinline__ void gemm_core(
    const bf16* __restrict__ Ah, const bf16* __restrict__ Al, int lda,
    const bf16* __restrict__ Bh, const bf16* __restrict__ Bl, int ldb,
    const float* __restrict__ bias,
    float* __restrict__ Cf, bf16* __restrict__ Ch, bf16* __restrict__ Cl, int ldc,
    int m0, int n0, int Keff)
{
    constexpr int ABY = MT * 64;        // A buffer bytes
    constexpr int BBY = 8192;           // B buffer bytes (128 rows)
    constexpr int STG = 2 * ABY + 2 * BBY;
    extern __shared__ uint16_t sm[];
    const uint32_t sb = smem_u32(sm);
    const int tid = threadIdx.x, lane = tid & 31, wrp = tid >> 5;
    const int wm = wrp >> 2, wn = wrp & 3;
    const int S = Keff >> 5;

    const int a_ml = (lane & 7) + ((lane >> 3) & 1) * 8;
    const int a_c0 = lane >> 4;             // chunk 0/1 within ks half
    const int b_nl = (lane & 7) + ((lane >> 4) << 3);
    const int b_c0 = (lane >> 3) & 1;

    const int row = tid >> 2, ch = tid & 3;     // staging coords
    const bf16* Aph = Ah + (long)(m0 + row) * lda + ch * 8;
    const bf16* Apl = Al + (long)(m0 + row) * lda + ch * 8;
    const bf16* Bph = Bh + (long)(n0 + row) * ldb + ch * 8;
    const bf16* Bpl = Bl + (long)(n0 + row) * ldb + ch * 8;
    const uint32_t swz = SWZ(row, ch);
    const uint32_t swz2 = SWZ(row + 64, ch);

    auto issue = [&](int s) {
        const int k0 = s << 5;
        const uint32_t db = sb + (uint32_t)(s % NSTAGE) * STG;
        CPA16(db + swz,             Aph + k0);
        CPA16(db + ABY + swz,       Apl + k0);
        CPA16(db + 2 * ABY + swz,   Bph + k0);
        CPA16(db + 2 * ABY + BBY + swz, Bpl + k0);
        if (MT == 64) {   // 256 thr cover only 64 B-rows per pass; do rows 64..127
            CPA16(db + 2 * ABY + swz2,       Bph + (long)64 * ldb + k0);
            CPA16(db + 2 * ABY + BBY + swz2, Bpl + (long)64 * ldb + k0);
        }
        CPCOMMIT();
    };

    float acc[2][4][4] = {};

    issue(0); issue(1);
    for (int s = 0; s < S; s++) {
        CPWAIT1();
        __syncthreads();
        const uint32_t stb = sb + (uint32_t)(s % NSTAGE) * STG;
        const uint32_t ahb = stb, alb = stb + ABY, bhb = stb + 2 * ABY, blb = bhb + BBY;
#pragma unroll
        for (int ks = 0; ks < 2; ks++) {
            uint32_t bhf[8], blf[8];
#pragma unroll
            for (int p = 0; p < 2; p++) {
                const uint32_t boff = SWZ(wn * 32 + p * 16 + b_nl, ks * 2 + b_c0);
                LDM4(bhf[p * 4 + 0], bhf[p * 4 + 1], bhf[p * 4 + 2], bhf[p * 4 + 3], bhb + boff);
                LDM4(blf[p * 4 + 0], blf[p * 4 + 1], blf[p * 4 + 2], blf[p * 4 + 3], blb + boff);
            }
#pragma unroll
            for (int mt = 0; mt < 2; mt++) {
                uint32_t ahf[4], alf[4];
                const uint32_t aoff = SWZ(wm * 32 + mt * 16 + a_ml, ks * 2 + a_c0);
                LDM4(ahf[0], ahf[1], ahf[2], ahf[3], ahb + aoff);
                LDM4(alf[0], alf[1], alf[2], alf[3], alb + aoff);
#pragma unroll
                for (int nt = 0; nt < 4; nt++) {
                    const int bi = (nt >> 1) * 4 + (nt & 1) * 2;
                    float* c = acc[mt][nt];
                    MMA16B(c, ahf, bhf[bi], bhf[bi + 1]);
                    MMA16B(c, ahf, blf[bi], blf[bi + 1]);
                    MMA16B(c, alf, bhf[bi], bhf[bi + 1]);
                }
            }
        }
        if (s + 2 < S) issue(s + 2); else CPCOMMIT();
    }

    const int er = lane >> 2, ec = (lane & 3) * 2;
#pragma unroll
    for (int mt = 0; mt < 2; mt++) {
        const int m = m0 + wm * 32 + mt * 16 + er;
        float bm0 = 0.f, bm8 = 0.f;
        if (BIAS == 2) { bm0 = bias[m]; bm8 = bias[m + 8]; }
#pragma unroll
        for (int nt = 0; nt < 4; nt++) {
            const int n = n0 + wn * 32 + nt * 8 + ec;
            float bn0 = 0.f, bn1 = 0.f;
            if (BIAS == 1) { bn0 = bias[n]; bn1 = bias[n + 1]; }
            const float* c = acc[mt][nt];
            float v00 = c[0] + bn0 + bm0, v01 = c[1] + bn1 + bm0;
            float v10 = c[2] + bn0 + bm8, v11 = c[3] + bn1 + bm8;
            if (OUT == 0) {
                *reinterpret_cast<float2*>(Cf + (long)m * ldc + n) = make_float2(v00, v01);
                *reinterpret_cast<float2*>(Cf + (long)(m + 8) * ldc + n) = make_float2(v10, v11);
            } else {
                bf16 h0, l0, h1, l1;
                bsplit(v00, h0, l0); bsplit(v01, h1, l1);
                *reinterpret_cast<__nv_bfloat162*>(Ch + (long)m * ldc + n) = __halves2bfloat162(h0, h1);
                *reinterpret_cast<__nv_bfloat162*>(Cl + (long)m * ldc + n) = __halves2bfloat162(l0, l1);
                bsplit(v10, h0, l0); bsplit(v11, h1, l1);
                *reinterpret_cast<__nv_bfloat162*>(Ch + (long)(m + 8) * ldc + n) = __halves2bfloat162(h0, h1);
                *reinterpret_cast<__nv_bfloat162*>(Cl + (long)(m + 8) * ldc + n) = __halves2bfloat162(l0, l1);
            }
        }
    }
}

// fp16 single-pass core (vocab GEMM): 512 thr, per-N bias, fp32 out.
__device__ __forceinline__ void gemm_core_h(
    const __half* __restrict__ A, int lda, const __half* __restrict__ B, int ldb,
    const float* __restrict__ bias, float* __restrict__ C, int ldc,
    int m0, int n0, int Keff)
{
    constexpr int BBY = 8192;
    constexpr int STG = 2 * BBY;
    extern __shared__ uint16_t sm[];
    const uint32_t sb = smem_u32(sm);
    const int tid = threadIdx.x, lane = tid & 31, wrp = tid >> 5;
    const int wm = wrp >> 2, wn = wrp & 3;
    const int S = Keff >> 5;

    const int a_ml = (lane & 7) + ((lane >> 3) & 1) * 8;
    const int a_c0 = lane >> 4;
    const int b_nl = (lane & 7) + ((lane >> 4) << 3);
    const int b_c0 = (lane >> 3) & 1;

    const int row = tid >> 2, ch = tid & 3;
    const __half* Ap = A + (long)(m0 + row) * lda + ch * 8;
    const __half* Bp = B + (long)(n0 + row) * ldb + ch * 8;
    const uint32_t swz = SWZ(row, ch);

    auto issue = [&](int s) {
        const int k0 = s << 5;
        const uint32_t db = sb + (uint32_t)(s % NSTAGE) * STG;
        CPA16(db + swz,       Ap + k0);
        CPA16(db + BBY + swz, Bp + k0);
        CPCOMMIT();
    };

    float acc[2][4][4] = {};
    issue(0); issue(1);
    for (int s = 0; s < S; s++) {
        CPWAIT1();
        __syncthreads();
        const uint32_t stb = sb + (uint32_t)(s % NSTAGE) * STG;
#pragma unroll
        for (int ks = 0; ks < 2; ks++) {
            uint32_t bhf[8];
#pragma unroll
            for (int p = 0; p < 2; p++) {
                const uint32_t boff = SWZ(wn * 32 + p * 16 + b_nl, ks * 2 + b_c0);
                LDM4(bhf[p * 4 + 0], bhf[p * 4 + 1], bhf[p * 4 + 2], bhf[p * 4 + 3], stb + BBY + boff);
            }
#pragma unroll
            for (int mt = 0; mt < 2; mt++) {
                uint32_t ahf[4];
                const uint32_t aoff = SWZ(wm * 32 + mt * 16 + a_ml, ks * 2 + a_c0);
                LDM4(ahf[0], ahf[1], ahf[2], ahf[3], stb + aoff);
#pragma unroll
                for (int nt = 0; nt < 4; nt++) {
                    const int bi = (nt >> 1) * 4 + (nt & 1) * 2;
                    MMA16H(acc[mt][nt], ahf, bhf[bi], bhf[bi + 1]);
                }
            }
        }
        if (s + 2 < S) issue(s + 2); else CPCOMMIT();
    }

    const int er = lane >> 2, ec = (lane & 3) * 2;
#pragma unroll
    for (int mt = 0; mt < 2; mt++) {
        const int m = m0 + wm * 32 + mt * 16 + er;
#pragma unroll
        for (int nt = 0; nt < 4; nt++) {
            const int n = n0 + wn * 32 + nt * 8 + ec;
            const float bn0 = bias[n], bn1 = bias[n + 1];
            const float* c = acc[mt][nt];
            *reinterpret_cast<float2*>(C + (long)m * ldc + n) = make_float2(c[0] + bn0, c[1] + bn1);
            *reinterpret_cast<float2*>(C + (long)(m + 8) * ldc + n) = make_float2(c[2] + bn0, c[3] + bn1);
        }
    }
}

// ---------------------------------------------------------------------------
// GEMM kernel wrappers
// ---------------------------------------------------------------------------
struct QKVP {
    const bf16 *xh, *xl;
    const bf16 *qwh, *qwl, *kwh, *kwl, *vwh, *vwl;
    const float *qb, *kb, *vb;
    bf16 *qh, *ql, *kh, *kl, *vh, *vl;
};

__global__ void __launch_bounds__(512) qkv_kernel(QKVP p)
{
    const int bx = blockIdx.x, by = blockIdx.y, bz = blockIdx.z;
    if (bz == 0) {
        gemm_core<128, 1, 1>(p.xh, p.xl, DD, p.qwh, p.qwl, DD, p.qb,
                             nullptr, p.qh, p.ql, DD, by * 128, bx * 128, DD);
    } else if (bz == 1) {
        gemm_core<128, 1, 1>(p.xh, p.xl, DD, p.kwh, p.kwl, DD, p.kb,
                             nullptr, p.kh, p.kl, DD, by * 128, bx * 128, DD);
    } else {
        const int b = by >> 3, dt = by & 7;
        gemm_core<128, 2, 1>(p.vwh, p.vwl, DD, p.xh + (long)b * MD, p.xl + (long)b * MD, DD, p.vb,
                             nullptr, p.vh + (long)b * MD, p.vl + (long)b * MD, TT,
                             dt * 128, bx * 128, DD);
    }
}

// scores: M-tile 64 (256 thr) -> 72 CTAs/batch, one full wave
__global__ void __launch_bounds__(256) sc_kernel(const bf16* __restrict__ qh, const bf16* __restrict__ ql,
                                                 const bf16* __restrict__ kh, const bf16* __restrict__ kl,
                                                 float* __restrict__ a)
{
    const int bx = blockIdx.x, by = blockIdx.y, b = blockIdx.z;
    if (2 * bx > by) return;    // n0 > m0+63
    gemm_core<64, 0, 0>(qh + (long)b * MD, ql + (long)b * MD, DD,
                        kh + (long)b * MD, kl + (long)b * MD, DD, nullptr,
                        a + (long)b * AA, nullptr, nullptr, TT, by * 64, bx * 128, DD);
}

__global__ void __launch_bounds__(512) av_kernel(const bf16* __restrict__ wh, const bf16* __restrict__ wl,
                                                 const bf16* __restrict__ vh, const bf16* __restrict__ vl,
                                                 float* __restrict__ o)
{
    const int bx = blockIdx.x, by = blockIdx.y, b = blockIdx.z;
    gemm_core<128, 0, 0>(wh + (long)b * AA, wl + (long)b * AA, TT,
                         vh + (long)b * MD, vl + (long)b * MD, TT, nullptr,
                         o + (long)b * MD, nullptr, nullptr, DD,
                         by * 128, bx * 128, min(TT, by * 128 + 128));
}

__global__ void __launch_bounds__(512) vocab_kernel(const __half* __restrict__ xn, const __half* __restrict__ dwh,
                                                    const float* __restrict__ db, float* __restrict__ out)
{
    gemm_core_h(xn, DD, dwh, DD, db, out, VV, blockIdx.y * 128, blockIdx.x * 128, DD);
}

// ---------------------------------------------------------------------------
// Converters + elementwise
// ---------------------------------------------------------------------------
__global__ void splitw_kernel(const float4* __restrict__ src, bf16* __restrict__ h,
                              bf16* __restrict__ l, int n4)
{
    int i = blockIdx.x * blockDim.x + threadIdx.x;
    if (i >= n4) return;
    float4 v = src[i];
    bf16 h0, l0, h1, l1, h2, l2, h3, l3;
    bsplit(v.x, h0, l0); bsplit(v.y, h1, l1); bsplit(v.z, h2, l2); bsplit(v.w, h3, l3);
    *reinterpret_cast<__nv_bfloat162*>(h + (long)i * 4)     = __halves2bfloat162(h0, h1);
    *reinterpret_cast<__nv_bfloat162*>(h + (long)i * 4 + 2) = __halves2bfloat162(h2, h3);
    *reinterpret_cast<__nv_bfloat162*>(l + (long)i * 4)     = __halves2bfloat162(l0, l1);
    *reinterpret_cast<__nv_bfloat162*>(l + (long)i * 4 + 2) = __halves2bfloat162(l2, l3);
}

__global__ void tohalf_kernel(const float4* __restrict__ src, __half* __restrict__ dst, int n4)
{
    int i = blockIdx.x * blockDim.x + threadIdx.x;
    if (i >= n4) return;
    float4 v = src[i];
    *reinterpret_cast<__half2*>(dst + (long)i * 4)     = __floats2half2_rn(v.x, v.y);
    *reinterpret_cast<__half2*>(dst + (long)i * 4 + 2) = __floats2half2_rn(v.z, v.w);
}

__global__ void embed_pe_kernel(const int* __restrict__ src, const float* __restrict__ pe,
                                const float* __restrict__ embed, float* __restrict__ x,
                                bf16* __restrict__ xh, bf16* __restrict__ xl)
{
    int row = blockIdx.x, b = row >> 10;
    long tok = src[row];
    const float4* e = reinterpret_cast<const float4*>(embed + tok * (long)DD);
    const float4* p = reinterpret_cast<const float4*>(pe + (long)b * DD);
    int i = threadIdx.x;
    float4 ev = e[i], pv = p[i];
    float4 v = make_float4(ev.x + pv.x, ev.y + pv.y, ev.z + pv.z, ev.w + pv.w);
    reinterpret_cast<float4*>(x + (long)row * DD)[i] = v;
    bf16 h0, l0, h1, l1, h2, l2, h3, l3;
    bsplit(v.x, h0, l0); bsplit(v.y, h1, l1); bsplit(v.z, h2, l2); bsplit(v.w, h3, l3);
    long o = (long)row * DD + i * 4;
    *reinterpret_cast<__nv_bfloat162*>(xh + o)     = __halves2bfloat162(h0, h1);
    *reinterpret_cast<__nv_bfloat162*>(xh + o + 2) = __halves2bfloat162(h2, h3);
    *reinterpret_cast<__nv_bfloat162*>(xl + o)     = __halves2bfloat162(l0, l1);
    *reinterpret_cast<__nv_bfloat162*>(xl + o + 2) = __halves2bfloat162(l2, l3);
}

__global__ void softmax_kernel(const float* __restrict__ A, bf16* __restrict__ Wh, bf16* __restrict__ Wl)
{
    int t = blockIdx.x, b = blockIdx.y;
    const float* row = A + ((long)b * TT + t) * TT;
    bf16* wh = Wh + ((long)b * TT + t) * TT;
    bf16* wl = Wl + ((long)b * TT + t) * TT;
    int n = t + 1, i = threadIdx.x;
    __shared__ float red[256];
    __shared__ float rowe[TT];
    float m = -1e30f;
    for (int s = i; s < n; s += 256) m = fmaxf(m, row[s]);
    red[i] = m; __syncthreads();
    for (int st = 128; st > 0; st >>= 1) { if (i < st) red[i] = fmaxf(red[i], red[i + st]); __syncthreads(); }
    m = red[0]; __syncthreads();
    float sum = 0.f;
    for (int s = i; s < n; s += 256) { float e = expf(row[s] - m); rowe[s] = e; sum += e; }
    red[i] = sum; __syncthreads();
    for (int st = 128; st > 0; st >>= 1) { if (i < st) red[i] += red[i + st]; __syncthreads(); }
    float inv = 1.0f / red[0];
    for (int s = i; s < TT; s += 256) {
        if (s < n) {
            float w = rowe[s] * inv;
            bf16 h, l; bsplit(w, h, l);
            wh[s] = h; wl[s] = l;
        } else {
            wh[s] = __float2bfloat16(0.f); wl[s] = __float2bfloat16(0.f);
        }
    }
}

__global__ void ln_res_kernel(const float* __restrict__ O, const float* __restrict__ w,
                              const float* __restrict__ bb, float* __restrict__ X,
                              bf16* __restrict__ xh, bf16* __restrict__ xl)
{
    int row = blockIdx.x, i = threadIdx.x;
    const float4 o = reinterpret_cast<const float4*>(O + (long)row * DD)[i];
    float4* x4 = reinterpret_cast<float4*>(X + (long)row * DD);
    __shared__ float red[256];
    red[i] = o.x + o.y + o.z + o.w; __syncthreads();
    for (int st = 128; st > 0; st >>= 1) { if (i < st) red[i] += red[i + st]; __syncthreads(); }
    float mu = red[0] * (1.0f / DD); __syncthreads();
    float dx = o.x - mu, dy = o.y - mu, dz = o.z - mu, dw_ = o.w - mu;
    red[i] = dx * dx + dy * dy + dz * dz + dw_ * dw_; __syncthreads();
    for (int st = 128; st > 0; st >>= 1) { if (i < st) red[i] += red[i + st]; __syncthreads(); }
    float rstd = rsqrtf(red[0] * (1.0f / DD) + 1e-6f);
    float4 wv = reinterpret_cast<const float4*>(w)[i];
    float4 bv = reinterpret_cast<const float4*>(bb)[i];
    float4 xv = x4[i];
    xv.x += dx * rstd * wv.x + bv.x;
    xv.y += dy * rstd * wv.y + bv.y;
    xv.z += dz * rstd * wv.z + bv.z;
    xv.w += dw_ * rstd * wv.w + bv.w;
    x4[i] = xv;
    bf16 h0, l0, h1, l1, h2, l2, h3, l3;
    bsplit(xv.x, h0, l0); bsplit(xv.y, h1, l1); bsplit(xv.z, h2, l2); bsplit(xv.w, h3, l3);
    long off = (long)row * DD + i * 4;
    *reinterpret_cast<__nv_bfloat162*>(xh + off)     = __halves2bfloat162(h0, h1);
    *reinterpret_cast<__nv_bfloat162*>(xh + off + 2) = __halves2bfloat162(h2, h3);
    *reinterpret_cast<__nv_bfloat162*>(xl + off)     = __halves2bfloat162(l0, l1);
    *reinterpret_cast<__nv_bfloat162*>(xl + off + 2) = __halves2bfloat162(l2, l3);
}

__global__ void final_ln_kernel(const float* __restrict__ X, const float* __restrict__ fw,
                                const float* __restrict__ fb, __half* __restrict__ Y)
{
    int row = blockIdx.x, i = threadIdx.x;
    const float4 x = reinterpret_cast<const float4*>(X + (long)row * DD)[i];
    __shared__ float red[256];
    red[i] = x.x + x.y + x.z + x.w; __syncthreads();
    for (int st = 128; st > 0; st >>= 1) { if (i < st) red[i] += red[i + st]; __syncthreads(); }
    float mu = red[0] * (1.0f / DD); __syncthreads();
    float dx = x.x - mu, dy = x.y - mu, dz = x.z - mu, dw_ = x.w - mu;
    red[i] = dx * dx + dy * dy + dz * dz + dw_ * dw_; __syncthreads();
    for (int st = 128; st > 0; st >>= 1) { if (i < st) red[i] += red[i + st]; __syncthreads(); }
    float rstd = rsqrtf(red[0] * (1.0f / DD) + 1e-5f);
    float4 wv = reinterpret_cast<const float4*>(fw)[i];
    float4 bv = reinterpret_cast<const float4*>(fb)[i];
    long off = (long)row * DD + i * 4;
    *reinterpret_cast<__half2*>(Y + off)     = __floats2half2_rn(dx * rstd * wv.x + bv.x, dy * rstd * wv.y + bv.y);
    *reinterpret_cast<__half2*>(Y + off + 2) = __floats2half2_rn(dz * rstd * wv.z + bv.z, dw_ * rstd * wv.w + bv.w);
}

// ---------------------------------------------------------------------------
extern "C" void kernel_launch(void* const* d_in, const int* in_sizes, int n_in,
                              void* d_out, int out_size)
{
    const int*   src = (const int*)d_in[0];
    const float* pe  = (const float*)d_in[1];
    const float* emb = (const float*)d_in[2];
    const float* qw  = (const float*)d_in[3];
    const float* qb  = (const float*)d_in[4];
    const float* kw  = (const float*)d_in[5];
    const float* kb  = (const float*)d_in[6];
    const float* vw  = (const float*)d_in[7];
    const float* vb  = (const float*)d_in[8];
    const float* lnw = (const float*)d_in[9];
    const float* lnb = (const float*)d_in[10];
    const float* fw  = (const float*)d_in[11];
    const float* fb  = (const float*)d_in[12];
    const float* dw  = (const float*)d_in[13];
    const float* db  = (const float*)d_in[14];
    float* out = (float*)d_out;

#define GA(sym, var) void* var##_; cudaGetSymbolAddress(&var##_, sym)
    GA(g_x, x);  GA(g_a, a);  GA(g_o, o);
    GA(g_xh, xh); GA(g_xl, xl);
    GA(g_qh, qh); GA(g_ql, ql); GA(g_kh, kh); GA(g_kl, kl);
    GA(g_vh, vh); GA(g_vl, vl); GA(g_wh, wh); GA(g_wl, wl);
    GA(g_qwh, qwh); GA(g_qwl, qwl); GA(g_kwh, kwh); GA(g_kwl, kwl);
    GA(g_vwh, vwh); GA(g_vwl, vwl);
    GA(g_dwh, dwh); GA(g_xnh, xnh);
#undef GA

    const int SMB = NSTAGE * (2 * 8192 + 2 * 8192);   // 98304 (MT=128)
    const int SMS = NSTAGE * (2 * 4096 + 2 * 8192);   // 73728 (MT=64)
    const int SMH = NSTAGE * 2 * 8192;                // 49152 (fp16)
    cudaFuncSetAttribute(qkv_kernel,   cudaFuncAttributeMaxDynamicSharedMemorySize, SMB);
    cudaFuncSetAttribute(sc_kernel,    cudaFuncAttributeMaxDynamicSharedMemorySize, SMS);
    cudaFuncSetAttribute(av_kernel,    cudaFuncAttributeMaxDynamicSharedMemorySize, SMB);
    cudaFuncSetAttribute(vocab_kernel, cudaFuncAttributeMaxDynamicSharedMemorySize, SMH);

    // per-launch weight conversions (deterministic, idempotent)
    {
        const int n4w = LL * DD * DD / 4;
        splitw_kernel<<<(n4w + 511) / 512, 512>>>((const float4*)qw, (bf16*)qwh_, (bf16*)qwl_, n4w);
        splitw_kernel<<<(n4w + 511) / 512, 512>>>((const float4*)kw, (bf16*)kwh_, (bf16*)kwl_, n4w);
        splitw_kernel<<<(n4w + 511) / 512, 512>>>((const float4*)vw, (bf16*)vwh_, (bf16*)vwl_, n4w);
        const int n4d = VV * DD / 4;
        tohalf_kernel<<<(n4d + 511) / 512, 512>>>((const float4*)dw, (__half*)dwh_, n4d);
    }

    embed_pe_kernel<<<BB * TT, 256>>>(src, pe, emb, (float*)x_, (bf16*)xh_, (bf16*)xl_);

    dim3 gqkv(DD / 128, (BB * TT) / 128, 3);
    dim3 gsc(TT / 128, TT / 64, BB);
    dim3 gav(TT / 128, TT / 128, BB);
    for (int l = 0; l < LL; l++) {
        const long wo = (long)l * DD * DD;
        QKVP p;
        p.xh = (const bf16*)xh_; p.xl = (const bf16*)xl_;
        p.qwh = (const bf16*)qwh_ + wo; p.qwl = (const bf16*)qwl_ + wo;
        p.kwh = (const bf16*)kwh_ + wo; p.kwl = (const bf16*)kwl_ + wo;
        p.vwh = (const bf16*)vwh_ + wo; p.vwl = (const bf16*)vwl_ + wo;
        p.qb = qb + l * DD; p.kb = kb + l * DD; p.vb = vb + l * DD;
        p.qh = (bf16*)qh_; p.ql = (bf16*)ql_;
        p.kh = (bf16*)kh_; p.kl = (bf16*)kl_;
        p.vh = (bf16*)vh_; p.vl = (bf16*)vl_;
        qkv_kernel<<<gqkv, 512, SMB>>>(p);
        sc_kernel<<<gsc, 256, SMS>>>((const bf16*)qh_, (const bf16*)ql_,
                                     (const bf16*)kh_, (const bf16*)kl_, (float*)a_);
        softmax_kernel<<<dim3(TT, BB), 256>>>((const float*)a_, (bf16*)wh_, (bf16*)wl_);
        av_kernel<<<gav, 512, SMB>>>((const bf16*)wh_, (const bf16*)wl_,
                                     (const bf16*)vh_, (const bf16*)vl_, (float*)o_);
        ln_res_kernel<<<BB * TT, 256>>>((const float*)o_, lnw + l * DD, lnb + l * DD,
                                        (float*)x_, (bf16*)xh_, (bf16*)xl_);
    }

    final_ln_kernel<<<BB * TT, 256>>>((const float*)x_, fw, fb, (__half*)xnh_);
    dim3 gf(VV / 128, (BB * TT) / 128);
    vocab_kernel<<<gf, 512, SMH>>>((const __half*)xnh_, (const __half*)dwh_, db, out);
}

// round 10
// speedup vs baseline: 4.5906x; 1.1822x over previous
#include <cuda_runtime.h>
#include <cuda_bf16.h>
#include <cuda_fp16.h>
#include <cstdint>

#define BB 2
#define TT 1024
#define DD 1024
#define VV 32000
#define LL 8
#define MD (TT * DD)
#define AA (TT * TT)

typedef __nv_bfloat16 bf16;

// fp32 masters
__device__ float g_x[BB * MD];
__device__ float g_a[BB * AA];
__device__ float g_o[BB * MD];
// split bf16 operands (accurate path: x, Q, K, weights qw/kw)
__device__ bf16 g_xh[BB * MD], g_xl[BB * MD];
__device__ bf16 g_qh[BB * MD], g_ql[BB * MD];
__device__ bf16 g_kh[BB * MD], g_kl[BB * MD];
__device__ bf16 g_qwh[LL * DD * DD], g_qwl[LL * DD * DD];
__device__ bf16 g_kwh[LL * DD * DD], g_kwl[LL * DD * DD];
// single fp16 operands (relaxed path: V, w, vw, dw, xn, x-as-fp16)
__device__ __half g_xf[BB * MD];
__device__ __half g_vf[BB * MD];          // V^T [b][d][t]
__device__ __half g_wf[BB * AA];
__device__ __half g_vwf[LL * DD * DD];
__device__ __half g_dwf[VV * DD];
__device__ __half g_xnf[BB * MD];

#define NSTAGE 3
// 64B rows + XOR swizzle: chunk c (16B) of row r at r*64 + (c ^ ((r>>1)&3))*16.
// Conflict-free for ldmatrix (8 rows cover all 32 banks exactly once).
#define SWZ(r, c) ((((uint32_t)(r)) << 6) + ((((c) ^ (((r) >> 1) & 3))) << 4))

__device__ __forceinline__ uint32_t smem_u32(const void* p) {
    uint32_t a;
    asm("{ .reg .u64 t; cvta.to.shared.u64 t, %1; cvt.u32.u64 %0, t; }" : "=r"(a) : "l"(p));
    return a;
}
#define LDM4(r0, r1, r2, r3, ad) \
    asm volatile("ldmatrix.sync.aligned.m8n8.x4.shared.b16 {%0,%1,%2,%3},[%4];" \
                 : "=r"(r0), "=r"(r1), "=r"(r2), "=r"(r3) : "r"(ad))
#define MMA16B(c, a, b0_, b1_) \
    asm volatile("mma.sync.aligned.m16n8k16.row.col.f32.bf16.bf16.f32 " \
                 "{%0,%1,%2,%3},{%4,%5,%6,%7},{%8,%9},{%0,%1,%2,%3};" \
                 : "+f"((c)[0]), "+f"((c)[1]), "+f"((c)[2]), "+f"((c)[3]) \
                 : "r"((a)[0]), "r"((a)[1]), "r"((a)[2]), "r"((a)[3]), "r"(b0_), "r"(b1_))
#define MMA16H(c, a, b0_, b1_) \
    asm volatile("mma.sync.aligned.m16n8k16.row.col.f32.f16.f16.f32 " \
                 "{%0,%1,%2,%3},{%4,%5,%6,%7},{%8,%9},{%0,%1,%2,%3};" \
                 : "+f"((c)[0]), "+f"((c)[1]), "+f"((c)[2]), "+f"((c)[3]) \
                 : "r"((a)[0]), "r"((a)[1]), "r"((a)[2]), "r"((a)[3]), "r"(b0_), "r"(b1_))
#define CPA16(d, s) asm volatile("cp.async.cg.shared.global [%0], [%1], 16;" :: "r"(d), "l"(s))
#define CPCOMMIT()  asm volatile("cp.async.commit_group;" ::: "memory")
#define CPWAIT1()   asm volatile("cp.async.wait_group 1;" ::: "memory")

__device__ __forceinline__ void bsplit(float v, bf16& h, bf16& l) {
    h = __float2bfloat16_rn(v);
    l = __float2bfloat16_rn(v - __bfloat162float(h));
}

// ---------------------------------------------------------------------------
// bf16 3-term split GEMM core. MT=128: 512 thr (4x4 warps of 32x32).
// MT=64: 256 thr (2x4 warps). N tile 128, BK=32.
// BIAS: 0 none, 1 per-N.  OUT: 0 fp32 Cf, 1 bf16 hi/lo Ch/Cl.
// ---------------------------------------------------------------------------
template <int MT, int BIAS, int OUT>
__device__ __forceinline__ void gemm_core(
    const bf16* __restrict__ Ah, const bf16* __restrict__ Al, int lda,
    const bf16* __restrict__ Bh, const bf16* __restrict__ Bl, int ldb,
    const float* __restrict__ bias,
    float* __restrict__ Cf, bf16* __restrict__ Ch, bf16* __restrict__ Cl, int ldc,
    int m0, int n0, int Keff)
{
    constexpr int ABY = MT * 64;
    constexpr int BBY = 8192;
    constexpr int STG = 2 * ABY + 2 * BBY;
    extern __shared__ uint16_t sm[];
    const uint32_t sb = smem_u32(sm);
    const int tid = threadIdx.x, lane = tid & 31, wrp = tid >> 5;
    const int wm = wrp >> 2, wn = wrp & 3;
    const int S = Keff >> 5;

    const int a_ml = (lane & 7) + ((lane >> 3) & 1) * 8;
    const int a_c0 = lane >> 4;
    const int b_nl = (lane & 7) + ((lane >> 4) << 3);
    const int b_c0 = (lane >> 3) & 1;

    const int row = tid >> 2, ch = tid & 3;
    const bf16* Aph = Ah + (long)(m0 + row) * lda + ch * 8;
    const bf16* Apl = Al + (long)(m0 + row) * lda + ch * 8;
    const bf16* Bph = Bh + (long)(n0 + row) * ldb + ch * 8;
    const bf16* Bpl = Bl + (long)(n0 + row) * ldb + ch * 8;
    const uint32_t swz = SWZ(row, ch);
    const uint32_t swz2 = SWZ(row + 64, ch);

    auto issue = [&](int s) {
        const int k0 = s << 5;
        const uint32_t db = sb + (uint32_t)(s % NSTAGE) * STG;
        CPA16(db + swz,                 Aph + k0);
        CPA16(db + ABY + swz,           Apl + k0);
        CPA16(db + 2 * ABY + swz,       Bph + k0);
        CPA16(db + 2 * ABY + BBY + swz, Bpl + k0);
        if (MT == 64) {
            CPA16(db + 2 * ABY + swz2,       Bph + (long)64 * ldb + k0);
            CPA16(db + 2 * ABY + BBY + swz2, Bpl + (long)64 * ldb + k0);
        }
        CPCOMMIT();
    };

    float acc[2][4][4] = {};
    issue(0); issue(1);
    for (int s = 0; s < S; s++) {
        CPWAIT1();
        __syncthreads();
        const uint32_t stb = sb + (uint32_t)(s % NSTAGE) * STG;
        const uint32_t ahb = stb, alb = stb + ABY, bhb = stb + 2 * ABY, blb = bhb + BBY;
#pragma unroll
        for (int ks = 0; ks < 2; ks++) {
            uint32_t bhf[8], blf[8];
#pragma unroll
            for (int p = 0; p < 2; p++) {
                const uint32_t boff = SWZ(wn * 32 + p * 16 + b_nl, ks * 2 + b_c0);
                LDM4(bhf[p * 4 + 0], bhf[p * 4 + 1], bhf[p * 4 + 2], bhf[p * 4 + 3], bhb + boff);
                LDM4(blf[p * 4 + 0], blf[p * 4 + 1], blf[p * 4 + 2], blf[p * 4 + 3], blb + boff);
            }
#pragma unroll
            for (int mt = 0; mt < 2; mt++) {
                uint32_t ahf[4], alf[4];
                const uint32_t aoff = SWZ(wm * 32 + mt * 16 + a_ml, ks * 2 + a_c0);
                LDM4(ahf[0], ahf[1], ahf[2], ahf[3], ahb + aoff);
                LDM4(alf[0], alf[1], alf[2], alf[3], alb + aoff);
#pragma unroll
                for (int nt = 0; nt < 4; nt++) {
                    const int bi = (nt >> 1) * 4 + (nt & 1) * 2;
                    float* c = acc[mt][nt];
                    MMA16B(c, ahf, bhf[bi], bhf[bi + 1]);
                    MMA16B(c, ahf, blf[bi], blf[bi + 1]);
                    MMA16B(c, alf, bhf[bi], bhf[bi + 1]);
                }
            }
        }
        if (s + 2 < S) issue(s + 2); else CPCOMMIT();
    }

    const int er = lane >> 2, ec = (lane & 3) * 2;
#pragma unroll
    for (int mt = 0; mt < 2; mt++) {
        const int m = m0 + wm * 32 + mt * 16 + er;
#pragma unroll
        for (int nt = 0; nt < 4; nt++) {
            const int n = n0 + wn * 32 + nt * 8 + ec;
            float bn0 = 0.f, bn1 = 0.f;
            if (BIAS == 1) { bn0 = bias[n]; bn1 = bias[n + 1]; }
            const float* c = acc[mt][nt];
            float v00 = c[0] + bn0, v01 = c[1] + bn1;
            float v10 = c[2] + bn0, v11 = c[3] + bn1;
            if (OUT == 0) {
                *reinterpret_cast<float2*>(Cf + (long)m * ldc + n) = make_float2(v00, v01);
                *reinterpret_cast<float2*>(Cf + (long)(m + 8) * ldc + n) = make_float2(v10, v11);
            } else {
                bf16 h0, l0, h1, l1;
                bsplit(v00, h0, l0); bsplit(v01, h1, l1);
                *reinterpret_cast<__nv_bfloat162*>(Ch + (long)m * ldc + n) = __halves2bfloat162(h0, h1);
                *reinterpret_cast<__nv_bfloat162*>(Cl + (long)m * ldc + n) = __halves2bfloat162(l0, l1);
                bsplit(v10, h0, l0); bsplit(v11, h1, l1);
                *reinterpret_cast<__nv_bfloat162*>(Ch + (long)(m + 8) * ldc + n) = __halves2bfloat162(h0, h1);
                *reinterpret_cast<__nv_bfloat162*>(Cl + (long)(m + 8) * ldc + n) = __halves2bfloat162(l0, l1);
            }
        }
    }
}

// ---------------------------------------------------------------------------
// fp16 single-pass core: 512 thr, 128x128 tile.
// BIAS: 0 none, 1 per-N, 2 per-M.  OUT: 0 fp32 Cf, 1 fp16 Chf.
// ---------------------------------------------------------------------------
template <int BIAS, int OUT>
__device__ __forceinline__ void gemm_core_h(
    const __half* __restrict__ A, int lda, const __half* __restrict__ B, int ldb,
    const float* __restrict__ bias,
    float* __restrict__ Cf, __half* __restrict__ Chf, int ldc,
    int m0, int n0, int Keff)
{
    constexpr int BBY = 8192;
    constexpr int STG = 2 * BBY;
    extern __shared__ uint16_t sm[];
    const uint32_t sb = smem_u32(sm);
    const int tid = threadIdx.x, lane = tid & 31, wrp = tid >> 5;
    const int wm = wrp >> 2, wn = wrp & 3;
    const int S = Keff >> 5;

    const int a_ml = (lane & 7) + ((lane >> 3) & 1) * 8;
    const int a_c0 = lane >> 4;
    const int b_nl = (lane & 7) + ((lane >> 4) << 3);
    const int b_c0 = (lane >> 3) & 1;

    const int row = tid >> 2, ch = tid & 3;
    const __half* Ap = A + (long)(m0 + row) * lda + ch * 8;
    const __half* Bp = B + (long)(n0 + row) * ldb + ch * 8;
    const uint32_t swz = SWZ(row, ch);

    auto issue = [&](int s) {
        const int k0 = s << 5;
        const uint32_t db = sb + (uint32_t)(s % NSTAGE) * STG;
        CPA16(db + swz,       Ap + k0);
        CPA16(db + BBY + swz, Bp + k0);
        CPCOMMIT();
    };

    float acc[2][4][4] = {};
    issue(0); issue(1);
    for (int s = 0; s < S; s++) {
        CPWAIT1();
        __syncthreads();
        const uint32_t stb = sb + (uint32_t)(s % NSTAGE) * STG;
#pragma unroll
        for (int ks = 0; ks < 2; ks++) {
            uint32_t bhf[8];
#pragma unroll
            for (int p = 0; p < 2; p++) {
                const uint32_t boff = SWZ(wn * 32 + p * 16 + b_nl, ks * 2 + b_c0);
                LDM4(bhf[p * 4 + 0], bhf[p * 4 + 1], bhf[p * 4 + 2], bhf[p * 4 + 3], stb + BBY + boff);
            }
#pragma unroll
            for (int mt = 0; mt < 2; mt++) {
                uint32_t ahf[4];
                const uint32_t aoff = SWZ(wm * 32 + mt * 16 + a_ml, ks * 2 + a_c0);
                LDM4(ahf[0], ahf[1], ahf[2], ahf[3], stb + aoff);
#pragma unroll
                for (int nt = 0; nt < 4; nt++) {
                    const int bi = (nt >> 1) * 4 + (nt & 1) * 2;
                    MMA16H(acc[mt][nt], ahf, bhf[bi], bhf[bi + 1]);
                }
            }
        }
        if (s + 2 < S) issue(s + 2); else CPCOMMIT();
    }

    const int er = lane >> 2, ec = (lane & 3) * 2;
#pragma unroll
    for (int mt = 0; mt < 2; mt++) {
        const int m = m0 + wm * 32 + mt * 16 + er;
        float bm0 = 0.f, bm8 = 0.f;
        if (BIAS == 2) { bm0 = bias[m]; bm8 = bias[m + 8]; }
#pragma unroll
        for (int nt = 0; nt < 4; nt++) {
            const int n = n0 + wn * 32 + nt * 8 + ec;
            float bn0 = 0.f, bn1 = 0.f;
            if (BIAS == 1) { bn0 = bias[n]; bn1 = bias[n + 1]; }
            const float* c = acc[mt][nt];
            float v00 = c[0] + bn0 + bm0, v01 = c[1] + bn1 + bm0;
            float v10 = c[2] + bn0 + bm8, v11 = c[3] + bn1 + bm8;
            if (OUT == 0) {
                *reinterpret_cast<float2*>(Cf + (long)m * ldc + n) = make_float2(v00, v01);
                *reinterpret_cast<float2*>(Cf + (long)(m + 8) * ldc + n) = make_float2(v10, v11);
            } else {
                *reinterpret_cast<__half2*>(Chf + (long)m * ldc + n) = __floats2half2_rn(v00, v01);
                *reinterpret_cast<__half2*>(Chf + (long)(m + 8) * ldc + n) = __floats2half2_rn(v10, v11);
            }
        }
    }
}

// ---------------------------------------------------------------------------
// Kernel wrappers
// ---------------------------------------------------------------------------
struct QKVP {
    const bf16 *xh, *xl;
    const __half *xf;
    const bf16 *qwh, *qwl, *kwh, *kwl;
    const __half *vwf;
    const float *qb, *kb, *vb;
    bf16 *qh, *ql, *kh, *kl;
    __half *vf;
};

__global__ void __launch_bounds__(512) qkv_kernel(QKVP p)
{
    const int bx = blockIdx.x, by = blockIdx.y, bz = blockIdx.z;
    if (bz == 0) {
        gemm_core<128, 1, 1>(p.xh, p.xl, DD, p.qwh, p.qwl, DD, p.qb,
                             nullptr, p.qh, p.ql, DD, by * 128, bx * 128, DD);
    } else if (bz == 1) {
        gemm_core<128, 1, 1>(p.xh, p.xl, DD, p.kwh, p.kwl, DD, p.kb,
                             nullptr, p.kh, p.kl, DD, by * 128, bx * 128, DD);
    } else {
        // V^T = vw @ x^T, single fp16, per-M bias, fp16 out
        const int b = by >> 3, dt = by & 7;
        gemm_core_h<2, 1>(p.vwf, DD, p.xf + (long)b * MD, DD, p.vb,
                          nullptr, p.vf + (long)b * MD, TT, dt * 128, bx * 128, DD);
    }
}

// scores: split bf16, M-tile 64 (256 thr), causal skip
__global__ void __launch_bounds__(256) sc_kernel(const bf16* __restrict__ qh, const bf16* __restrict__ ql,
                                                 const bf16* __restrict__ kh, const bf16* __restrict__ kl,
                                                 float* __restrict__ a)
{
    const int bx = blockIdx.x, by = blockIdx.y, b = blockIdx.z;
    if (2 * bx > by) return;
    gemm_core<64, 0, 0>(qh + (long)b * MD, ql + (long)b * MD, DD,
                        kh + (long)b * MD, kl + (long)b * MD, DD, nullptr,
                        a + (long)b * AA, nullptr, nullptr, TT, by * 64, bx * 128, DD);
}

// o = w @ V, single fp16, K-limited
__global__ void __launch_bounds__(512) av_kernel(const __half* __restrict__ wf,
                                                 const __half* __restrict__ vf,
                                                 float* __restrict__ o)
{
    const int bx = blockIdx.x, by = blockIdx.y, b = blockIdx.z;
    gemm_core_h<0, 0>(wf + (long)b * AA, TT, vf + (long)b * MD, TT, nullptr,
                      o + (long)b * MD, nullptr, DD,
                      by * 128, bx * 128, min(TT, by * 128 + 128));
}

__global__ void __launch_bounds__(512) vocab_kernel(const __half* __restrict__ xn, const __half* __restrict__ dwf,
                                                    const float* __restrict__ db, float* __restrict__ out)
{
    gemm_core_h<1, 0>(xn, DD, dwf, DD, db, out, nullptr, VV, blockIdx.y * 128, blockIdx.x * 128, DD);
}

// ---------------------------------------------------------------------------
// Converters + elementwise
// ---------------------------------------------------------------------------
__global__ void splitw_kernel(const float4* __restrict__ src, bf16* __restrict__ h,
                              bf16* __restrict__ l, int n4)
{
    int i = blockIdx.x * blockDim.x + threadIdx.x;
    if (i >= n4) return;
    float4 v = src[i];
    bf16 h0, l0, h1, l1, h2, l2, h3, l3;
    bsplit(v.x, h0, l0); bsplit(v.y, h1, l1); bsplit(v.z, h2, l2); bsplit(v.w, h3, l3);
    *reinterpret_cast<__nv_bfloat162*>(h + (long)i * 4)     = __halves2bfloat162(h0, h1);
    *reinterpret_cast<__nv_bfloat162*>(h + (long)i * 4 + 2) = __halves2bfloat162(h2, h3);
    *reinterpret_cast<__nv_bfloat162*>(l + (long)i * 4)     = __halves2bfloat162(l0, l1);
    *reinterpret_cast<__nv_bfloat162*>(l + (long)i * 4 + 2) = __halves2bfloat162(l2, l3);
}

__global__ void tohalf_kernel(const float4* __restrict__ src, __half* __restrict__ dst, int n4)
{
    int i = blockIdx.x * blockDim.x + threadIdx.x;
    if (i >= n4) return;
    float4 v = src[i];
    *reinterpret_cast<__half2*>(dst + (long)i * 4)     = __floats2half2_rn(v.x, v.y);
    *reinterpret_cast<__half2*>(dst + (long)i * 4 + 2) = __floats2half2_rn(v.z, v.w);
}

__device__ __forceinline__ void store_x3(float4 v, long off, float* X,
                                         bf16* xh, bf16* xl, __half* xf)
{
    if (X) *reinterpret_cast<float4*>(X + off) = v;
    bf16 h0, l0, h1, l1, h2, l2, h3, l3;
    bsplit(v.x, h0, l0); bsplit(v.y, h1, l1); bsplit(v.z, h2, l2); bsplit(v.w, h3, l3);
    *reinterpret_cast<__nv_bfloat162*>(xh + off)     = __halves2bfloat162(h0, h1);
    *reinterpret_cast<__nv_bfloat162*>(xh + off + 2) = __halves2bfloat162(h2, h3);
    *reinterpret_cast<__nv_bfloat162*>(xl + off)     = __halves2bfloat162(l0, l1);
    *reinterpret_cast<__nv_bfloat162*>(xl + off + 2) = __halves2bfloat162(l2, l3);
    *reinterpret_cast<__half2*>(xf + off)     = __floats2half2_rn(v.x, v.y);
    *reinterpret_cast<__half2*>(xf + off + 2) = __floats2half2_rn(v.z, v.w);
}

__global__ void embed_pe_kernel(const int* __restrict__ src, const float* __restrict__ pe,
                                const float* __restrict__ embed, float* __restrict__ x,
                                bf16* __restrict__ xh, bf16* __restrict__ xl, __half* __restrict__ xf)
{
    int row = blockIdx.x, b = row >> 10;
    long tok = src[row];
    const float4* e = reinterpret_cast<const float4*>(embed + tok * (long)DD);
    const float4* p = reinterpret_cast<const float4*>(pe + (long)b * DD);
    int i = threadIdx.x;
    float4 ev = e[i], pv = p[i];
    float4 v = make_float4(ev.x + pv.x, ev.y + pv.y, ev.z + pv.z, ev.w + pv.w);
    store_x3(v, (long)row * DD + i * 4, x, xh, xl, xf);
}

__global__ void softmax_kernel(const float* __restrict__ A, __half* __restrict__ Wf)
{
    int t = blockIdx.x, b = blockIdx.y;
    const float* row = A + ((long)b * TT + t) * TT;
    __half* wf = Wf + ((long)b * TT + t) * TT;
    int n = t + 1, i = threadIdx.x;
    __shared__ float red[256];
    __shared__ float rowe[TT];
    float m = -1e30f;
    for (int s = i; s < n; s += 256) m = fmaxf(m, row[s]);
    red[i] = m; __syncthreads();
    for (int st = 128; st > 0; st >>= 1) { if (i < st) red[i] = fmaxf(red[i], red[i + st]); __syncthreads(); }
    m = red[0]; __syncthreads();
    float sum = 0.f;
    for (int s = i; s < n; s += 256) { float e = expf(row[s] - m); rowe[s] = e; sum += e; }
    red[i] = sum; __syncthreads();
    for (int st = 128; st > 0; st >>= 1) { if (i < st) red[i] += red[i + st]; __syncthreads(); }
    float inv = 1.0f / red[0];
    for (int s = i; s < TT; s += 256)
        wf[s] = (s < n) ? __float2half_rn(rowe[s] * inv) : __float2half_rn(0.f);
}

__global__ void ln_res_kernel(const float* __restrict__ O, const float* __restrict__ w,
                              const float* __restrict__ bb, float* __restrict__ X,
                              bf16* __restrict__ xh, bf16* __restrict__ xl, __half* __restrict__ xf)
{
    int row = blockIdx.x, i = threadIdx.x;
    const float4 o = reinterpret_cast<const float4*>(O + (long)row * DD)[i];
    float4* x4 = reinterpret_cast<float4*>(X + (long)row * DD);
    __shared__ float red[256];
    red[i] = o.x + o.y + o.z + o.w; __syncthreads();
    for (int st = 128; st > 0; st >>= 1) { if (i < st) red[i] += red[i + st]; __syncthreads(); }
    float mu = red[0] * (1.0f / DD); __syncthreads();
    float dx = o.x - mu, dy = o.y - mu, dz = o.z - mu, dw_ = o.w - mu;
    red[i] = dx * dx + dy * dy + dz * dz + dw_ * dw_; __syncthreads();
    for (int st = 128; st > 0; st >>= 1) { if (i < st) red[i] += red[i + st]; __syncthreads(); }
    float rstd = rsqrtf(red[0] * (1.0f / DD) + 1e-6f);
    float4 wv = reinterpret_cast<const float4*>(w)[i];
    float4 bv = reinterpret_cast<const float4*>(bb)[i];
    float4 xv = x4[i];
    xv.x += dx * rstd * wv.x + bv.x;
    xv.y += dy * rstd * wv.y + bv.y;
    xv.z += dz * rstd * wv.z + bv.z;
    xv.w += dw_ * rstd * wv.w + bv.w;
    x4[i] = xv;
    store_x3(xv, (long)row * DD + i * 4, nullptr, xh, xl, xf);
}

__global__ void final_ln_kernel(const float* __restrict__ X, const float* __restrict__ fw,
                                const float* __restrict__ fb, __half* __restrict__ Y)
{
    int row = blockIdx.x, i = threadIdx.x;
    const float4 x = reinterpret_cast<const float4*>(X + (long)row * DD)[i];
    __shared__ float red[256];
    red[i] = x.x + x.y + x.z + x.w; __syncthreads();
    for (int st = 128; st > 0; st >>= 1) { if (i < st) red[i] += red[i + st]; __syncthreads(); }
    float mu = red[0] * (1.0f / DD); __syncthreads();
    float dx = x.x - mu, dy = x.y - mu, dz = x.z - mu, dw_ = x.w - mu;
    red[i] = dx * dx + dy * dy + dz * dz + dw_ * dw_; __syncthreads();
    for (int st = 128; st > 0; st >>= 1) { if (i < st) red[i] += red[i + st]; __syncthreads(); }
    float rstd = rsqrtf(red[0] * (1.0f / DD) + 1e-5f);
    float4 wv = reinterpret_cast<const float4*>(fw)[i];
    float4 bv = reinterpret_cast<const float4*>(fb)[i];
    long off = (long)row * DD + i * 4;
    *reinterpret_cast<__half2*>(Y + off)     = __floats2half2_rn(dx * rstd * wv.x + bv.x, dy * rstd * wv.y + bv.y);
    *reinterpret_cast<__half2*>(Y + off + 2) = __floats2half2_rn(dz * rstd * wv.z + bv.z, dw_ * rstd * wv.w + bv.w);
}

// ---------------------------------------------------------------------------
extern "C" void kernel_launch(void* const* d_in, const int* in_sizes, int n_in,
                              void* d_out, int out_size)
{
    const int*   src = (const int*)d_in[0];
    const float* pe  = (const float*)d_in[1];
    const float* emb = (const float*)d_in[2];
    const float* qw  = (const float*)d_in[3];
    const float* qb  = (const float*)d_in[4];
    const float* kw  = (const float*)d_in[5];
    const float* kb  = (const float*)d_in[6];
    const float* vw  = (const float*)d_in[7];
    const float* vb  = (const float*)d_in[8];
    const float* lnw = (const float*)d_in[9];
    const float* lnb = (const float*)d_in[10];
    const float* fw  = (const float*)d_in[11];
    const float* fb  = (const float*)d_in[12];
    const float* dw  = (const float*)d_in[13];
    const float* db  = (const float*)d_in[14];
    float* out = (float*)d_out;

#define GA(sym, var) void* var##_; cudaGetSymbolAddress(&var##_, sym)
    GA(g_x, x);  GA(g_a, a);  GA(g_o, o);
    GA(g_xh, xh); GA(g_xl, xl); GA(g_xf, xf);
    GA(g_qh, qh); GA(g_ql, ql); GA(g_kh, kh); GA(g_kl, kl);
    GA(g_vf, vf); GA(g_wf, wf);
    GA(g_qwh, qwh); GA(g_qwl, qwl); GA(g_kwh, kwh); GA(g_kwl, kwl);
    GA(g_vwf, vwf); GA(g_dwf, dwf); GA(g_xnf, xnf);
#undef GA

    const int SMB = NSTAGE * (2 * 8192 + 2 * 8192);   // 98304 (split MT=128 / qkv)
    const int SMS = NSTAGE * (2 * 4096 + 2 * 8192);   // 73728 (split MT=64)
    const int SMH = NSTAGE * 2 * 8192;                // 49152 (fp16)
    cudaFuncSetAttribute(qkv_kernel,   cudaFuncAttributeMaxDynamicSharedMemorySize, SMB);
    cudaFuncSetAttribute(sc_kernel,    cudaFuncAttributeMaxDynamicSharedMemorySize, SMS);
    cudaFuncSetAttribute(av_kernel,    cudaFuncAttributeMaxDynamicSharedMemorySize, SMH);
    cudaFuncSetAttribute(vocab_kernel, cudaFuncAttributeMaxDynamicSharedMemorySize, SMH);

    // per-launch weight conversions (deterministic, idempotent)
    {
        const int n4w = LL * DD * DD / 4;
        splitw_kernel<<<(n4w + 511) / 512, 512>>>((const float4*)qw, (bf16*)qwh_, (bf16*)qwl_, n4w);
        splitw_kernel<<<(n4w + 511) / 512, 512>>>((const float4*)kw, (bf16*)kwh_, (bf16*)kwl_, n4w);
        tohalf_kernel<<<(n4w + 511) / 512, 512>>>((const float4*)vw, (__half*)vwf_, n4w);
        const int n4d = VV * DD / 4;
        tohalf_kernel<<<(n4d + 511) / 512, 512>>>((const float4*)dw, (__half*)dwf_, n4d);
    }

    embed_pe_kernel<<<BB * TT, 256>>>(src, pe, emb, (float*)x_, (bf16*)xh_, (bf16*)xl_, (__half*)xf_);

    dim3 gqkv(DD / 128, (BB * TT) / 128, 3);
    dim3 gsc(TT / 128, TT / 64, BB);
    dim3 gav(TT / 128, TT / 128, BB);
    for (int l = 0; l < LL; l++) {
        const long wo = (long)l * DD * DD;
        QKVP p;
        p.xh = (const bf16*)xh_; p.xl = (const bf16*)xl_; p.xf = (const __half*)xf_;
        p.qwh = (const bf16*)qwh_ + wo; p.qwl = (const bf16*)qwl_ + wo;
        p.kwh = (const bf16*)kwh_ + wo; p.kwl = (const bf16*)kwl_ + wo;
        p.vwf = (const __half*)vwf_ + wo;
        p.qb = qb + l * DD; p.kb = kb + l * DD; p.vb = vb + l * DD;
        p.qh = (bf16*)qh_; p.ql = (bf16*)ql_;
        p.kh = (bf16*)kh_; p.kl = (bf16*)kl_;
        p.vf = (__half*)vf_;
        qkv_kernel<<<gqkv, 512, SMB>>>(p);
        sc_kernel<<<gsc, 256, SMS>>>((const bf16*)qh_, (const bf16*)ql_,
                                     (const bf16*)kh_, (const bf16*)kl_, (float*)a_);
        softmax_kernel<<<dim3(TT, BB), 256>>>((const float*)a_, (__half*)wf_);
        av_kernel<<<gav, 512, SMH>>>((const __half*)wf_, (const __half*)vf_, (float*)o_);
        ln_res_kernel<<<BB * TT, 256>>>((const float*)o_, lnw + l * DD, lnb + l * DD,
                                        (float*)x_, (bf16*)xh_, (bf16*)xl_, (__half*)xf_);
    }

    final_ln_kernel<<<BB * TT, 256>>>((const float*)x_, fw, fb, (__half*)xnf_);
    dim3 gf(VV / 128, (BB * TT) / 128);
    vocab_kernel<<<gf, 512, SMH>>>((const __half*)xnf_, (const __half*)dwf_, db, out);
}

// round 11
// speedup vs baseline: 5.2513x; 1.1439x over previous
#include <cuda_runtime.h>
#include <cuda_bf16.h>
#include <cuda_fp16.h>
#include <cstdint>

#define BB 2
#define TT 1024
#define DD 1024
#define VV 32000
#define LL 8
#define MD (TT * DD)
#define AA (TT * TT)

typedef __nv_bfloat16 bf16;

// fp32 masters
__device__ float g_x[BB * MD];
__device__ float g_a[BB * AA];
__device__ float g_o[BB * MD];
// split bf16 operands (accurate path: x, Q, K, weights qw/kw)
__device__ bf16 g_xh[BB * MD], g_xl[BB * MD];
__device__ bf16 g_qh[BB * MD], g_ql[BB * MD];
__device__ bf16 g_kh[BB * MD], g_kl[BB * MD];
__device__ bf16 g_qwh[LL * DD * DD], g_qwl[LL * DD * DD];
__device__ bf16 g_kwh[LL * DD * DD], g_kwl[LL * DD * DD];
// single fp16 operands (relaxed path: V, w, vw, dw, xn, x-as-fp16)
__device__ __half g_xf[BB * MD];
__device__ __half g_vf[BB * MD];          // V^T [b][d][t]
__device__ __half g_wf[BB * AA];
__device__ __half g_vwf[LL * DD * DD];
__device__ __half g_dwf[VV * DD];
__device__ __half g_xnf[BB * MD];

#define NSTAGE 3
// 64B rows + XOR swizzle: chunk c (16B) of row r at r*64 + (c ^ ((r>>1)&3))*16.
// Conflict-free for ldmatrix (8 rows cover all 32 banks exactly once).
#define SWZ(r, c) ((((uint32_t)(r)) << 6) + ((((c) ^ (((r) >> 1) & 3))) << 4))

__device__ __forceinline__ uint32_t smem_u32(const void* p) {
    uint32_t a;
    asm("{ .reg .u64 t; cvta.to.shared.u64 t, %1; cvt.u32.u64 %0, t; }" : "=r"(a) : "l"(p));
    return a;
}
#define LDM4(r0, r1, r2, r3, ad) \
    asm volatile("ldmatrix.sync.aligned.m8n8.x4.shared.b16 {%0,%1,%2,%3},[%4];" \
                 : "=r"(r0), "=r"(r1), "=r"(r2), "=r"(r3) : "r"(ad))
#define MMA16B(c, a, b0_, b1_) \
    asm volatile("mma.sync.aligned.m16n8k16.row.col.f32.bf16.bf16.f32 " \
                 "{%0,%1,%2,%3},{%4,%5,%6,%7},{%8,%9},{%0,%1,%2,%3};" \
                 : "+f"((c)[0]), "+f"((c)[1]), "+f"((c)[2]), "+f"((c)[3]) \
                 : "r"((a)[0]), "r"((a)[1]), "r"((a)[2]), "r"((a)[3]), "r"(b0_), "r"(b1_))
#define MMA16H(c, a, b0_, b1_) \
    asm volatile("mma.sync.aligned.m16n8k16.row.col.f32.f16.f16.f32 " \
                 "{%0,%1,%2,%3},{%4,%5,%6,%7},{%8,%9},{%0,%1,%2,%3};" \
                 : "+f"((c)[0]), "+f"((c)[1]), "+f"((c)[2]), "+f"((c)[3]) \
                 : "r"((a)[0]), "r"((a)[1]), "r"((a)[2]), "r"((a)[3]), "r"(b0_), "r"(b1_))
#define CPA16(d, s) asm volatile("cp.async.cg.shared.global [%0], [%1], 16;" :: "r"(d), "l"(s))
#define CPCOMMIT()  asm volatile("cp.async.commit_group;" ::: "memory")
#define CPWAIT1()   asm volatile("cp.async.wait_group 1;" ::: "memory")

__device__ __forceinline__ void bsplit(float v, bf16& h, bf16& l) {
    h = __float2bfloat16_rn(v);
    l = __float2bfloat16_rn(v - __bfloat162float(h));
}

// ---------------------------------------------------------------------------
// bf16 3-term split GEMM core. MT=128: 512 thr (4x4 warps of 32x32).
// MT=64: 256 thr (2x4 warps). N tile 128. Stages of BK=64 (two 32-K
// sub-buffers), NSTAGE=3, loads issued 2 stages ahead BEFORE compute.
// BIAS: 0 none, 1 per-N.  OUT: 0 fp32 Cf, 1 bf16 hi/lo Ch/Cl.
// ---------------------------------------------------------------------------
template <int MT, int BIAS, int OUT>
__device__ __forceinline__ void gemm_core(
    const bf16* __restrict__ Ah, const bf16* __restrict__ Al, int lda,
    const bf16* __restrict__ Bh, const bf16* __restrict__ Bl, int ldb,
    const float* __restrict__ bias,
    float* __restrict__ Cf, bf16* __restrict__ Ch, bf16* __restrict__ Cl, int ldc,
    int m0, int n0, int Keff)
{
    constexpr int ABY = MT * 64;
    constexpr int BBY = 8192;
    constexpr int STG32 = 2 * ABY + 2 * BBY;
    constexpr int STG64 = 2 * STG32;
    extern __shared__ uint16_t sm[];
    const uint32_t sb = smem_u32(sm);
    const int tid = threadIdx.x, lane = tid & 31, wrp = tid >> 5;
    const int wm = wrp >> 2, wn = wrp & 3;
    const int S2 = Keff >> 6;

    const int a_ml = (lane & 7) + ((lane >> 3) & 1) * 8;
    const int a_c0 = lane >> 4;
    const int b_nl = (lane & 7) + ((lane >> 4) << 3);
    const int b_c0 = (lane >> 3) & 1;

    const int row = tid >> 2, ch = tid & 3;
    const bf16* Aph = Ah + (long)(m0 + row) * lda + ch * 8;
    const bf16* Apl = Al + (long)(m0 + row) * lda + ch * 8;
    const bf16* Bph = Bh + (long)(n0 + row) * ldb + ch * 8;
    const bf16* Bpl = Bl + (long)(n0 + row) * ldb + ch * 8;
    const uint32_t swz = SWZ(row, ch);
    const uint32_t swz2 = SWZ(row + 64, ch);

    auto issue32 = [&](int k32, uint32_t db) {
        const int k0 = k32 << 5;
        CPA16(db + swz,                 Aph + k0);
        CPA16(db + ABY + swz,           Apl + k0);
        CPA16(db + 2 * ABY + swz,       Bph + k0);
        CPA16(db + 2 * ABY + BBY + swz, Bpl + k0);
        if (MT == 64) {
            CPA16(db + 2 * ABY + swz2,       Bph + (long)64 * ldb + k0);
            CPA16(db + 2 * ABY + BBY + swz2, Bpl + (long)64 * ldb + k0);
        }
    };
    auto issue = [&](int s2) {
        const uint32_t db = sb + (uint32_t)(s2 % NSTAGE) * STG64;
        issue32(2 * s2, db);
        issue32(2 * s2 + 1, db + STG32);
        CPCOMMIT();
    };

    float acc[2][4][4] = {};

    auto compute32 = [&](uint32_t stb) {
        const uint32_t ahb = stb, alb = stb + ABY, bhb = stb + 2 * ABY, blb = bhb + BBY;
#pragma unroll
        for (int ks = 0; ks < 2; ks++) {
            uint32_t bhf[8], blf[8];
#pragma unroll
            for (int p = 0; p < 2; p++) {
                const uint32_t boff = SWZ(wn * 32 + p * 16 + b_nl, ks * 2 + b_c0);
                LDM4(bhf[p * 4 + 0], bhf[p * 4 + 1], bhf[p * 4 + 2], bhf[p * 4 + 3], bhb + boff);
                LDM4(blf[p * 4 + 0], blf[p * 4 + 1], blf[p * 4 + 2], blf[p * 4 + 3], blb + boff);
            }
#pragma unroll
            for (int mt = 0; mt < 2; mt++) {
                uint32_t ahf[4], alf[4];
                const uint32_t aoff = SWZ(wm * 32 + mt * 16 + a_ml, ks * 2 + a_c0);
                LDM4(ahf[0], ahf[1], ahf[2], ahf[3], ahb + aoff);
                LDM4(alf[0], alf[1], alf[2], alf[3], alb + aoff);
#pragma unroll
                for (int nt = 0; nt < 4; nt++) {
                    const int bi = (nt >> 1) * 4 + (nt & 1) * 2;
                    float* c = acc[mt][nt];
                    MMA16B(c, ahf, bhf[bi], bhf[bi + 1]);
                    MMA16B(c, ahf, blf[bi], blf[bi + 1]);
                    MMA16B(c, alf, bhf[bi], bhf[bi + 1]);
                }
            }
        }
    };

    issue(0); issue(1);
    for (int s2 = 0; s2 < S2; s2++) {
        CPWAIT1();
        __syncthreads();
        if (s2 + 2 < S2) issue(s2 + 2); else CPCOMMIT();
        const uint32_t stb = sb + (uint32_t)(s2 % NSTAGE) * STG64;
        compute32(stb);
        compute32(stb + STG32);
    }

    const int er = lane >> 2, ec = (lane & 3) * 2;
#pragma unroll
    for (int mt = 0; mt < 2; mt++) {
        const int m = m0 + wm * 32 + mt * 16 + er;
#pragma unroll
        for (int nt = 0; nt < 4; nt++) {
            const int n = n0 + wn * 32 + nt * 8 + ec;
            float bn0 = 0.f, bn1 = 0.f;
            if (BIAS == 1) { bn0 = bias[n]; bn1 = bias[n + 1]; }
            const float* c = acc[mt][nt];
            float v00 = c[0] + bn0, v01 = c[1] + bn1;
            float v10 = c[2] + bn0, v11 = c[3] + bn1;
            if (OUT == 0) {
                *reinterpret_cast<float2*>(Cf + (long)m * ldc + n) = make_float2(v00, v01);
                *reinterpret_cast<float2*>(Cf + (long)(m + 8) * ldc + n) = make_float2(v10, v11);
            } else {
                bf16 h0, l0, h1, l1;
                bsplit(v00, h0, l0); bsplit(v01, h1, l1);
                *reinterpret_cast<__nv_bfloat162*>(Ch + (long)m * ldc + n) = __halves2bfloat162(h0, h1);
                *reinterpret_cast<__nv_bfloat162*>(Cl + (long)m * ldc + n) = __halves2bfloat162(l0, l1);
                bsplit(v10, h0, l0); bsplit(v11, h1, l1);
                *reinterpret_cast<__nv_bfloat162*>(Ch + (long)(m + 8) * ldc + n) = __halves2bfloat162(h0, h1);
                *reinterpret_cast<__nv_bfloat162*>(Cl + (long)(m + 8) * ldc + n) = __halves2bfloat162(l0, l1);
            }
        }
    }
}

// ---------------------------------------------------------------------------
// fp16 single-pass core: 512 thr, 128x128 tile, BK=64 stages, issue-ahead.
// BIAS: 0 none, 1 per-N, 2 per-M.  OUT: 0 fp32 Cf, 1 fp16 Chf.
// ---------------------------------------------------------------------------
template <int BIAS, int OUT>
__device__ __forceinline__ void gemm_core_h(
    const __half* __restrict__ A, int lda, const __half* __restrict__ B, int ldb,
    const float* __restrict__ bias,
    float* __restrict__ Cf, __half* __restrict__ Chf, int ldc,
    int m0, int n0, int Keff)
{
    constexpr int BBY = 8192;
    constexpr int STG32 = 2 * BBY;
    constexpr int STG64 = 2 * STG32;
    extern __shared__ uint16_t sm[];
    const uint32_t sb = smem_u32(sm);
    const int tid = threadIdx.x, lane = tid & 31, wrp = tid >> 5;
    const int wm = wrp >> 2, wn = wrp & 3;
    const int S2 = Keff >> 6;

    const int a_ml = (lane & 7) + ((lane >> 3) & 1) * 8;
    const int a_c0 = lane >> 4;
    const int b_nl = (lane & 7) + ((lane >> 4) << 3);
    const int b_c0 = (lane >> 3) & 1;

    const int row = tid >> 2, ch = tid & 3;
    const __half* Ap = A + (long)(m0 + row) * lda + ch * 8;
    const __half* Bp = B + (long)(n0 + row) * ldb + ch * 8;
    const uint32_t swz = SWZ(row, ch);

    auto issue32 = [&](int k32, uint32_t db) {
        const int k0 = k32 << 5;
        CPA16(db + swz,       Ap + k0);
        CPA16(db + BBY + swz, Bp + k0);
    };
    auto issue = [&](int s2) {
        const uint32_t db = sb + (uint32_t)(s2 % NSTAGE) * STG64;
        issue32(2 * s2, db);
        issue32(2 * s2 + 1, db + STG32);
        CPCOMMIT();
    };

    float acc[2][4][4] = {};

    auto compute32 = [&](uint32_t stb) {
#pragma unroll
        for (int ks = 0; ks < 2; ks++) {
            uint32_t bhf[8];
#pragma unroll
            for (int p = 0; p < 2; p++) {
                const uint32_t boff = SWZ(wn * 32 + p * 16 + b_nl, ks * 2 + b_c0);
                LDM4(bhf[p * 4 + 0], bhf[p * 4 + 1], bhf[p * 4 + 2], bhf[p * 4 + 3], stb + BBY + boff);
            }
#pragma unroll
            for (int mt = 0; mt < 2; mt++) {
                uint32_t ahf[4];
                const uint32_t aoff = SWZ(wm * 32 + mt * 16 + a_ml, ks * 2 + a_c0);
                LDM4(ahf[0], ahf[1], ahf[2], ahf[3], stb + aoff);
#pragma unroll
                for (int nt = 0; nt < 4; nt++) {
                    const int bi = (nt >> 1) * 4 + (nt & 1) * 2;
                    MMA16H(acc[mt][nt], ahf, bhf[bi], bhf[bi + 1]);
                }
            }
        }
    };

    issue(0); issue(1);
    for (int s2 = 0; s2 < S2; s2++) {
        CPWAIT1();
        __syncthreads();
        if (s2 + 2 < S2) issue(s2 + 2); else CPCOMMIT();
        const uint32_t stb = sb + (uint32_t)(s2 % NSTAGE) * STG64;
        compute32(stb);
        compute32(stb + STG32);
    }

    const int er = lane >> 2, ec = (lane & 3) * 2;
#pragma unroll
    for (int mt = 0; mt < 2; mt++) {
        const int m = m0 + wm * 32 + mt * 16 + er;
        float bm0 = 0.f, bm8 = 0.f;
        if (BIAS == 2) { bm0 = bias[m]; bm8 = bias[m + 8]; }
#pragma unroll
        for (int nt = 0; nt < 4; nt++) {
            const int n = n0 + wn * 32 + nt * 8 + ec;
            float bn0 = 0.f, bn1 = 0.f;
            if (BIAS == 1) { bn0 = bias[n]; bn1 = bias[n + 1]; }
            const float* c = acc[mt][nt];
            float v00 = c[0] + bn0 + bm0, v01 = c[1] + bn1 + bm0;
            float v10 = c[2] + bn0 + bm8, v11 = c[3] + bn1 + bm8;
            if (OUT == 0) {
                *reinterpret_cast<float2*>(Cf + (long)m * ldc + n) = make_float2(v00, v01);
                *reinterpret_cast<float2*>(Cf + (long)(m + 8) * ldc + n) = make_float2(v10, v11);
            } else {
                *reinterpret_cast<__half2*>(Chf + (long)m * ldc + n) = __floats2half2_rn(v00, v01);
                *reinterpret_cast<__half2*>(Chf + (long)(m + 8) * ldc + n) = __floats2half2_rn(v10, v11);
            }
        }
    }
}

// ---------------------------------------------------------------------------
// Kernel wrappers
// ---------------------------------------------------------------------------
struct QKVP {
    const bf16 *xh, *xl;
    const __half *xf;
    const bf16 *qwh, *qwl, *kwh, *kwl;
    const __half *vwf;
    const float *qb, *kb, *vb;
    bf16 *qh, *ql, *kh, *kl;
    __half *vf;
};

__global__ void __launch_bounds__(512) qkv_kernel(QKVP p)
{
    const int bx = blockIdx.x, by = blockIdx.y, bz = blockIdx.z;
    if (bz == 0) {
        gemm_core<128, 1, 1>(p.xh, p.xl, DD, p.qwh, p.qwl, DD, p.qb,
                             nullptr, p.qh, p.ql, DD, by * 128, bx * 128, DD);
    } else if (bz == 1) {
        gemm_core<128, 1, 1>(p.xh, p.xl, DD, p.kwh, p.kwl, DD, p.kb,
                             nullptr, p.kh, p.kl, DD, by * 128, bx * 128, DD);
    } else {
        // V^T = vw @ x^T, single fp16, per-M bias, fp16 out
        const int b = by >> 3, dt = by & 7;
        gemm_core_h<2, 1>(p.vwf, DD, p.xf + (long)b * MD, DD, p.vb,
                          nullptr, p.vf + (long)b * MD, TT, dt * 128, bx * 128, DD);
    }
}

// scores: split bf16, M-tile 64 (256 thr), causal skip
__global__ void __launch_bounds__(256) sc_kernel(const bf16* __restrict__ qh, const bf16* __restrict__ ql,
                                                 const bf16* __restrict__ kh, const bf16* __restrict__ kl,
                                                 float* __restrict__ a)
{
    const int bx = blockIdx.x, by = blockIdx.y, b = blockIdx.z;
    if (2 * bx > by) return;
    gemm_core<64, 0, 0>(qh + (long)b * MD, ql + (long)b * MD, DD,
                        kh + (long)b * MD, kl + (long)b * MD, DD, nullptr,
                        a + (long)b * AA, nullptr, nullptr, TT, by * 64, bx * 128, DD);
}

// o = w @ V, single fp16, K-limited
__global__ void __launch_bounds__(512) av_kernel(const __half* __restrict__ wf,
                                                 const __half* __restrict__ vf,
                                                 float* __restrict__ o)
{
    const int bx = blockIdx.x, by = blockIdx.y, b = blockIdx.z;
    gemm_core_h<0, 0>(wf + (long)b * AA, TT, vf + (long)b * MD, TT, nullptr,
                      o + (long)b * MD, nullptr, DD,
                      by * 128, bx * 128, min(TT, by * 128 + 128));
}

__global__ void __launch_bounds__(512) vocab_kernel(const __half* __restrict__ xn, const __half* __restrict__ dwf,
                                                    const float* __restrict__ db, float* __restrict__ out)
{
    gemm_core_h<1, 0>(xn, DD, dwf, DD, db, out, nullptr, VV, blockIdx.y * 128, blockIdx.x * 128, DD);
}

// ---------------------------------------------------------------------------
// Converters + elementwise
// ---------------------------------------------------------------------------
__global__ void splitw_kernel(const float4* __restrict__ src, bf16* __restrict__ h,
                              bf16* __restrict__ l, int n4)
{
    int i = blockIdx.x * blockDim.x + threadIdx.x;
    if (i >= n4) return;
    float4 v = src[i];
    bf16 h0, l0, h1, l1, h2, l2, h3, l3;
    bsplit(v.x, h0, l0); bsplit(v.y, h1, l1); bsplit(v.z, h2, l2); bsplit(v.w, h3, l3);
    *reinterpret_cast<__nv_bfloat162*>(h + (long)i * 4)     = __halves2bfloat162(h0, h1);
    *reinterpret_cast<__nv_bfloat162*>(h + (long)i * 4 + 2) = __halves2bfloat162(h2, h3);
    *reinterpret_cast<__nv_bfloat162*>(l + (long)i * 4)     = __halves2bfloat162(l0, l1);
    *reinterpret_cast<__nv_bfloat162*>(l + (long)i * 4 + 2) = __halves2bfloat162(l2, l3);
}

__global__ void tohalf_kernel(const float4* __restrict__ src, __half* __restrict__ dst, int n4)
{
    int i = blockIdx.x * blockDim.x + threadIdx.x;
    if (i >= n4) return;
    float4 v = src[i];
    *reinterpret_cast<__half2*>(dst + (long)i * 4)     = __floats2half2_rn(v.x, v.y);
    *reinterpret_cast<__half2*>(dst + (long)i * 4 + 2) = __floats2half2_rn(v.z, v.w);
}

__device__ __forceinline__ void store_x3(float4 v, long off, float* X,
                                         bf16* xh, bf16* xl, __half* xf)
{
    if (X) *reinterpret_cast<float4*>(X + off) = v;
    bf16 h0, l0, h1, l1, h2, l2, h3, l3;
    bsplit(v.x, h0, l0); bsplit(v.y, h1, l1); bsplit(v.z, h2, l2); bsplit(v.w, h3, l3);
    *reinterpret_cast<__nv_bfloat162*>(xh + off)     = __halves2bfloat162(h0, h1);
    *reinterpret_cast<__nv_bfloat162*>(xh + off + 2) = __halves2bfloat162(h2, h3);
    *reinterpret_cast<__nv_bfloat162*>(xl + off)     = __halves2bfloat162(l0, l1);
    *reinterpret_cast<__nv_bfloat162*>(xl + off + 2) = __halves2bfloat162(l2, l3);
    *reinterpret_cast<__half2*>(xf + off)     = __floats2half2_rn(v.x, v.y);
    *reinterpret_cast<__half2*>(xf + off + 2) = __floats2half2_rn(v.z, v.w);
}

__global__ void embed_pe_kernel(const int* __restrict__ src, const float* __restrict__ pe,
                                const float* __restrict__ embed, float* __restrict__ x,
                                bf16* __restrict__ xh, bf16* __restrict__ xl, __half* __restrict__ xf)
{
    int row = blockIdx.x, b = row >> 10;
    long tok = src[row];
    const float4* e = reinterpret_cast<const float4*>(embed + tok * (long)DD);
    const float4* p = reinterpret_cast<const float4*>(pe + (long)b * DD);
    int i = threadIdx.x;
    float4 ev = e[i], pv = p[i];
    float4 v = make_float4(ev.x + pv.x, ev.y + pv.y, ev.z + pv.z, ev.w + pv.w);
    store_x3(v, (long)row * DD + i * 4, x, xh, xl, xf);
}

__global__ void softmax_kernel(const float* __restrict__ A, __half* __restrict__ Wf)
{
    int t = blockIdx.x, b = blockIdx.y;
    const float* row = A + ((long)b * TT + t) * TT;
    __half* wf = Wf + ((long)b * TT + t) * TT;
    int n = t + 1, i = threadIdx.x;
    __shared__ float red[256];
    __shared__ float rowe[TT];
    float m = -1e30f;
    for (int s = i; s < n; s += 256) m = fmaxf(m, row[s]);
    red[i] = m; __syncthreads();
    for (int st = 128; st > 0; st >>= 1) { if (i < st) red[i] = fmaxf(red[i], red[i + st]); __syncthreads(); }
    m = red[0]; __syncthreads();
    float sum = 0.f;
    for (int s = i; s < n; s += 256) { float e = expf(row[s] - m); rowe[s] = e; sum += e; }
    red[i] = sum; __syncthreads();
    for (int st = 128; st > 0; st >>= 1) { if (i < st) red[i] += red[i + st]; __syncthreads(); }
    float inv = 1.0f / red[0];
    for (int s = i; s < TT; s += 256)
        wf[s] = (s < n) ? __float2half_rn(rowe[s] * inv) : __float2half_rn(0.f);
}

__global__ void ln_res_kernel(const float* __restrict__ O, const float* __restrict__ w,
                              const float* __restrict__ bb, float* __restrict__ X,
                              bf16* __restrict__ xh, bf16* __restrict__ xl, __half* __restrict__ xf)
{
    int row = blockIdx.x, i = threadIdx.x;
    const float4 o = reinterpret_cast<const float4*>(O + (long)row * DD)[i];
    float4* x4 = reinterpret_cast<float4*>(X + (long)row * DD);
    __shared__ float red[256];
    red[i] = o.x + o.y + o.z + o.w; __syncthreads();
    for (int st = 128; st > 0; st >>= 1) { if (i < st) red[i] += red[i + st]; __syncthreads(); }
    float mu = red[0] * (1.0f / DD); __syncthreads();
    float dx = o.x - mu, dy = o.y - mu, dz = o.z - mu, dw_ = o.w - mu;
    red[i] = dx * dx + dy * dy + dz * dz + dw_ * dw_; __syncthreads();
    for (int st = 128; st > 0; st >>= 1) { if (i < st) red[i] += red[i + st]; __syncthreads(); }
    float rstd = rsqrtf(red[0] * (1.0f / DD) + 1e-6f);
    float4 wv = reinterpret_cast<const float4*>(w)[i];
    float4 bv = reinterpret_cast<const float4*>(bb)[i];
    float4 xv = x4[i];
    xv.x += dx * rstd * wv.x + bv.x;
    xv.y += dy * rstd * wv.y + bv.y;
    xv.z += dz * rstd * wv.z + bv.z;
    xv.w += dw_ * rstd * wv.w + bv.w;
    x4[i] = xv;
    store_x3(xv, (long)row * DD + i * 4, nullptr, xh, xl, xf);
}

__global__ void final_ln_kernel(const float* __restrict__ X, const float* __restrict__ fw,
                                const float* __restrict__ fb, __half* __restrict__ Y)
{
    int row = blockIdx.x, i = threadIdx.x;
    const float4 x = reinterpret_cast<const float4*>(X + (long)row * DD)[i];
    __shared__ float red[256];
    red[i] = x.x + x.y + x.z + x.w; __syncthreads();
    for (int st = 128; st > 0; st >>= 1) { if (i < st) red[i] += red[i + st]; __syncthreads(); }
    float mu = red[0] * (1.0f / DD); __syncthreads();
    float dx = x.x - mu, dy = x.y - mu, dz = x.z - mu, dw_ = x.w - mu;
    red[i] = dx * dx + dy * dy + dz * dz + dw_ * dw_; __syncthreads();
    for (int st = 128; st > 0; st >>= 1) { if (i < st) red[i] += red[i + st]; __syncthreads(); }
    float rstd = rsqrtf(red[0] * (1.0f / DD) + 1e-5f);
    float4 wv = reinterpret_cast<const float4*>(fw)[i];
    float4 bv = reinterpret_cast<const float4*>(fb)[i];
    long off = (long)row * DD + i * 4;
    *reinterpret_cast<__half2*>(Y + off)     = __floats2half2_rn(dx * rstd * wv.x + bv.x, dy * rstd * wv.y + bv.y);
    *reinterpret_cast<__half2*>(Y + off + 2) = __floats2half2_rn(dz * rstd * wv.z + bv.z, dw_ * rstd * wv.w + bv.w);
}

// ---------------------------------------------------------------------------
extern "C" void kernel_launch(void* const* d_in, const int* in_sizes, int n_in,
                              void* d_out, int out_size)
{
    const int*   src = (const int*)d_in[0];
    const float* pe  = (const float*)d_in[1];
    const float* emb = (const float*)d_in[2];
    const float* qw  = (const float*)d_in[3];
    const float* qb  = (const float*)d_in[4];
    const float* kw  = (const float*)d_in[5];
    const float* kb  = (const float*)d_in[6];
    const float* vw  = (const float*)d_in[7];
    const float* vb  = (const float*)d_in[8];
    const float* lnw = (const float*)d_in[9];
    const float* lnb = (const float*)d_in[10];
    const float* fw  = (const float*)d_in[11];
    const float* fb  = (const float*)d_in[12];
    const float* dw  = (const float*)d_in[13];
    const float* db  = (const float*)d_in[14];
    float* out = (float*)d_out;

#define GA(sym, var) void* var##_; cudaGetSymbolAddress(&var##_, sym)
    GA(g_x, x);  GA(g_a, a);  GA(g_o, o);
    GA(g_xh, xh); GA(g_xl, xl); GA(g_xf, xf);
    GA(g_qh, qh); GA(g_ql, ql); GA(g_kh, kh); GA(g_kl, kl);
    GA(g_vf, vf); GA(g_wf, wf);
    GA(g_qwh, qwh); GA(g_qwl, qwl); GA(g_kwh, kwh); GA(g_kwl, kwl);
    GA(g_vwf, vwf); GA(g_dwf, dwf); GA(g_xnf, xnf);
#undef GA

    const int SMB = NSTAGE * 2 * (2 * 8192 + 2 * 8192);   // 196608 (split MT=128)
    const int SMS = NSTAGE * 2 * (2 * 4096 + 2 * 8192);   // 147456 (split MT=64)
    const int SMH = NSTAGE * 2 * (2 * 8192);              // 98304  (fp16)
    cudaFuncSetAttribute(qkv_kernel,   cudaFuncAttributeMaxDynamicSharedMemorySize, SMB);
    cudaFuncSetAttribute(sc_kernel,    cudaFuncAttributeMaxDynamicSharedMemorySize, SMS);
    cudaFuncSetAttribute(av_kernel,    cudaFuncAttributeMaxDynamicSharedMemorySize, SMH);
    cudaFuncSetAttribute(vocab_kernel, cudaFuncAttributeMaxDynamicSharedMemorySize, SMH);

    // per-launch weight conversions (deterministic, idempotent)
    {
        const int n4w = LL * DD * DD / 4;
        splitw_kernel<<<(n4w + 511) / 512, 512>>>((const float4*)qw, (bf16*)qwh_, (bf16*)qwl_, n4w);
        splitw_kernel<<<(n4w + 511) / 512, 512>>>((const float4*)kw, (bf16*)kwh_, (bf16*)kwl_, n4w);
        tohalf_kernel<<<(n4w + 511) / 512, 512>>>((const float4*)vw, (__half*)vwf_, n4w);
        const int n4d = VV * DD / 4;
        tohalf_kernel<<<(n4d + 511) / 512, 512>>>((const float4*)dw, (__half*)dwf_, n4d);
    }

    embed_pe_kernel<<<BB * TT, 256>>>(src, pe, emb, (float*)x_, (bf16*)xh_, (bf16*)xl_, (__half*)xf_);

    dim3 gqkv(DD / 128, (BB * TT) / 128, 3);
    dim3 gsc(TT / 128, TT / 64, BB);
    dim3 gav(TT / 128, TT / 128, BB);
    for (int l = 0; l < LL; l++) {
        const long wo = (long)l * DD * DD;
        QKVP p;
        p.xh = (const bf16*)xh_; p.xl = (const bf16*)xl_; p.xf = (const __half*)xf_;
        p.qwh = (const bf16*)qwh_ + wo; p.qwl = (const bf16*)qwl_ + wo;
        p.kwh = (const bf16*)kwh_ + wo; p.kwl = (const bf16*)kwl_ + wo;
        p.vwf = (const __half*)vwf_ + wo;
        p.qb = qb + l * DD; p.kb = kb + l * DD; p.vb = vb + l * DD;
        p.qh = (bf16*)qh_; p.ql = (bf16*)ql_;
        p.kh = (bf16*)kh_; p.kl = (bf16*)kl_;
        p.vf = (__half*)vf_;
        qkv_kernel<<<gqkv, 512, SMB>>>(p);
        sc_kernel<<<gsc, 256, SMS>>>((const bf16*)qh_, (const bf16*)ql_,
                                     (const bf16*)kh_, (const bf16*)kl_, (float*)a_);
        softmax_kernel<<<dim3(TT, BB), 256>>>((const float*)a_, (__half*)wf_);
        av_kernel<<<gav, 512, SMH>>>((const __half*)wf_, (const __half*)vf_, (float*)o_);
        ln_res_kernel<<<BB * TT, 256>>>((const float*)o_, lnw + l * DD, lnb + l * DD,
                                        (float*)x_, (bf16*)xh_, (bf16*)xl_, (__half*)xf_);
    }

    final_ln_kernel<<<BB * TT, 256>>>((const float*)x_, fw, fb, (__half*)xnf_);
    dim3 gf(VV / 128, (BB * TT) / 128);
    vocab_kernel<<<gf, 512, SMH>>>((const __half*)xnf_, (const __half*)dwf_, db, out);
}

// round 12
// speedup vs baseline: 5.3591x; 1.0205x over previous
#include <cuda_runtime.h>
#include <cuda_bf16.h>
#include <cuda_fp16.h>
#include <cstdint>

#define BB 2
#define TT 1024
#define DD 1024
#define VV 32000
#define LL 8
#define MD (TT * DD)
#define AA (TT * TT)

typedef __nv_bfloat16 bf16;

// fp32 masters
__device__ float g_x[BB * MD];
__device__ float g_a[BB * AA];
__device__ float g_o[BB * MD];
// split bf16 operands (accurate path: x, Q, K, weights qw/kw)
__device__ bf16 g_xh[BB * MD], g_xl[BB * MD];
__device__ bf16 g_qh[BB * MD], g_ql[BB * MD];
__device__ bf16 g_kh[BB * MD], g_kl[BB * MD];
__device__ bf16 g_qwh[LL * DD * DD], g_qwl[LL * DD * DD];
__device__ bf16 g_kwh[LL * DD * DD], g_kwl[LL * DD * DD];
// single fp16 operands (relaxed path: V, w, vw, dw, xn, x-as-fp16)
__device__ __half g_xf[BB * MD];
__device__ __half g_vf[BB * MD];          // V^T [b][d][t]
__device__ __half g_wf[BB * AA];
__device__ __half g_vwf[LL * DD * DD];
__device__ __half g_dwf[VV * DD];
__device__ __half g_xnf[BB * MD];

#define NSTAGE 3
// 64B rows + XOR swizzle: chunk c (16B) of row r at r*64 + (c ^ ((r>>1)&3))*16.
// Conflict-free for ldmatrix (8 rows cover all 32 banks exactly once).
#define SWZ(r, c) ((((uint32_t)(r)) << 6) + ((((c) ^ (((r) >> 1) & 3))) << 4))

__device__ __forceinline__ uint32_t smem_u32(const void* p) {
    uint32_t a;
    asm("{ .reg .u64 t; cvta.to.shared.u64 t, %1; cvt.u32.u64 %0, t; }" : "=r"(a) : "l"(p));
    return a;
}
#define LDM4(r0, r1, r2, r3, ad) \
    asm volatile("ldmatrix.sync.aligned.m8n8.x4.shared.b16 {%0,%1,%2,%3},[%4];" \
                 : "=r"(r0), "=r"(r1), "=r"(r2), "=r"(r3) : "r"(ad))
#define MMA16B(c, a, b0_, b1_) \
    asm volatile("mma.sync.aligned.m16n8k16.row.col.f32.bf16.bf16.f32 " \
                 "{%0,%1,%2,%3},{%4,%5,%6,%7},{%8,%9},{%0,%1,%2,%3};" \
                 : "+f"((c)[0]), "+f"((c)[1]), "+f"((c)[2]), "+f"((c)[3]) \
                 : "r"((a)[0]), "r"((a)[1]), "r"((a)[2]), "r"((a)[3]), "r"(b0_), "r"(b1_))
#define MMA16H(c, a, b0_, b1_) \
    asm volatile("mma.sync.aligned.m16n8k16.row.col.f32.f16.f16.f32 " \
                 "{%0,%1,%2,%3},{%4,%5,%6,%7},{%8,%9},{%0,%1,%2,%3};" \
                 : "+f"((c)[0]), "+f"((c)[1]), "+f"((c)[2]), "+f"((c)[3]) \
                 : "r"((a)[0]), "r"((a)[1]), "r"((a)[2]), "r"((a)[3]), "r"(b0_), "r"(b1_))
#define CPA16(d, s) asm volatile("cp.async.cg.shared.global [%0], [%1], 16;" :: "r"(d), "l"(s))
#define CPCOMMIT()  asm volatile("cp.async.commit_group;" ::: "memory")
#define CPWAIT1()   asm volatile("cp.async.wait_group 1;" ::: "memory")

__device__ __forceinline__ void bsplit(float v, bf16& h, bf16& l) {
    h = __float2bfloat16_rn(v);
    l = __float2bfloat16_rn(v - __bfloat162float(h));
}

// ---------------------------------------------------------------------------
// bf16 3-term split GEMM core. MT=128: 512 thr (4x4 warps of 32x32).
// MT=64: 256 thr (2x4 warps). N tile 128. Stages of BK=64 (two 32-K
// sub-buffers), NSTAGE=3, loads issued 2 stages ahead BEFORE compute.
// BIAS: 0 none, 1 per-N.  OUT: 0 fp32 Cf, 1 bf16 hi/lo Ch/Cl.
// ---------------------------------------------------------------------------
template <int MT, int BIAS, int OUT>
__device__ __forceinline__ void gemm_core(
    const bf16* __restrict__ Ah, const bf16* __restrict__ Al, int lda,
    const bf16* __restrict__ Bh, const bf16* __restrict__ Bl, int ldb,
    const float* __restrict__ bias,
    float* __restrict__ Cf, bf16* __restrict__ Ch, bf16* __restrict__ Cl, int ldc,
    int m0, int n0, int Keff)
{
    constexpr int ABY = MT * 64;
    constexpr int BBY = 8192;
    constexpr int STG32 = 2 * ABY + 2 * BBY;
    constexpr int STG64 = 2 * STG32;
    extern __shared__ uint16_t sm[];
    const uint32_t sb = smem_u32(sm);
    const int tid = threadIdx.x, lane = tid & 31, wrp = tid >> 5;
    const int wm = wrp >> 2, wn = wrp & 3;
    const int S2 = Keff >> 6;

    const int a_ml = (lane & 7) + ((lane >> 3) & 1) * 8;
    const int a_c0 = lane >> 4;
    const int b_nl = (lane & 7) + ((lane >> 4) << 3);
    const int b_c0 = (lane >> 3) & 1;

    const int row = tid >> 2, ch = tid & 3;
    const bf16* Aph = Ah + (long)(m0 + row) * lda + ch * 8;
    const bf16* Apl = Al + (long)(m0 + row) * lda + ch * 8;
    const bf16* Bph = Bh + (long)(n0 + row) * ldb + ch * 8;
    const bf16* Bpl = Bl + (long)(n0 + row) * ldb + ch * 8;
    const uint32_t swz = SWZ(row, ch);
    const uint32_t swz2 = SWZ(row + 64, ch);

    auto issue32 = [&](int k32, uint32_t db) {
        const int k0 = k32 << 5;
        CPA16(db + swz,                 Aph + k0);
        CPA16(db + ABY + swz,           Apl + k0);
        CPA16(db + 2 * ABY + swz,       Bph + k0);
        CPA16(db + 2 * ABY + BBY + swz, Bpl + k0);
        if (MT == 64) {
            CPA16(db + 2 * ABY + swz2,       Bph + (long)64 * ldb + k0);
            CPA16(db + 2 * ABY + BBY + swz2, Bpl + (long)64 * ldb + k0);
        }
    };
    auto issue = [&](int s2) {
        const uint32_t db = sb + (uint32_t)(s2 % NSTAGE) * STG64;
        issue32(2 * s2, db);
        issue32(2 * s2 + 1, db + STG32);
        CPCOMMIT();
    };

    float acc[2][4][4] = {};

    auto compute32 = [&](uint32_t stb) {
        const uint32_t ahb = stb, alb = stb + ABY, bhb = stb + 2 * ABY, blb = bhb + BBY;
#pragma unroll
        for (int ks = 0; ks < 2; ks++) {
            uint32_t bhf[8], blf[8];
#pragma unroll
            for (int p = 0; p < 2; p++) {
                const uint32_t boff = SWZ(wn * 32 + p * 16 + b_nl, ks * 2 + b_c0);
                LDM4(bhf[p * 4 + 0], bhf[p * 4 + 1], bhf[p * 4 + 2], bhf[p * 4 + 3], bhb + boff);
                LDM4(blf[p * 4 + 0], blf[p * 4 + 1], blf[p * 4 + 2], blf[p * 4 + 3], blb + boff);
            }
#pragma unroll
            for (int mt = 0; mt < 2; mt++) {
                uint32_t ahf[4], alf[4];
                const uint32_t aoff = SWZ(wm * 32 + mt * 16 + a_ml, ks * 2 + a_c0);
                LDM4(ahf[0], ahf[1], ahf[2], ahf[3], ahb + aoff);
                LDM4(alf[0], alf[1], alf[2], alf[3], alb + aoff);
#pragma unroll
                for (int nt = 0; nt < 4; nt++) {
                    const int bi = (nt >> 1) * 4 + (nt & 1) * 2;
                    float* c = acc[mt][nt];
                    MMA16B(c, ahf, bhf[bi], bhf[bi + 1]);
                    MMA16B(c, ahf, blf[bi], blf[bi + 1]);
                    MMA16B(c, alf, bhf[bi], bhf[bi + 1]);
                }
            }
        }
    };

    issue(0); issue(1);
    for (int s2 = 0; s2 < S2; s2++) {
        CPWAIT1();
        __syncthreads();
        if (s2 + 2 < S2) issue(s2 + 2); else CPCOMMIT();
        const uint32_t stb = sb + (uint32_t)(s2 % NSTAGE) * STG64;
        compute32(stb);
        compute32(stb + STG32);
    }

    const int er = lane >> 2, ec = (lane & 3) * 2;
#pragma unroll
    for (int mt = 0; mt < 2; mt++) {
        const int m = m0 + wm * 32 + mt * 16 + er;
#pragma unroll
        for (int nt = 0; nt < 4; nt++) {
            const int n = n0 + wn * 32 + nt * 8 + ec;
            float bn0 = 0.f, bn1 = 0.f;
            if (BIAS == 1) { bn0 = bias[n]; bn1 = bias[n + 1]; }
            const float* c = acc[mt][nt];
            float v00 = c[0] + bn0, v01 = c[1] + bn1;
            float v10 = c[2] + bn0, v11 = c[3] + bn1;
            if (OUT == 0) {
                *reinterpret_cast<float2*>(Cf + (long)m * ldc + n) = make_float2(v00, v01);
                *reinterpret_cast<float2*>(Cf + (long)(m + 8) * ldc + n) = make_float2(v10, v11);
            } else {
                bf16 h0, l0, h1, l1;
                bsplit(v00, h0, l0); bsplit(v01, h1, l1);
                *reinterpret_cast<__nv_bfloat162*>(Ch + (long)m * ldc + n) = __halves2bfloat162(h0, h1);
                *reinterpret_cast<__nv_bfloat162*>(Cl + (long)m * ldc + n) = __halves2bfloat162(l0, l1);
                bsplit(v10, h0, l0); bsplit(v11, h1, l1);
                *reinterpret_cast<__nv_bfloat162*>(Ch + (long)(m + 8) * ldc + n) = __halves2bfloat162(h0, h1);
                *reinterpret_cast<__nv_bfloat162*>(Cl + (long)(m + 8) * ldc + n) = __halves2bfloat162(l0, l1);
            }
        }
    }
}

// ---------------------------------------------------------------------------
// fp16 single-pass core: 512 thr, 128x128 tile, BK=64 stages, issue-ahead.
// BIAS: 0 none, 1 per-N, 2 per-M.  OUT: 0 fp32 Cf, 1 fp16 Chf.
// ---------------------------------------------------------------------------
template <int BIAS, int OUT>
__device__ __forceinline__ void gemm_core_h(
    const __half* __restrict__ A, int lda, const __half* __restrict__ B, int ldb,
    const float* __restrict__ bias,
    float* __restrict__ Cf, __half* __restrict__ Chf, int ldc,
    int m0, int n0, int Keff)
{
    constexpr int BBY = 8192;
    constexpr int STG32 = 2 * BBY;
    constexpr int STG64 = 2 * STG32;
    extern __shared__ uint16_t sm[];
    const uint32_t sb = smem_u32(sm);
    const int tid = threadIdx.x, lane = tid & 31, wrp = tid >> 5;
    const int wm = wrp >> 2, wn = wrp & 3;
    const int S2 = Keff >> 6;

    const int a_ml = (lane & 7) + ((lane >> 3) & 1) * 8;
    const int a_c0 = lane >> 4;
    const int b_nl = (lane & 7) + ((lane >> 4) << 3);
    const int b_c0 = (lane >> 3) & 1;

    const int row = tid >> 2, ch = tid & 3;
    const __half* Ap = A + (long)(m0 + row) * lda + ch * 8;
    const __half* Bp = B + (long)(n0 + row) * ldb + ch * 8;
    const uint32_t swz = SWZ(row, ch);

    auto issue32 = [&](int k32, uint32_t db) {
        const int k0 = k32 << 5;
        CPA16(db + swz,       Ap + k0);
        CPA16(db + BBY + swz, Bp + k0);
    };
    auto issue = [&](int s2) {
        const uint32_t db = sb + (uint32_t)(s2 % NSTAGE) * STG64;
        issue32(2 * s2, db);
        issue32(2 * s2 + 1, db + STG32);
        CPCOMMIT();
    };

    float acc[2][4][4] = {};

    auto compute32 = [&](uint32_t stb) {
#pragma unroll
        for (int ks = 0; ks < 2; ks++) {
            uint32_t bhf[8];
#pragma unroll
            for (int p = 0; p < 2; p++) {
                const uint32_t boff = SWZ(wn * 32 + p * 16 + b_nl, ks * 2 + b_c0);
                LDM4(bhf[p * 4 + 0], bhf[p * 4 + 1], bhf[p * 4 + 2], bhf[p * 4 + 3], stb + BBY + boff);
            }
#pragma unroll
            for (int mt = 0; mt < 2; mt++) {
                uint32_t ahf[4];
                const uint32_t aoff = SWZ(wm * 32 + mt * 16 + a_ml, ks * 2 + a_c0);
                LDM4(ahf[0], ahf[1], ahf[2], ahf[3], stb + aoff);
#pragma unroll
                for (int nt = 0; nt < 4; nt++) {
                    const int bi = (nt >> 1) * 4 + (nt & 1) * 2;
                    MMA16H(acc[mt][nt], ahf, bhf[bi], bhf[bi + 1]);
                }
            }
        }
    };

    issue(0); issue(1);
    for (int s2 = 0; s2 < S2; s2++) {
        CPWAIT1();
        __syncthreads();
        if (s2 + 2 < S2) issue(s2 + 2); else CPCOMMIT();
        const uint32_t stb = sb + (uint32_t)(s2 % NSTAGE) * STG64;
        compute32(stb);
        compute32(stb + STG32);
    }

    const int er = lane >> 2, ec = (lane & 3) * 2;
#pragma unroll
    for (int mt = 0; mt < 2; mt++) {
        const int m = m0 + wm * 32 + mt * 16 + er;
        float bm0 = 0.f, bm8 = 0.f;
        if (BIAS == 2) { bm0 = bias[m]; bm8 = bias[m + 8]; }
#pragma unroll
        for (int nt = 0; nt < 4; nt++) {
            const int n = n0 + wn * 32 + nt * 8 + ec;
            float bn0 = 0.f, bn1 = 0.f;
            if (BIAS == 1) { bn0 = bias[n]; bn1 = bias[n + 1]; }
            const float* c = acc[mt][nt];
            float v00 = c[0] + bn0 + bm0, v01 = c[1] + bn1 + bm0;
            float v10 = c[2] + bn0 + bm8, v11 = c[3] + bn1 + bm8;
            if (OUT == 0) {
                *reinterpret_cast<float2*>(Cf + (long)m * ldc + n) = make_float2(v00, v01);
                *reinterpret_cast<float2*>(Cf + (long)(m + 8) * ldc + n) = make_float2(v10, v11);
            } else {
                *reinterpret_cast<__half2*>(Chf + (long)m * ldc + n) = __floats2half2_rn(v00, v01);
                *reinterpret_cast<__half2*>(Chf + (long)(m + 8) * ldc + n) = __floats2half2_rn(v10, v11);
            }
        }
    }
}

// ---------------------------------------------------------------------------
// Kernel wrappers
// ---------------------------------------------------------------------------
struct QKVP {
    const bf16 *xh, *xl;
    const __half *xf;
    const bf16 *qwh, *qwl, *kwh, *kwl;
    const __half *vwf;
    const float *qb, *kb, *vb;
    bf16 *qh, *ql, *kh, *kl;
    __half *vf;
};

__global__ void __launch_bounds__(512) qkv_kernel(QKVP p)
{
    const int bx = blockIdx.x, by = blockIdx.y, bz = blockIdx.z;
    if (bz == 0) {
        gemm_core<128, 1, 1>(p.xh, p.xl, DD, p.qwh, p.qwl, DD, p.qb,
                             nullptr, p.qh, p.ql, DD, by * 128, bx * 128, DD);
    } else if (bz == 1) {
        gemm_core<128, 1, 1>(p.xh, p.xl, DD, p.kwh, p.kwl, DD, p.kb,
                             nullptr, p.kh, p.kl, DD, by * 128, bx * 128, DD);
    } else {
        // V^T = vw @ x^T, single fp16, per-M bias, fp16 out
        const int b = by >> 3, dt = by & 7;
        gemm_core_h<2, 1>(p.vwf, DD, p.xf + (long)b * MD, DD, p.vb,
                          nullptr, p.vf + (long)b * MD, TT, dt * 128, bx * 128, DD);
    }
}

// scores: split bf16, M-tile 64 (256 thr), causal skip
__global__ void __launch_bounds__(256) sc_kernel(const bf16* __restrict__ qh, const bf16* __restrict__ ql,
                                                 const bf16* __restrict__ kh, const bf16* __restrict__ kl,
                                                 float* __restrict__ a)
{
    const int bx = blockIdx.x, by = blockIdx.y, b = blockIdx.z;
    if (2 * bx > by) return;
    gemm_core<64, 0, 0>(qh + (long)b * MD, ql + (long)b * MD, DD,
                        kh + (long)b * MD, kl + (long)b * MD, DD, nullptr,
                        a + (long)b * AA, nullptr, nullptr, TT, by * 64, bx * 128, DD);
}

// o = w @ V, single fp16, K-limited, 2 CTAs/SM target
__global__ void __launch_bounds__(512, 2) av_kernel(const __half* __restrict__ wf,
                                                    const __half* __restrict__ vf,
                                                    float* __restrict__ o)
{
    const int bx = blockIdx.x, by = blockIdx.y, b = blockIdx.z;
    gemm_core_h<0, 0>(wf + (long)b * AA, TT, vf + (long)b * MD, TT, nullptr,
                      o + (long)b * MD, nullptr, DD,
                      by * 128, bx * 128, min(TT, by * 128 + 128));
}

// vocab: grid x = M tiles (16, fast) so consecutive CTAs share the dw tile
// (L2 reuse); 2 CTAs/SM target via launch bounds (<=64 regs).
__global__ void __launch_bounds__(512, 2) vocab_kernel(const __half* __restrict__ xn,
                                                       const __half* __restrict__ dwf,
                                                       const float* __restrict__ db,
                                                       float* __restrict__ out)
{
    gemm_core_h<1, 0>(xn, DD, dwf, DD, db, out, nullptr, VV, blockIdx.x * 128, blockIdx.y * 128, DD);
}

// ---------------------------------------------------------------------------
// Converters + elementwise
// ---------------------------------------------------------------------------
__global__ void splitw_kernel(const float4* __restrict__ src, bf16* __restrict__ h,
                              bf16* __restrict__ l, int n4)
{
    int i = blockIdx.x * blockDim.x + threadIdx.x;
    if (i >= n4) return;
    float4 v = src[i];
    bf16 h0, l0, h1, l1, h2, l2, h3, l3;
    bsplit(v.x, h0, l0); bsplit(v.y, h1, l1); bsplit(v.z, h2, l2); bsplit(v.w, h3, l3);
    *reinterpret_cast<__nv_bfloat162*>(h + (long)i * 4)     = __halves2bfloat162(h0, h1);
    *reinterpret_cast<__nv_bfloat162*>(h + (long)i * 4 + 2) = __halves2bfloat162(h2, h3);
    *reinterpret_cast<__nv_bfloat162*>(l + (long)i * 4)     = __halves2bfloat162(l0, l1);
    *reinterpret_cast<__nv_bfloat162*>(l + (long)i * 4 + 2) = __halves2bfloat162(l2, l3);
}

__global__ void tohalf_kernel(const float4* __restrict__ src, __half* __restrict__ dst, int n4)
{
    int i = blockIdx.x * blockDim.x + threadIdx.x;
    if (i >= n4) return;
    float4 v = src[i];
    *reinterpret_cast<__half2*>(dst + (long)i * 4)     = __floats2half2_rn(v.x, v.y);
    *reinterpret_cast<__half2*>(dst + (long)i * 4 + 2) = __floats2half2_rn(v.z, v.w);
}

__device__ __forceinline__ void store_x3(float4 v, long off, float* X,
                                         bf16* xh, bf16* xl, __half* xf)
{
    if (X) *reinterpret_cast<float4*>(X + off) = v;
    bf16 h0, l0, h1, l1, h2, l2, h3, l3;
    bsplit(v.x, h0, l0); bsplit(v.y, h1, l1); bsplit(v.z, h2, l2); bsplit(v.w, h3, l3);
    *reinterpret_cast<__nv_bfloat162*>(xh + off)     = __halves2bfloat162(h0, h1);
    *reinterpret_cast<__nv_bfloat162*>(xh + off + 2) = __halves2bfloat162(h2, h3);
    *reinterpret_cast<__nv_bfloat162*>(xl + off)     = __halves2bfloat162(l0, l1);
    *reinterpret_cast<__nv_bfloat162*>(xl + off + 2) = __halves2bfloat162(l2, l3);
    *reinterpret_cast<__half2*>(xf + off)     = __floats2half2_rn(v.x, v.y);
    *reinterpret_cast<__half2*>(xf + off + 2) = __floats2half2_rn(v.z, v.w);
}

__global__ void embed_pe_kernel(const int* __restrict__ src, const float* __restrict__ pe,
                                const float* __restrict__ embed, float* __restrict__ x,
                                bf16* __restrict__ xh, bf16* __restrict__ xl, __half* __restrict__ xf)
{
    int row = blockIdx.x, b = row >> 10;
    long tok = src[row];
    const float4* e = reinterpret_cast<const float4*>(embed + tok * (long)DD);
    const float4* p = reinterpret_cast<const float4*>(pe + (long)b * DD);
    int i = threadIdx.x;
    float4 ev = e[i], pv = p[i];
    float4 v = make_float4(ev.x + pv.x, ev.y + pv.y, ev.z + pv.z, ev.w + pv.w);
    store_x3(v, (long)row * DD + i * 4, x, xh, xl, xf);
}

__global__ void softmax_kernel(const float* __restrict__ A, __half* __restrict__ Wf)
{
    int t = blockIdx.x, b = blockIdx.y;
    const float* row = A + ((long)b * TT + t) * TT;
    __half* wf = Wf + ((long)b * TT + t) * TT;
    int n = t + 1, i = threadIdx.x;
    __shared__ float red[256];
    __shared__ float rowe[TT];
    float m = -1e30f;
    for (int s = i; s < n; s += 256) m = fmaxf(m, row[s]);
    red[i] = m; __syncthreads();
    for (int st = 128; st > 0; st >>= 1) { if (i < st) red[i] = fmaxf(red[i], red[i + st]); __syncthreads(); }
    m = red[0]; __syncthreads();
    float sum = 0.f;
    for (int s = i; s < n; s += 256) { float e = expf(row[s] - m); rowe[s] = e; sum += e; }
    red[i] = sum; __syncthreads();
    for (int st = 128; st > 0; st >>= 1) { if (i < st) red[i] += red[i + st]; __syncthreads(); }
    float inv = 1.0f / red[0];
    for (int s = i; s < TT; s += 256)
        wf[s] = (s < n) ? __float2half_rn(rowe[s] * inv) : __float2half_rn(0.f);
}

__global__ void ln_res_kernel(const float* __restrict__ O, const float* __restrict__ w,
                              const float* __restrict__ bb, float* __restrict__ X,
                              bf16* __restrict__ xh, bf16* __restrict__ xl, __half* __restrict__ xf)
{
    int row = blockIdx.x, i = threadIdx.x;
    const float4 o = reinterpret_cast<const float4*>(O + (long)row * DD)[i];
    float4* x4 = reinterpret_cast<float4*>(X + (long)row * DD);
    __shared__ float red[256];
    red[i] = o.x + o.y + o.z + o.w; __syncthreads();
    for (int st = 128; st > 0; st >>= 1) { if (i < st) red[i] += red[i + st]; __syncthreads(); }
    float mu = red[0] * (1.0f / DD); __syncthreads();
    float dx = o.x - mu, dy = o.y - mu, dz = o.z - mu, dw_ = o.w - mu;
    red[i] = dx * dx + dy * dy + dz * dz + dw_ * dw_; __syncthreads();
    for (int st = 128; st > 0; st >>= 1) { if (i < st) red[i] += red[i + st]; __syncthreads(); }
    float rstd = rsqrtf(red[0] * (1.0f / DD) + 1e-6f);
    float4 wv = reinterpret_cast<const float4*>(w)[i];
    float4 bv = reinterpret_cast<const float4*>(bb)[i];
    float4 xv = x4[i];
    xv.x += dx * rstd * wv.x + bv.x;
    xv.y += dy * rstd * wv.y + bv.y;
    xv.z += dz * rstd * wv.z + bv.z;
    xv.w += dw_ * rstd * wv.w + bv.w;
    x4[i] = xv;
    store_x3(xv, (long)row * DD + i * 4, nullptr, xh, xl, xf);
}

__global__ void final_ln_kernel(const float* __restrict__ X, const float* __restrict__ fw,
                                const float* __restrict__ fb, __half* __restrict__ Y)
{
    int row = blockIdx.x, i = threadIdx.x;
    const float4 x = reinterpret_cast<const float4*>(X + (long)row * DD)[i];
    __shared__ float red[256];
    red[i] = x.x + x.y + x.z + x.w; __syncthreads();
    for (int st = 128; st > 0; st >>= 1) { if (i < st) red[i] += red[i + st]; __syncthreads(); }
    float mu = red[0] * (1.0f / DD); __syncthreads();
    float dx = x.x - mu, dy = x.y - mu, dz = x.z - mu, dw_ = x.w - mu;
    red[i] = dx * dx + dy * dy + dz * dz + dw_ * dw_; __syncthreads();
    for (int st = 128; st > 0; st >>= 1) { if (i < st) red[i] += red[i + st]; __syncthreads(); }
    float rstd = rsqrtf(red[0] * (1.0f / DD) + 1e-5f);
    float4 wv = reinterpret_cast<const float4*>(fw)[i];
    float4 bv = reinterpret_cast<const float4*>(fb)[i];
    long off = (long)row * DD + i * 4;
    *reinterpret_cast<__half2*>(Y + off)     = __floats2half2_rn(dx * rstd * wv.x + bv.x, dy * rstd * wv.y + bv.y);
    *reinterpret_cast<__half2*>(Y + off + 2) = __floats2half2_rn(dz * rstd * wv.z + bv.z, dw_ * rstd * wv.w + bv.w);
}

// ---------------------------------------------------------------------------
extern "C" void kernel_launch(void* const* d_in, const int* in_sizes, int n_in,
                              void* d_out, int out_size)
{
    const int*   src = (const int*)d_in[0];
    const float* pe  = (const float*)d_in[1];
    const float* emb = (const float*)d_in[2];
    const float* qw  = (const float*)d_in[3];
    const float* qb  = (const float*)d_in[4];
    const float* kw  = (const float*)d_in[5];
    const float* kb  = (const float*)d_in[6];
    const float* vw  = (const float*)d_in[7];
    const float* vb  = (const float*)d_in[8];
    const float* lnw = (const float*)d_in[9];
    const float* lnb = (const float*)d_in[10];
    const float* fw  = (const float*)d_in[11];
    const float* fb  = (const float*)d_in[12];
    const float* dw  = (const float*)d_in[13];
    const float* db  = (const float*)d_in[14];
    float* out = (float*)d_out;

#define GA(sym, var) void* var##_; cudaGetSymbolAddress(&var##_, sym)
    GA(g_x, x);  GA(g_a, a);  GA(g_o, o);
    GA(g_xh, xh); GA(g_xl, xl); GA(g_xf, xf);
    GA(g_qh, qh); GA(g_ql, ql); GA(g_kh, kh); GA(g_kl, kl);
    GA(g_vf, vf); GA(g_wf, wf);
    GA(g_qwh, qwh); GA(g_qwl, qwl); GA(g_kwh, kwh); GA(g_kwl, kwl);
    GA(g_vwf, vwf); GA(g_dwf, dwf); GA(g_xnf, xnf);
#undef GA

    const int SMB = NSTAGE * 2 * (2 * 8192 + 2 * 8192);   // 196608 (split MT=128)
    const int SMS = NSTAGE * 2 * (2 * 4096 + 2 * 8192);   // 147456 (split MT=64)
    const int SMH = NSTAGE * 2 * (2 * 8192);              // 98304  (fp16)
    cudaFuncSetAttribute(qkv_kernel,   cudaFuncAttributeMaxDynamicSharedMemorySize, SMB);
    cudaFuncSetAttribute(sc_kernel,    cudaFuncAttributeMaxDynamicSharedMemorySize, SMS);
    cudaFuncSetAttribute(av_kernel,    cudaFuncAttributeMaxDynamicSharedMemorySize, SMH);
    cudaFuncSetAttribute(vocab_kernel, cudaFuncAttributeMaxDynamicSharedMemorySize, SMH);

    // per-launch weight conversions (deterministic, idempotent)
    {
        const int n4w = LL * DD * DD / 4;
        splitw_kernel<<<(n4w + 511) / 512, 512>>>((const float4*)qw, (bf16*)qwh_, (bf16*)qwl_, n4w);
        splitw_kernel<<<(n4w + 511) / 512, 512>>>((const float4*)kw, (bf16*)kwh_, (bf16*)kwl_, n4w);
        tohalf_kernel<<<(n4w + 511) / 512, 512>>>((const float4*)vw, (__half*)vwf_, n4w);
        const int n4d = VV * DD / 4;
        tohalf_kernel<<<(n4d + 511) / 512, 512>>>((const float4*)dw, (__half*)dwf_, n4d);
    }

    embed_pe_kernel<<<BB * TT, 256>>>(src, pe, emb, (float*)x_, (bf16*)xh_, (bf16*)xl_, (__half*)xf_);

    dim3 gqkv(DD / 128, (BB * TT) / 128, 3);
    dim3 gsc(TT / 128, TT / 64, BB);
    dim3 gav(TT / 128, TT / 128, BB);
    for (int l = 0; l < LL; l++) {
        const long wo = (long)l * DD * DD;
        QKVP p;
        p.xh = (const bf16*)xh_; p.xl = (const bf16*)xl_; p.xf = (const __half*)xf_;
        p.qwh = (const bf16*)qwh_ + wo; p.qwl = (const bf16*)qwl_ + wo;
        p.kwh = (const bf16*)kwh_ + wo; p.kwl = (const bf16*)kwl_ + wo;
        p.vwf = (const __half*)vwf_ + wo;
        p.qb = qb + l * DD; p.kb = kb + l * DD; p.vb = vb + l * DD;
        p.qh = (bf16*)qh_; p.ql = (bf16*)ql_;
        p.kh = (bf16*)kh_; p.kl = (bf16*)kl_;
        p.vf = (__half*)vf_;
        qkv_kernel<<<gqkv, 512, SMB>>>(p);
        sc_kernel<<<gsc, 256, SMS>>>((const bf16*)qh_, (const bf16*)ql_,
                                     (const bf16*)kh_, (const bf16*)kl_, (float*)a_);
        softmax_kernel<<<dim3(TT, BB), 256>>>((const float*)a_, (__half*)wf_);
        av_kernel<<<gav, 512, SMH>>>((const __half*)wf_, (const __half*)vf_, (float*)o_);
        ln_res_kernel<<<BB * TT, 256>>>((const float*)o_, lnw + l * DD, lnb + l * DD,
                                        (float*)x_, (bf16*)xh_, (bf16*)xl_, (__half*)xf_);
    }

    final_ln_kernel<<<BB * TT, 256>>>((const float*)x_, fw, fb, (__half*)xnf_);
    dim3 gf((BB * TT) / 128, VV / 128);   // x = M tiles (fast) -> dw tile shared in L2
    vocab_kernel<<<gf, 512, SMH>>>((const __half*)xnf_, (const __half*)dwf_, db, out);
}